// round 12
// baseline (speedup 1.0000x reference)
#include <cuda_runtime.h>
#include <cuda_fp16.h>
#include <cstdint>

// ---------------------------------------------------------------------------
// Problem constants
// ---------------------------------------------------------------------------
#define KNB 10
#define BB  2048
#define N1  20480
#define NP1 204800
#define NP2 20480
// D = T = 128, QD = 256, KD = 384, H = 2, hd = 128

// ---------------------------------------------------------------------------
// Scratch
// ---------------------------------------------------------------------------
__device__ __half g_kv1[(size_t)NP1 * 512];
__device__ float g_q1 [(size_t)N1  * 256];
__device__ float g_attn1[(size_t)N1 * 256];
__device__ float g_h1 [(size_t)N1  * 128];
__device__ float g_emb1[(size_t)N1 * 128];
__device__ unsigned char g_inv1[N1];
__device__ __half g_kv2[(size_t)NP2 * 512];
__device__ float g_q2 [(size_t)BB  * 256];
__device__ float g_attn2[(size_t)BB * 256];
__device__ float g_h2 [(size_t)BB  * 128];
__device__ unsigned char g_inv2[BB];
// pre-permuted fragment-ordered fp16 weights for KV (2 layers x 512 n x 384 k)
__device__ __half g_bph[2 * 512 * 384];
// folded tail weights: Wcat = [f1w_left@Wo || f1w_right]  (2 layers x 128 x 384)
__device__ float g_wcat[2 * 128 * 384];
__device__ float g_c0[2 * 128];          // f1w_left @ bo per layer
__device__ float g_bq2[2 * 256];         // bq + st @ Wq_right^T per layer

#define MODE_PLAIN      0
#define MODE_QGATHER    1
#define MODE_CONCAT     4

// ---------------------------------------------------------------------------
// fp16 mma helper + fast cosine (FMA-pipe)
// ---------------------------------------------------------------------------
__device__ __forceinline__ void mma_f16(float* c, const uint32_t* a, uint32_t b0, uint32_t b1) {
    asm volatile(
        "mma.sync.aligned.m16n8k16.row.col.f32.f16.f16.f32 "
        "{%0,%1,%2,%3}, {%4,%5,%6,%7}, {%8,%9}, {%0,%1,%2,%3};"
        : "+f"(c[0]), "+f"(c[1]), "+f"(c[2]), "+f"(c[3])
        : "r"(a[0]), "r"(a[1]), "r"(a[2]), "r"(a[3]), "r"(b0), "r"(b1));
}
__device__ __forceinline__ uint32_t f2h2(float a, float b) {
    __half2 h = __floats2half2_rn(a, b);
    return *(uint32_t*)&h;
}

// cos(t) via quadrant reduction + minimax polys; |err| ~ 1e-6, valid |t| < ~1e4.
__device__ __forceinline__ float fast_cos(float t) {
    float qf = rintf(t * 0.6366197723675814f);
    int q = (int)qf;
    float r = fmaf(qf, -1.5707962513f, t);
    r = fmaf(qf, -7.54978942e-8f, r);
    float z = r * r;
    float cp = fmaf(z, fmaf(z, fmaf(z, -1.3888397e-3f, 4.16666418e-2f), -0.5f), 1.0f);
    float sp = r * fmaf(z, fmaf(z, 8.3321608e-3f, -1.66666547e-1f), 1.0f);
    float v = (q & 1) ? sp : cp;
    uint32_t sgn = (uint32_t)((q + 1) & 2) << 30;
    return __uint_as_float(__float_as_uint(v) ^ sgn);
}

__device__ __forceinline__ uint32_t smem_u32p(const void* p) {
    uint32_t a;
    asm("{ .reg .u64 t; cvta.to.shared.u64 t, %1; cvt.u32.u64 %0, t; }" : "=r"(a) : "l"(p));
    return a;
}

// ===========================================================================
// B pre-permutation: Wk||Wv [512 n][384 k] fp32 -> fragment-ordered fp16
// ===========================================================================
__global__ void prep_b_kernel(const float* __restrict__ Wk, const float* __restrict__ Wv,
                              __half* __restrict__ dst) {
    int idx = blockIdx.x * blockDim.x + threadIdx.x;
    if (idx >= 2 * 512 * 384) return;
    int l = idx / (512 * 384);
    int rem = idx - l * (512 * 384);
    int n = rem / 384;
    int k = rem - n * 384;
    const float* W = (n < 256) ? (Wk + (size_t)l * 256 * 384 + (size_t)n * 384)
                               : (Wv + (size_t)l * 256 * 384 + (size_t)(n - 256) * 384);
    float v = W[k];
    int nt = n >> 3, gid = n & 7;
    int ktp = k >> 5, k32 = k & 31;
    int kt_in = k32 >> 4, klo = k32 & 15;
    int tg = (klo & 7) >> 1, reg = klo >> 3, par = k & 1;
    int lane = gid * 4 + tg;
    size_t off = ((((size_t)l * 64 + nt) * 12 + ktp) * 32 + lane) * 8 + (kt_in * 2 + reg) * 2 + par;
    dst[off] = __float2half_rn(v);
}

// ===========================================================================
// Tail fold: Wcat / c0
// ===========================================================================
__global__ void prep_wc_kernel(const float* __restrict__ Wo, const float* __restrict__ bo,
                               const float* __restrict__ f1w,
                               float* __restrict__ wcat, float* __restrict__ c0) {
    int l = blockIdx.x >> 7;
    int i = blockIdx.x & 127;
    int k = threadIdx.x;
    const float* f1 = f1w + ((size_t)l * 128 + i) * 384;
    float v;
    if (k < 256) {
        const float* wo = Wo + (size_t)l * 256 * 256;
        float s = 0.f;
#pragma unroll 4
        for (int j = 0; j < 256; j++) s = fmaf(f1[j], wo[j * 256 + k], s);
        v = s;
    } else {
        v = f1[k];
    }
    wcat[((size_t)l * 128 + i) * 384 + k] = v;
    if (k == 0) {
        const float* bol = bo + l * 256;
        float s = 0.f;
#pragma unroll 4
        for (int j = 0; j < 256; j++) s = fmaf(f1[j], bol[j], s);
        c0[l * 128 + i] = s;
    }
}

// ===========================================================================
// Q-bias fold: bq2[l][n] = bq[l][n] + sum_j cos(tb[j]) * Wq[l][n][128+j]
// ===========================================================================
__global__ void prep_bq_kernel(const float* __restrict__ Wq, const float* __restrict__ bq,
                               const float* __restrict__ tb, float* __restrict__ bq2) {
    int l = blockIdx.x;
    int n = threadIdx.x;
    __shared__ float st[128];
    if (n < 128) st[n] = __cosf(tb[n]);
    __syncthreads();
    const float* w = Wq + (((size_t)l * 256 + n) * 256) + 128;
    float s = bq[l * 256 + n];
#pragma unroll 4
    for (int j = 0; j < 128; j++) s = fmaf(st[j], w[j], s);
    bq2[l * 256 + n] = s;
}

// ===========================================================================
// KV projection kernel v8: fp16 mma m16n8k16, persistent CTAs, 3-stage
// pipeline: cp.async raw staging + double-buffered fragment-permuted A.
//   block i:  MMA/epilogue on perm[par]   (raw(i+1) streaming in via cp.async)
//             wait + barrier
//             convert raw -> perm[par^1]  (smem->smem, cos on FMA pipe)
//             barrier; issue cp.async raw(i+2)
// CTA = 64 rows x 512 cols, 512 threads (16 warps, warp = 64 rows x 32 cols).
// ===========================================================================
struct KvParams {
    const __half* Bp;
    const float *bk, *bv;
    __half* C;
    int DIV, nblk;
    const float *ts, *etm, *tw, *tb;
    const float *Adense, *nf, *memv, *ef;
    const int *idx, *eidx;
};

#define KV_PERM_BYTES (2 * 49152)
#define KV_RAW_BYTES  98304
#define KV_DSMEM (KV_PERM_BYTES + KV_RAW_BYTES)

__device__ __forceinline__ void kv_stash_h2(uint32_t* As, int m, int k, uint32_t h2) {
    int kt = k >> 4, mi = m >> 4;
    int r16 = m & 15, gid = r16 & 7, hi_r = r16 >> 3;
    int klo = k & 15, tg = (klo & 7) >> 1;
    int reg = hi_r + ((klo >> 3) << 1);
    As[(((kt * 4 + mi) * 32) + gid * 4 + tg) * 4 + reg] = h2;
}

// prefetch raw gather data for one 64-row block into smem via cp.async
template <int DENSE>
__device__ __forceinline__ void kv_prefetch(uint32_t raw_smem, int bm, const KvParams& p, int tid) {
#pragma unroll 1
    for (int c = tid; c < 6144; c += 512) {
        int row = c / 96;
        int off4 = c - row * 96;
        int sec = off4 >> 5;
        int within = off4 & 31;
        int m = bm + row;
        const float* src;
        if (sec == 0) {
            src = DENSE ? (p.Adense + (size_t)m * 128 + within * 4)
                        : (p.nf + (size_t)__ldg(&p.idx[m]) * 128 + within * 4);
        } else if (sec == 1) {
            if (DENSE) continue;
            src = p.memv + (size_t)__ldg(&p.idx[m]) * 128 + within * 4;
        } else {
            src = p.ef + (size_t)__ldg(&p.eidx[m]) * 128 + within * 4;
        }
        uint32_t dst = raw_smem + c * 16;
        asm volatile("cp.async.cg.shared.global [%0], [%1], 16;" :: "r"(dst), "l"(src));
    }
    asm volatile("cp.async.commit_group;" ::: "memory");
}

// convert raw smem -> fragment-permuted fp16 A (incl. fused time encoding)
template <int DENSE>
__device__ __forceinline__ void kv_convert(uint32_t* As, const float4* raw4, int bm,
                                           const KvParams& p, int tid) {
    const int grow = tid >> 3;
    const int gseg = tid & 7;
    const int m = bm + grow;
#pragma unroll
    for (int i = 0; i < 4; i++) {
        int cf = gseg + 8 * i;
        float4 v = raw4[grow * 96 + cf];
        if (!DENSE) {
            float4 y = raw4[grow * 96 + 32 + cf];
            v.x += y.x; v.y += y.y; v.z += y.z; v.w += y.w;
        }
        int k = cf * 4;
        kv_stash_h2(As, grow, k, f2h2(v.x, v.y));
        kv_stash_h2(As, grow, k + 2, f2h2(v.z, v.w));
        float4 e = raw4[grow * 96 + 64 + cf];
        kv_stash_h2(As, grow, 128 + k, f2h2(e.x, e.y));
        kv_stash_h2(As, grow, 128 + k + 2, f2h2(e.z, e.w));
    }
    float dt = __ldg(&p.ts[m / p.DIV]) - __ldg(&p.etm[m]);
#pragma unroll
    for (int i = 0; i < 4; i++) {
        int j0 = (gseg + 8 * i) * 4;
        float c0 = fast_cos(fmaf(dt, __ldg(&p.tw[j0 + 0]), __ldg(&p.tb[j0 + 0])));
        float c1 = fast_cos(fmaf(dt, __ldg(&p.tw[j0 + 1]), __ldg(&p.tb[j0 + 1])));
        float c2 = fast_cos(fmaf(dt, __ldg(&p.tw[j0 + 2]), __ldg(&p.tb[j0 + 2])));
        float c3 = fast_cos(fmaf(dt, __ldg(&p.tw[j0 + 3]), __ldg(&p.tb[j0 + 3])));
        kv_stash_h2(As, grow, 256 + j0, f2h2(c0, c1));
        kv_stash_h2(As, grow, 256 + j0 + 2, f2h2(c2, c3));
    }
}

template <int DENSE>
__global__ void __launch_bounds__(512, 1) kv_kernel(KvParams p) {
    extern __shared__ char smem[];
    uint32_t* perm = (uint32_t*)smem;                                  // 2 x 48KB
    const float4* raw4 = (const float4*)(smem + KV_PERM_BYTES);       // 96KB
    const uint32_t raw_u32 = smem_u32p(smem + KV_PERM_BYTES);

    const int tid = threadIdx.x;
    const int lane = tid & 31;
    const int wid = tid >> 5;
    const int gID = lane >> 2;
    const int tg = lane & 3;
    const char* bpw = (const char*)p.Bp + (size_t)(wid * 4) * 6144;
    const int stride = gridDim.x;

    int blk = blockIdx.x;
    if (blk >= p.nblk) return;

    // ---- pipeline prologue ----
    kv_prefetch<DENSE>(raw_u32, blk * 64, p, tid);
    asm volatile("cp.async.wait_group 0;" ::: "memory");
    __syncthreads();
    kv_convert<DENSE>(perm, raw4, blk * 64, p, tid);
    __syncthreads();
    {
        int nxt = blk + stride;
        if (nxt < p.nblk) kv_prefetch<DENSE>(raw_u32, nxt * 64, p, tid);
    }

    int parity = 0;
#pragma unroll 1
    for (; blk < p.nblk; blk += stride) {
        const int bm = blk * 64;
        const uint4* As4 = (const uint4*)(perm + parity * 12288);

        float acc[4][4][4];
#pragma unroll
        for (int mi = 0; mi < 4; mi++)
#pragma unroll
            for (int nj = 0; nj < 4; nj++)
#pragma unroll
                for (int q = 0; q < 4; q++) acc[mi][nj][q] = 0.f;

        uint4 bA[4], bB[4];

#define KV_LDB(buf, ktp_) { \
    _Pragma("unroll") \
    for (int nj = 0; nj < 4; nj++) \
        buf[nj] = *(const uint4*)(bpw + (size_t)nj * 6144 + (ktp_) * 512 + lane * 16); }

#define KV_STEP(buf, ktp_) { \
    _Pragma("unroll") \
    for (int kt_in = 0; kt_in < 2; kt_in++) { \
        const int kt = (ktp_) * 2 + kt_in; \
        _Pragma("unroll") \
        for (int mi = 0; mi < 4; mi++) { \
            uint4 av = As4[(kt * 4 + mi) * 32 + lane]; \
            uint32_t aa[4] = {av.x, av.y, av.z, av.w}; \
            _Pragma("unroll") \
            for (int nj = 0; nj < 4; nj++) { \
                uint32_t b0 = kt_in ? buf[nj].z : buf[nj].x; \
                uint32_t b1 = kt_in ? buf[nj].w : buf[nj].y; \
                mma_f16(acc[mi][nj], aa, b0, b1); \
            } \
        } \
    } }

        KV_LDB(bA, 0);
#pragma unroll 1
        for (int ktp = 0; ktp < 12; ktp += 2) {
            KV_LDB(bB, ktp + 1);
            KV_STEP(bA, ktp);
            if (ktp + 2 < 12) KV_LDB(bA, ktp + 2);
            KV_STEP(bB, ktp + 1);
        }
#undef KV_LDB
#undef KV_STEP

        // ---- epilogue (fp16 out) ----
#pragma unroll
        for (int mi = 0; mi < 4; mi++) {
            const int r_lo = bm + mi * 16 + gID;
            __half* clo = p.C + (size_t)r_lo * 512;
            __half* chi = clo + (size_t)8 * 512;
#pragma unroll
            for (int nj = 0; nj < 4; nj++) {
                const int col = wid * 32 + nj * 8 + tg * 2;
                const float b0 = (col < 256) ? __ldg(&p.bk[col]) : __ldg(&p.bv[col - 256]);
                const float b1 = (col + 1 < 256) ? __ldg(&p.bk[col + 1]) : __ldg(&p.bv[col + 1 - 256]);
                *(__half2*)(clo + col) = __floats2half2_rn(acc[mi][nj][0] + b0, acc[mi][nj][1] + b1);
                *(__half2*)(chi + col) = __floats2half2_rn(acc[mi][nj][2] + b0, acc[mi][nj][3] + b1);
            }
        }

        // ---- pipeline: convert(i+1), then launch raw(i+2) ----
        {
            int n1 = blk + stride;
            if (n1 < p.nblk) {
                asm volatile("cp.async.wait_group 0;" ::: "memory");
                __syncthreads();   // raw(i+1) visible to all; perm[par^1] free
                kv_convert<DENSE>(perm + (parity ^ 1) * 12288, raw4, n1 * 64, p, tid);
                __syncthreads();   // convert reads of raw done; perm writes visible
                int n2 = n1 + stride;
                if (n2 < p.nblk) kv_prefetch<DENSE>(raw_u32, n2 * 64, p, tid);
            }
        }
        parity ^= 1;
    }
}

// ===========================================================================
// fp16 mma.sync GEMM m16n8k16 (Q / fused-fc1 / fc2): CTA = 128(m) x 128(n).
// ===========================================================================
struct TcParams {
    int Kdim, ldA, ldC, ldW;
    const float* W;
    const float* bias;
    const float* cbias;
    float* C;
    int relu;
    const unsigned char* invalid;
    const float *Adense, *nf, *memv;
    const int *idx;
};

template <int MODE>
__global__ void __launch_bounds__(256) mma_gemm(TcParams p) {
    __shared__ uint32_t As[128][20];
    __shared__ uint32_t Bs[128][20];
    const int tid = threadIdx.x;
    const int lane = tid & 31;
    const int wid = tid >> 5;
    const int bm = blockIdx.x * 128;
    const int noff = blockIdx.y * 128;
    const float* W = p.W + (size_t)noff * p.ldW;
    const float* bias = p.bias + noff;
    const int row = tid >> 1;
    const int seg = tid & 1;
    const int m = bm + row;
    const int wr = (wid >> 1) * 32;
    const int wc = (wid & 1) * 64;
    const int groupID = lane >> 2;
    const int tg = lane & 3;

    float acc[2][8][4];
#pragma unroll
    for (int mi = 0; mi < 2; mi++)
#pragma unroll
        for (int nj = 0; nj < 8; nj++)
#pragma unroll
            for (int q = 0; q < 4; q++) acc[mi][nj][q] = 0.f;

#pragma unroll 1
    for (int k0 = 0; k0 < p.Kdim; k0 += 32) {
        const int kb = k0 + seg * 16;
        {
            const float* s0 = nullptr;
            const float* s1 = nullptr;
            if constexpr (MODE == MODE_PLAIN) {
                s0 = p.Adense + (size_t)m * p.ldA + kb;
            } else if constexpr (MODE == MODE_QGATHER) {
                int nd = __ldg(&p.idx[m]);
                s0 = p.nf + (size_t)nd * 128 + kb;
                s1 = p.memv + (size_t)nd * 128 + kb;
            } else {  // MODE_CONCAT
                if (kb < 256) {
                    s0 = p.Adense + (size_t)m * 256 + kb;
                } else {
                    int nd = __ldg(&p.idx[m]);
                    s0 = p.nf + (size_t)nd * 128 + (kb - 256);
                    s1 = p.memv + (size_t)nd * 128 + (kb - 256);
                }
            }
            uint32_t h[8];
#pragma unroll
            for (int i = 0; i < 4; i++) {
                float4 v = *(const float4*)(s0 + i * 4);
                if (s1) {
                    float4 w = *(const float4*)(s1 + i * 4);
                    v.x += w.x; v.y += w.y; v.z += w.z; v.w += w.w;
                }
                h[i * 2 + 0] = f2h2(v.x, v.y);
                h[i * 2 + 1] = f2h2(v.z, v.w);
            }
            *(uint4*)&As[row][seg * 8] = make_uint4(h[0], h[1], h[2], h[3]);
            *(uint4*)&As[row][seg * 8 + 4] = make_uint4(h[4], h[5], h[6], h[7]);
        }
        {
            const float* wsrc = W + (size_t)row * p.ldW + kb;
            uint32_t h[8];
#pragma unroll
            for (int i = 0; i < 4; i++) {
                float4 v = *(const float4*)(wsrc + i * 4);
                h[i * 2 + 0] = f2h2(v.x, v.y);
                h[i * 2 + 1] = f2h2(v.z, v.w);
            }
            *(uint4*)&Bs[row][seg * 8] = make_uint4(h[0], h[1], h[2], h[3]);
            *(uint4*)&Bs[row][seg * 8 + 4] = make_uint4(h[4], h[5], h[6], h[7]);
        }
        __syncthreads();
#pragma unroll
        for (int kt = 0; kt < 2; kt++) {
            const int cb = kt * 8;
            uint32_t a[2][4];
#pragma unroll
            for (int mi = 0; mi < 2; mi++) {
                int r0 = wr + mi * 16 + groupID;
                a[mi][0] = As[r0][cb + tg];
                a[mi][1] = As[r0 + 8][cb + tg];
                a[mi][2] = As[r0][cb + 4 + tg];
                a[mi][3] = As[r0 + 8][cb + 4 + tg];
            }
#pragma unroll
            for (int nj = 0; nj < 8; nj++) {
                int nb_ = wc + nj * 8 + groupID;
                uint32_t b0 = Bs[nb_][cb + tg];
                uint32_t b1 = Bs[nb_][cb + 4 + tg];
                mma_f16(acc[0][nj], a[0], b0, b1);
                mma_f16(acc[1][nj], a[1], b0, b1);
            }
        }
        __syncthreads();
    }

#pragma unroll
    for (int mi = 0; mi < 2; mi++) {
        const int r_lo = bm + wr + mi * 16 + groupID;
        const int r_hi = r_lo + 8;
        const bool z_lo = (p.invalid != nullptr) && p.invalid[r_lo];
        const bool z_hi = (p.invalid != nullptr) && p.invalid[r_hi];
        float* clo = p.C + (size_t)r_lo * p.ldC + noff;
        float* chi = p.C + (size_t)r_hi * p.ldC + noff;
#pragma unroll
        for (int nj = 0; nj < 8; nj++) {
            const int cl = wc + nj * 8 + tg * 2;
            const float b0 = __ldg(&bias[cl]);
            const float b1 = __ldg(&bias[cl + 1]);
            float cb0 = 0.f, cb1 = 0.f;
            if (p.cbias) {
                cb0 = __ldg(&p.cbias[noff + cl]);
                cb1 = __ldg(&p.cbias[noff + cl + 1]);
            }
            float v00 = acc[mi][nj][0] + b0 + (z_lo ? 0.f : cb0);
            float v01 = acc[mi][nj][1] + b1 + (z_lo ? 0.f : cb1);
            float v10 = acc[mi][nj][2] + b0 + (z_hi ? 0.f : cb0);
            float v11 = acc[mi][nj][3] + b1 + (z_hi ? 0.f : cb1);
            if (p.relu) {
                v00 = fmaxf(v00, 0.f); v01 = fmaxf(v01, 0.f);
                v10 = fmaxf(v10, 0.f); v11 = fmaxf(v11, 0.f);
            }
            *(float2*)(clo + cl) = make_float2(v00, v01);
            *(float2*)(chi + cl) = make_float2(v10, v11);
        }
    }
}

// ---------------------------------------------------------------------------
// Temporal attention (kv fp16); zeroes output rows with no valid neighbor.
// ---------------------------------------------------------------------------
__global__ void attn_kernel(const float* __restrict__ q, const __half* __restrict__ kv,
                            const int* __restrict__ nbrs, float* __restrict__ outp,
                            unsigned char* __restrict__ invalid) {
    const int r = blockIdx.x;
    const int tid = threadIdx.x;
    const int warp = tid >> 5;
    const int lane = tid & 31;
    __shared__ float sq[256];
    __shared__ float sc[2][KNB];
    __shared__ float swt[2][KNB];
    __shared__ int smask[KNB];
    __shared__ int sinv;

    if (tid < 256) sq[tid] = q[(size_t)r * 256 + tid];
    if (tid < KNB) smask[tid] = (nbrs[r * KNB + tid] != 0) ? 1 : 0;
    __syncthreads();
    if (tid == 0) {
        int any = 0;
#pragma unroll
        for (int k = 0; k < KNB; k++) any |= smask[k];
        if (!any) smask[KNB - 1] = 1;
        sinv = !any;
        invalid[r] = (unsigned char)(!any);
    }
    __syncthreads();

    if (warp < KNB) {
        const __half* kp = kv + ((size_t)r * KNB + warp) * 512;
        float s0 = 0.f, s1 = 0.f;
#pragma unroll
        for (int i = 0; i < 4; i++) {
            int d = lane + 32 * i;
            s0 = fmaf(sq[d], __half2float(__ldg(&kp[d])), s0);
            s1 = fmaf(sq[128 + d], __half2float(__ldg(&kp[128 + d])), s1);
        }
#pragma unroll
        for (int o = 16; o > 0; o >>= 1) {
            s0 += __shfl_down_sync(0xffffffffu, s0, o);
            s1 += __shfl_down_sync(0xffffffffu, s1, o);
        }
        if (lane == 0) {
            const float scale = 0.08838834764831845f;
            sc[0][warp] = smask[warp] ? s0 * scale : -1e9f;
            sc[1][warp] = smask[warp] ? s1 * scale : -1e9f;
        }
    }
    __syncthreads();

    if (tid < 2) {
        float mx = -3.0e38f;
#pragma unroll
        for (int k = 0; k < KNB; k++) mx = fmaxf(mx, sc[tid][k]);
        float sum = 0.f;
#pragma unroll
        for (int k = 0; k < KNB; k++) {
            float e = __expf(sc[tid][k] - mx);
            swt[tid][k] = e;
            sum += e;
        }
        float inv = 1.0f / sum;
#pragma unroll
        for (int k = 0; k < KNB; k++) swt[tid][k] *= inv;
    }
    __syncthreads();

    if (tid < 256) {
        int h = tid >> 7;
        float o = 0.f;
#pragma unroll
        for (int k = 0; k < KNB; k++)
            o = fmaf(swt[h][k], __half2float(__ldg(&kv[((size_t)r * KNB + k) * 512 + 256 + tid])), o);
        outp[(size_t)r * 256 + tid] = sinv ? 0.f : o;
    }
}

// ---------------------------------------------------------------------------
// Host side
// ---------------------------------------------------------------------------
static void launch_mma(int mode, int M, int nchunks, const TcParams& p, cudaStream_t s) {
    dim3 grid(M / 128, nchunks);
    switch (mode) {
        case MODE_PLAIN:   mma_gemm<MODE_PLAIN><<<grid, 256, 0, s>>>(p); break;
        case MODE_QGATHER: mma_gemm<MODE_QGATHER><<<grid, 256, 0, s>>>(p); break;
        case MODE_CONCAT:  mma_gemm<MODE_CONCAT><<<grid, 256, 0, s>>>(p); break;
    }
}

extern "C" void kernel_launch(void* const* d_in, const int* in_sizes, int n_in,
                              void* d_out, int out_size) {
    const float* nf   = (const float*)d_in[0];
    const float* mem  = (const float*)d_in[1];
    const float* ef   = (const float*)d_in[2];
    const float* tw   = (const float*)d_in[3];
    const float* tb   = (const float*)d_in[4];
    const float* Wq   = (const float*)d_in[5];
    const float* bq   = (const float*)d_in[6];
    const float* Wk   = (const float*)d_in[7];
    const float* bk   = (const float*)d_in[8];
    const float* Wv   = (const float*)d_in[9];
    const float* bv   = (const float*)d_in[10];
    const float* Wo   = (const float*)d_in[11];
    const float* bo   = (const float*)d_in[12];
    const float* f1w  = (const float*)d_in[13];
    const float* f1b  = (const float*)d_in[14];
    const float* f2w  = (const float*)d_in[15];
    const float* f2b  = (const float*)d_in[16];
    const int*   src  = (const int*)d_in[17];
    const float* ts   = (const float*)d_in[18];
    const int*   nb2  = (const int*)d_in[19];
    const int*   ei2  = (const int*)d_in[20];
    const float* tm2  = (const float*)d_in[21];
    const int*   nb1  = (const int*)d_in[22];
    const int*   ei1  = (const int*)d_in[23];
    const float* tm1  = (const float*)d_in[24];
    float* out = (float*)d_out;

    float *pq1, *pattn1, *ph1, *pemb1;
    float *pq2, *pattn2, *ph2, *pwcat, *pc0, *pbq2;
    __half *pkv1, *pkv2, *pbph;
    unsigned char *pinv1, *pinv2;
    cudaGetSymbolAddress((void**)&pkv1, g_kv1);
    cudaGetSymbolAddress((void**)&pq1, g_q1);
    cudaGetSymbolAddress((void**)&pattn1, g_attn1);
    cudaGetSymbolAddress((void**)&ph1, g_h1);
    cudaGetSymbolAddress((void**)&pemb1, g_emb1);
    cudaGetSymbolAddress((void**)&pinv1, g_inv1);
    cudaGetSymbolAddress((void**)&pkv2, g_kv2);
    cudaGetSymbolAddress((void**)&pq2, g_q2);
    cudaGetSymbolAddress((void**)&pattn2, g_attn2);
    cudaGetSymbolAddress((void**)&ph2, g_h2);
    cudaGetSymbolAddress((void**)&pinv2, g_inv2);
    cudaGetSymbolAddress((void**)&pbph, g_bph);
    cudaGetSymbolAddress((void**)&pwcat, g_wcat);
    cudaGetSymbolAddress((void**)&pc0, g_c0);
    cudaGetSymbolAddress((void**)&pbq2, g_bq2);

    static cudaStream_t s_side = nullptr;
    static cudaEvent_t ev_fork = nullptr, ev_join = nullptr;
    if (s_side == nullptr) {
        cudaStreamCreateWithFlags(&s_side, cudaStreamNonBlocking);
        cudaEventCreateWithFlags(&ev_fork, cudaEventDisableTiming);
        cudaEventCreateWithFlags(&ev_join, cudaEventDisableTiming);
        cudaFuncSetAttribute(kv_kernel<0>, cudaFuncAttributeMaxDynamicSharedMemorySize, KV_DSMEM);
        cudaFuncSetAttribute(kv_kernel<1>, cudaFuncAttributeMaxDynamicSharedMemorySize, KV_DSMEM);
    }

    const cudaStream_t s0 = 0;

    const float* bk1 = bk + 256;
    const float* bv1 = bv + 256;
    const float* f2w1 = f2w + 128 * 128; const float* f2b1 = f2b + 128;

    // ---- fork immediately: side stream does preps + Q1 + Q2 ----
    cudaEventRecord(ev_fork, s0);
    cudaStreamWaitEvent(s_side, ev_fork, 0);

    prep_bq_kernel<<<2, 256, 0, s_side>>>(Wq, bq, tb, pbq2);
    prep_wc_kernel<<<256, 384, 0, s_side>>>(Wo, bo, f1w, pwcat, pc0);
    {   // Q1 (fp16, K=128): [20480,256], 2 col chunks
        TcParams p{};
        p.Kdim = 128; p.ldC = 256; p.ldW = 256;
        p.W = Wq; p.bias = pbq2; p.C = pq1;
        p.nf = nf; p.memv = mem; p.idx = nb2;
        launch_mma(MODE_QGATHER, N1, 2, p, s_side);
    }
    {   // Q2 (fp16, K=128)
        TcParams p{};
        p.Kdim = 128; p.ldC = 256; p.ldW = 256;
        p.W = Wq + 256 * 256; p.bias = pbq2 + 256; p.C = pq2;
        p.nf = nf; p.memv = mem; p.idx = src;
        launch_mma(MODE_QGATHER, BB, 2, p, s_side);
    }
    cudaEventRecord(ev_join, s_side);

    // ---- main stream: prep_b then KV1 (persistent, 136 SMs) ----
    prep_b_kernel<<<(2 * 512 * 384 + 255) / 256, 256, 0, s0>>>(Wk, Wv, pbph);
    {
        KvParams p{};
        p.Bp = pbph; p.bk = bk; p.bv = bv; p.C = pkv1;
        p.DIV = 100; p.nblk = NP1 / 64;
        p.ts = ts; p.etm = tm1; p.tw = tw; p.tb = tb;
        p.nf = nf; p.memv = mem; p.ef = ef; p.idx = nb1; p.eidx = ei1;
        kv_kernel<0><<<136, 512, KV_DSMEM, s0>>>(p);
    }
    cudaStreamWaitEvent(s0, ev_join, 0);

    attn_kernel<<<N1, 320, 0, s0>>>(pq1, pkv1, nb1, pattn1, pinv1);
    {   // fused O1+fc1 (fp16): K=384 [attn || base], conditional c0, relu
        TcParams p{};
        p.Kdim = 384; p.ldC = 128; p.ldW = 384;
        p.W = pwcat; p.bias = f1b; p.cbias = pc0; p.C = ph1;
        p.Adense = pattn1; p.nf = nf; p.memv = mem; p.idx = nb2;
        p.invalid = pinv1; p.relu = 1;
        launch_mma(MODE_CONCAT, N1, 1, p, s0);
    }
    {   // fc2 L0 (fp16) -> emb1
        TcParams p{};
        p.Kdim = 128; p.ldA = 128; p.ldC = 128; p.ldW = 128;
        p.W = f2w; p.bias = f2b; p.C = pemb1; p.Adense = ph1;
        launch_mma(MODE_PLAIN, N1, 1, p, s0);
    }
    {   // KV2 (fp16, dense, persistent)
        KvParams p{};
        p.Bp = pbph + 512 * 384; p.bk = bk1; p.bv = bv1; p.C = pkv2;
        p.DIV = 10; p.nblk = NP2 / 64;
        p.ts = ts; p.etm = tm2; p.tw = tw; p.tb = tb;
        p.Adense = pemb1; p.ef = ef; p.eidx = ei2;
        kv_kernel<1><<<148, 512, KV_DSMEM, s0>>>(p);
    }
    attn_kernel<<<BB, 320, 0, s0>>>(pq2, pkv2, nb2, pattn2, pinv2);
    {   // fused O2+fc1 L1 (fp16)
        TcParams p{};
        p.Kdim = 384; p.ldC = 128; p.ldW = 384;
        p.W = pwcat + 128 * 384; p.bias = f1b + 128; p.cbias = pc0 + 128; p.C = ph2;
        p.Adense = pattn2; p.nf = nf; p.memv = mem; p.idx = src;
        p.invalid = pinv2; p.relu = 1;
        launch_mma(MODE_CONCAT, BB, 1, p, s0);
    }
    {   // fc2 L1 (fp16) -> out
        TcParams p{};
        p.Kdim = 128; p.ldA = 128; p.ldC = 128; p.ldW = 128;
        p.W = f2w1; p.bias = f2b1; p.C = out; p.Adense = ph2;
        launch_mma(MODE_PLAIN, BB, 1, p, s0);
    }
}

// round 13
// speedup vs baseline: 1.1492x; 1.1492x over previous
#include <cuda_runtime.h>
#include <cuda_fp16.h>
#include <cstdint>

// ---------------------------------------------------------------------------
// Problem constants
// ---------------------------------------------------------------------------
#define KNB 10
#define BB  2048
#define N1  20480
#define NP1 204800
#define NP2 20480
// D = T = 128, QD = 256, KD = 384, H = 2, hd = 128

// ---------------------------------------------------------------------------
// Scratch
// ---------------------------------------------------------------------------
__device__ __half g_kv1[(size_t)NP1 * 512];
__device__ __half g_q1 [(size_t)N1  * 256];
__device__ __half g_attn1[(size_t)N1 * 256];
__device__ float g_h1 [(size_t)N1  * 128];
__device__ float g_emb1[(size_t)N1 * 128];
__device__ unsigned char g_inv1[N1];
__device__ __half g_kv2[(size_t)NP2 * 512];
__device__ __half g_q2 [(size_t)BB  * 256];
__device__ __half g_attn2[(size_t)BB * 256];
__device__ float g_h2 [(size_t)BB  * 128];
__device__ unsigned char g_inv2[BB];
// pre-permuted fragment-ordered fp16 weights for KV (2 layers x 512 n x 384 k)
__device__ __half g_bph[2 * 512 * 384];
// folded tail weights: Wcat = [f1w_left@Wo || f1w_right]  (2 layers x 128 x 384)
__device__ float g_wcat[2 * 128 * 384];
__device__ float g_c0[2 * 128];          // f1w_left @ bo per layer
__device__ float g_bq2[2 * 256];         // bq + st @ Wq_right^T per layer

#define MODE_PLAIN      0
#define MODE_QGATHER    1
#define MODE_CONCAT     4

// ---------------------------------------------------------------------------
// fp16 mma helper + fast cosine (FMA-pipe)
// ---------------------------------------------------------------------------
__device__ __forceinline__ void mma_f16(float* c, const uint32_t* a, uint32_t b0, uint32_t b1) {
    asm volatile(
        "mma.sync.aligned.m16n8k16.row.col.f32.f16.f16.f32 "
        "{%0,%1,%2,%3}, {%4,%5,%6,%7}, {%8,%9}, {%0,%1,%2,%3};"
        : "+f"(c[0]), "+f"(c[1]), "+f"(c[2]), "+f"(c[3])
        : "r"(a[0]), "r"(a[1]), "r"(a[2]), "r"(a[3]), "r"(b0), "r"(b1));
}
__device__ __forceinline__ uint32_t f2h2(float a, float b) {
    __half2 h = __floats2half2_rn(a, b);
    return *(uint32_t*)&h;
}

// cos(t) via quadrant reduction + minimax polys; |err| ~ 1e-6, valid |t| < ~1e4.
__device__ __forceinline__ float fast_cos(float t) {
    float qf = rintf(t * 0.6366197723675814f);
    int q = (int)qf;
    float r = fmaf(qf, -1.5707962513f, t);
    r = fmaf(qf, -7.54978942e-8f, r);
    float z = r * r;
    float cp = fmaf(z, fmaf(z, fmaf(z, -1.3888397e-3f, 4.16666418e-2f), -0.5f), 1.0f);
    float sp = r * fmaf(z, fmaf(z, 8.3321608e-3f, -1.66666547e-1f), 1.0f);
    float v = (q & 1) ? sp : cp;
    uint32_t sgn = (uint32_t)((q + 1) & 2) << 30;
    return __uint_as_float(__float_as_uint(v) ^ sgn);
}

// ===========================================================================
// B pre-permutation (one layer per launch): W[512 n][384 k] fp32 -> fragment-
// ordered fp16 for m16n8k16.
// ===========================================================================
__global__ void prep_b_kernel(const float* __restrict__ Wk, const float* __restrict__ Wv,
                              __half* __restrict__ dst, int layer) {
    int idx = blockIdx.x * blockDim.x + threadIdx.x;   // 512 * 384
    if (idx >= 512 * 384) return;
    int n = idx / 384;
    int k = idx - n * 384;
    const float* W = (n < 256) ? (Wk + (size_t)layer * 256 * 384 + (size_t)n * 384)
                               : (Wv + (size_t)layer * 256 * 384 + (size_t)(n - 256) * 384);
    float v = W[k];
    int nt = n >> 3, gid = n & 7;
    int ktp = k >> 5, k32 = k & 31;
    int kt_in = k32 >> 4, klo = k32 & 15;
    int tg = (klo & 7) >> 1, reg = klo >> 3, par = k & 1;
    int lane = gid * 4 + tg;
    size_t off = ((((size_t)layer * 64 + nt) * 12 + ktp) * 32 + lane) * 8 + (kt_in * 2 + reg) * 2 + par;
    dst[off] = __float2half_rn(v);
}

// ===========================================================================
// Tail fold: Wcat / c0
// ===========================================================================
__global__ void prep_wc_kernel(const float* __restrict__ Wo, const float* __restrict__ bo,
                               const float* __restrict__ f1w,
                               float* __restrict__ wcat, float* __restrict__ c0) {
    int l = blockIdx.x >> 7;
    int i = blockIdx.x & 127;
    int k = threadIdx.x;
    const float* f1 = f1w + ((size_t)l * 128 + i) * 384;
    float v;
    if (k < 256) {
        const float* wo = Wo + (size_t)l * 256 * 256;
        float s = 0.f;
#pragma unroll 4
        for (int j = 0; j < 256; j++) s = fmaf(f1[j], wo[j * 256 + k], s);
        v = s;
    } else {
        v = f1[k];
    }
    wcat[((size_t)l * 128 + i) * 384 + k] = v;
    if (k == 0) {
        const float* bol = bo + l * 256;
        float s = 0.f;
#pragma unroll 4
        for (int j = 0; j < 256; j++) s = fmaf(f1[j], bol[j], s);
        c0[l * 128 + i] = s;
    }
}

// ===========================================================================
// Q-bias fold: bq2[l][n] = bq[l][n] + sum_j cos(tb[j]) * Wq[l][n][128+j]
// ===========================================================================
__global__ void prep_bq_kernel(const float* __restrict__ Wq, const float* __restrict__ bq,
                               const float* __restrict__ tb, float* __restrict__ bq2) {
    int l = blockIdx.x;
    int n = threadIdx.x;
    __shared__ float st[128];
    if (n < 128) st[n] = __cosf(tb[n]);
    __syncthreads();
    const float* w = Wq + (((size_t)l * 256 + n) * 256) + 128;
    float s = bq[l * 256 + n];
#pragma unroll 4
    for (int j = 0; j < 128; j++) s = fmaf(st[j], w[j], s);
    bq2[l * 256 + n] = s;
}

// ===========================================================================
// KV projection kernel (R11/v7): fp16 mma m16n8k16, persistent CTAs,
// double-buffered fragment-permuted A; convert(i+1) after epilogue(i),
// one barrier per iteration; fast_cos on FMA pipe. Smem 96KB (L1 stays big).
// ===========================================================================
struct KvParams {
    const __half* Bp;
    const float *bk, *bv;
    __half* C;
    int DIV, nblk;
    const float *ts, *etm, *tw, *tb;
    const float *Adense, *nf, *memv, *ef;
    const int *idx, *eidx;
};

#define KV_DSMEM (2 * 49152)

__device__ __forceinline__ void kv_stash_h2(uint32_t* As, int m, int k, uint32_t h2) {
    int kt = k >> 4, mi = m >> 4;
    int r16 = m & 15, gid = r16 & 7, hi_r = r16 >> 3;
    int klo = k & 15, tg = (klo & 7) >> 1;
    int reg = hi_r + ((klo >> 3) << 1);
    As[(((kt * 4 + mi) * 32) + gid * 4 + tg) * 4 + reg] = h2;
}

template <int DENSE>
__device__ __forceinline__ void kv_convert(uint32_t* As, int bm, const KvParams& p, int tid) {
    const int grow = tid >> 3;
    const int gseg = tid & 7;
    const int m = bm + grow;
    if (DENSE) {
        const float4* s = (const float4*)(p.Adense + (size_t)m * 128);
#pragma unroll
        for (int i = 0; i < 4; i++) {
            int cf = gseg + 8 * i;
            float4 v = s[cf];
            int k = cf * 4;
            kv_stash_h2(As, grow, k, f2h2(v.x, v.y));
            kv_stash_h2(As, grow, k + 2, f2h2(v.z, v.w));
        }
    } else {
        int nd = __ldg(&p.idx[m]);
        const float4* s0 = (const float4*)(p.nf + (size_t)nd * 128);
        const float4* s1 = (const float4*)(p.memv + (size_t)nd * 128);
#pragma unroll
        for (int i = 0; i < 4; i++) {
            int cf = gseg + 8 * i;
            float4 x = s0[cf], y = s1[cf];
            int k = cf * 4;
            kv_stash_h2(As, grow, k, f2h2(x.x + y.x, x.y + y.y));
            kv_stash_h2(As, grow, k + 2, f2h2(x.z + y.z, x.w + y.w));
        }
    }
    {
        int e = __ldg(&p.eidx[m]);
        const float4* s = (const float4*)(p.ef + (size_t)e * 128);
#pragma unroll
        for (int i = 0; i < 4; i++) {
            int cf = gseg + 8 * i;
            float4 v = s[cf];
            int k = cf * 4;
            kv_stash_h2(As, grow, 128 + k, f2h2(v.x, v.y));
            kv_stash_h2(As, grow, 128 + k + 2, f2h2(v.z, v.w));
        }
    }
    float dt = __ldg(&p.ts[m / p.DIV]) - __ldg(&p.etm[m]);
#pragma unroll
    for (int i = 0; i < 4; i++) {
        int j0 = (gseg + 8 * i) * 4;
        float c0 = fast_cos(fmaf(dt, __ldg(&p.tw[j0 + 0]), __ldg(&p.tb[j0 + 0])));
        float c1 = fast_cos(fmaf(dt, __ldg(&p.tw[j0 + 1]), __ldg(&p.tb[j0 + 1])));
        float c2 = fast_cos(fmaf(dt, __ldg(&p.tw[j0 + 2]), __ldg(&p.tb[j0 + 2])));
        float c3 = fast_cos(fmaf(dt, __ldg(&p.tw[j0 + 3]), __ldg(&p.tb[j0 + 3])));
        kv_stash_h2(As, grow, 256 + j0, f2h2(c0, c1));
        kv_stash_h2(As, grow, 256 + j0 + 2, f2h2(c2, c3));
    }
}

template <int DENSE>
__global__ void __launch_bounds__(512, 1) kv_kernel(KvParams p) {
    extern __shared__ char smem[];
    uint32_t* perm = (uint32_t*)smem;

    const int tid = threadIdx.x;
    const int lane = tid & 31;
    const int wid = tid >> 5;
    const int gID = lane >> 2;
    const int tg = lane & 3;
    const char* bpw = (const char*)p.Bp + (size_t)(wid * 4) * 6144;

    int blk = blockIdx.x;
    if (blk < p.nblk) kv_convert<DENSE>(perm, blk * 64, p, tid);
    __syncthreads();

    int parity = 0;
#pragma unroll 1
    for (; blk < p.nblk; blk += gridDim.x) {
        const int bm = blk * 64;
        const uint4* As4 = (const uint4*)(perm + parity * 12288);

        float acc[4][4][4];
#pragma unroll
        for (int mi = 0; mi < 4; mi++)
#pragma unroll
            for (int nj = 0; nj < 4; nj++)
#pragma unroll
                for (int q = 0; q < 4; q++) acc[mi][nj][q] = 0.f;

        uint4 bA[4], bB[4];

#define KV_LDB(buf, ktp_) { \
    _Pragma("unroll") \
    for (int nj = 0; nj < 4; nj++) \
        buf[nj] = *(const uint4*)(bpw + (size_t)nj * 6144 + (ktp_) * 512 + lane * 16); }

#define KV_STEP(buf, ktp_) { \
    _Pragma("unroll") \
    for (int kt_in = 0; kt_in < 2; kt_in++) { \
        const int kt = (ktp_) * 2 + kt_in; \
        _Pragma("unroll") \
        for (int mi = 0; mi < 4; mi++) { \
            uint4 av = As4[(kt * 4 + mi) * 32 + lane]; \
            uint32_t aa[4] = {av.x, av.y, av.z, av.w}; \
            _Pragma("unroll") \
            for (int nj = 0; nj < 4; nj++) { \
                uint32_t b0 = kt_in ? buf[nj].z : buf[nj].x; \
                uint32_t b1 = kt_in ? buf[nj].w : buf[nj].y; \
                mma_f16(acc[mi][nj], aa, b0, b1); \
            } \
        } \
    } }

        KV_LDB(bA, 0);
#pragma unroll 1
        for (int ktp = 0; ktp < 12; ktp += 2) {
            KV_LDB(bB, ktp + 1);
            KV_STEP(bA, ktp);
            if (ktp + 2 < 12) KV_LDB(bA, ktp + 2);
            KV_STEP(bB, ktp + 1);
        }
#undef KV_LDB
#undef KV_STEP

#pragma unroll
        for (int mi = 0; mi < 4; mi++) {
            const int r_lo = bm + mi * 16 + gID;
            __half* clo = p.C + (size_t)r_lo * 512;
            __half* chi = clo + (size_t)8 * 512;
#pragma unroll
            for (int nj = 0; nj < 4; nj++) {
                const int col = wid * 32 + nj * 8 + tg * 2;
                const float b0 = (col < 256) ? __ldg(&p.bk[col]) : __ldg(&p.bv[col - 256]);
                const float b1 = (col + 1 < 256) ? __ldg(&p.bk[col + 1]) : __ldg(&p.bv[col + 1 - 256]);
                *(__half2*)(clo + col) = __floats2half2_rn(acc[mi][nj][0] + b0, acc[mi][nj][1] + b1);
                *(__half2*)(chi + col) = __floats2half2_rn(acc[mi][nj][2] + b0, acc[mi][nj][3] + b1);
            }
        }

        {
            int nxt = blk + gridDim.x;
            if (nxt < p.nblk)
                kv_convert<DENSE>(perm + (parity ^ 1) * 12288, nxt * 64, p, tid);
        }
        __syncthreads();
        parity ^= 1;
    }
}

// ===========================================================================
// fp16 mma.sync GEMM m16n8k16: CTA = 128(m) x 128(n).
//   AH=1: dense A operand is fp16 (direct copy, no conversion).
//   half_out: write C as fp16.
// ===========================================================================
struct TcParams {
    int Kdim, ldA, ldC, ldW, half_out;
    const float* W;
    const float* bias;
    const float* cbias;
    void* C;
    int relu;
    const unsigned char* invalid;
    const float* Adense;
    const __half* Ah;
    const float *nf, *memv;
    const int *idx;
};

template <int MODE, int AH>
__global__ void __launch_bounds__(256) mma_gemm(TcParams p) {
    __shared__ uint32_t As[128][20];
    __shared__ uint32_t Bs[128][20];
    const int tid = threadIdx.x;
    const int lane = tid & 31;
    const int wid = tid >> 5;
    const int bm = blockIdx.x * 128;
    const int noff = blockIdx.y * 128;
    const float* W = p.W + (size_t)noff * p.ldW;
    const float* bias = p.bias + noff;
    const int row = tid >> 1;
    const int seg = tid & 1;
    const int m = bm + row;
    const int wr = (wid >> 1) * 32;
    const int wc = (wid & 1) * 64;
    const int groupID = lane >> 2;
    const int tg = lane & 3;

    float acc[2][8][4];
#pragma unroll
    for (int mi = 0; mi < 2; mi++)
#pragma unroll
        for (int nj = 0; nj < 8; nj++)
#pragma unroll
            for (int q = 0; q < 4; q++) acc[mi][nj][q] = 0.f;

#pragma unroll 1
    for (int k0 = 0; k0 < p.Kdim; k0 += 32) {
        const int kb = k0 + seg * 16;
        // ---- stage A ----
        {
            bool use_half = false;
            const __half* ah = nullptr;
            const float* s0 = nullptr;
            const float* s1 = nullptr;
            if constexpr (MODE == MODE_PLAIN) {
                s0 = p.Adense + (size_t)m * p.ldA + kb;
            } else if constexpr (MODE == MODE_QGATHER) {
                int nd = __ldg(&p.idx[m]);
                s0 = p.nf + (size_t)nd * 128 + kb;
                s1 = p.memv + (size_t)nd * 128 + kb;
            } else {  // MODE_CONCAT
                if (kb < 256) {
                    if (AH) {
                        use_half = true;
                        ah = p.Ah + (size_t)m * 256 + kb;
                    } else {
                        s0 = p.Adense + (size_t)m * 256 + kb;
                    }
                } else {
                    int nd = __ldg(&p.idx[m]);
                    s0 = p.nf + (size_t)nd * 128 + (kb - 256);
                    s1 = p.memv + (size_t)nd * 128 + (kb - 256);
                }
            }
            if (AH && use_half) {
                uint4 u0 = *(const uint4*)ah;
                uint4 u1 = *(const uint4*)(ah + 8);
                *(uint4*)&As[row][seg * 8] = u0;
                *(uint4*)&As[row][seg * 8 + 4] = u1;
            } else {
                uint32_t h[8];
#pragma unroll
                for (int i = 0; i < 4; i++) {
                    float4 v = *(const float4*)(s0 + i * 4);
                    if (s1) {
                        float4 w = *(const float4*)(s1 + i * 4);
                        v.x += w.x; v.y += w.y; v.z += w.z; v.w += w.w;
                    }
                    h[i * 2 + 0] = f2h2(v.x, v.y);
                    h[i * 2 + 1] = f2h2(v.z, v.w);
                }
                *(uint4*)&As[row][seg * 8] = make_uint4(h[0], h[1], h[2], h[3]);
                *(uint4*)&As[row][seg * 8 + 4] = make_uint4(h[4], h[5], h[6], h[7]);
            }
        }
        // ---- stage B ----
        {
            const float* wsrc = W + (size_t)row * p.ldW + kb;
            uint32_t h[8];
#pragma unroll
            for (int i = 0; i < 4; i++) {
                float4 v = *(const float4*)(wsrc + i * 4);
                h[i * 2 + 0] = f2h2(v.x, v.y);
                h[i * 2 + 1] = f2h2(v.z, v.w);
            }
            *(uint4*)&Bs[row][seg * 8] = make_uint4(h[0], h[1], h[2], h[3]);
            *(uint4*)&Bs[row][seg * 8 + 4] = make_uint4(h[4], h[5], h[6], h[7]);
        }
        __syncthreads();
#pragma unroll
        for (int kt = 0; kt < 2; kt++) {
            const int cb = kt * 8;
            uint32_t a[2][4];
#pragma unroll
            for (int mi = 0; mi < 2; mi++) {
                int r0 = wr + mi * 16 + groupID;
                a[mi][0] = As[r0][cb + tg];
                a[mi][1] = As[r0 + 8][cb + tg];
                a[mi][2] = As[r0][cb + 4 + tg];
                a[mi][3] = As[r0 + 8][cb + 4 + tg];
            }
#pragma unroll
            for (int nj = 0; nj < 8; nj++) {
                int nb_ = wc + nj * 8 + groupID;
                uint32_t b0 = Bs[nb_][cb + tg];
                uint32_t b1 = Bs[nb_][cb + 4 + tg];
                mma_f16(acc[0][nj], a[0], b0, b1);
                mma_f16(acc[1][nj], a[1], b0, b1);
            }
        }
        __syncthreads();
    }

#pragma unroll
    for (int mi = 0; mi < 2; mi++) {
        const int r_lo = bm + wr + mi * 16 + groupID;
        const int r_hi = r_lo + 8;
        const bool z_lo = (p.invalid != nullptr) && p.invalid[r_lo];
        const bool z_hi = (p.invalid != nullptr) && p.invalid[r_hi];
#pragma unroll
        for (int nj = 0; nj < 8; nj++) {
            const int cl = wc + nj * 8 + tg * 2;
            const float b0 = __ldg(&bias[cl]);
            const float b1 = __ldg(&bias[cl + 1]);
            float cb0 = 0.f, cb1 = 0.f;
            if (p.cbias) {
                cb0 = __ldg(&p.cbias[noff + cl]);
                cb1 = __ldg(&p.cbias[noff + cl + 1]);
            }
            float v00 = acc[mi][nj][0] + b0 + (z_lo ? 0.f : cb0);
            float v01 = acc[mi][nj][1] + b1 + (z_lo ? 0.f : cb1);
            float v10 = acc[mi][nj][2] + b0 + (z_hi ? 0.f : cb0);
            float v11 = acc[mi][nj][3] + b1 + (z_hi ? 0.f : cb1);
            if (p.relu) {
                v00 = fmaxf(v00, 0.f); v01 = fmaxf(v01, 0.f);
                v10 = fmaxf(v10, 0.f); v11 = fmaxf(v11, 0.f);
            }
            if (p.half_out) {
                __half* clo = (__half*)p.C + (size_t)r_lo * p.ldC + noff;
                __half* chi = (__half*)p.C + (size_t)r_hi * p.ldC + noff;
                *(__half2*)(clo + cl) = __floats2half2_rn(v00, v01);
                *(__half2*)(chi + cl) = __floats2half2_rn(v10, v11);
            } else {
                float* clo = (float*)p.C + (size_t)r_lo * p.ldC + noff;
                float* chi = (float*)p.C + (size_t)r_hi * p.ldC + noff;
                *(float2*)(clo + cl) = make_float2(v00, v01);
                *(float2*)(chi + cl) = make_float2(v10, v11);
            }
        }
    }
}

// ---------------------------------------------------------------------------
// Temporal attention (q fp16, kv fp16, out fp16); zeroes invalid rows.
// ---------------------------------------------------------------------------
__global__ void attn_kernel(const __half* __restrict__ q, const __half* __restrict__ kv,
                            const int* __restrict__ nbrs, __half* __restrict__ outp,
                            unsigned char* __restrict__ invalid) {
    const int r = blockIdx.x;
    const int tid = threadIdx.x;
    const int warp = tid >> 5;
    const int lane = tid & 31;
    __shared__ float sq[256];
    __shared__ float sc[2][KNB];
    __shared__ float swt[2][KNB];
    __shared__ int smask[KNB];
    __shared__ int sinv;

    if (tid < 256) sq[tid] = __half2float(q[(size_t)r * 256 + tid]);
    if (tid < KNB) smask[tid] = (nbrs[r * KNB + tid] != 0) ? 1 : 0;
    __syncthreads();
    if (tid == 0) {
        int any = 0;
#pragma unroll
        for (int k = 0; k < KNB; k++) any |= smask[k];
        if (!any) smask[KNB - 1] = 1;
        sinv = !any;
        invalid[r] = (unsigned char)(!any);
    }
    __syncthreads();

    if (warp < KNB) {
        const __half* kp = kv + ((size_t)r * KNB + warp) * 512;
        float s0 = 0.f, s1 = 0.f;
#pragma unroll
        for (int i = 0; i < 4; i++) {
            int d = lane + 32 * i;
            s0 = fmaf(sq[d], __half2float(__ldg(&kp[d])), s0);
            s1 = fmaf(sq[128 + d], __half2float(__ldg(&kp[128 + d])), s1);
        }
#pragma unroll
        for (int o = 16; o > 0; o >>= 1) {
            s0 += __shfl_down_sync(0xffffffffu, s0, o);
            s1 += __shfl_down_sync(0xffffffffu, s1, o);
        }
        if (lane == 0) {
            const float scale = 0.08838834764831845f;
            sc[0][warp] = smask[warp] ? s0 * scale : -1e9f;
            sc[1][warp] = smask[warp] ? s1 * scale : -1e9f;
        }
    }
    __syncthreads();

    if (tid < 2) {
        float mx = -3.0e38f;
#pragma unroll
        for (int k = 0; k < KNB; k++) mx = fmaxf(mx, sc[tid][k]);
        float sum = 0.f;
#pragma unroll
        for (int k = 0; k < KNB; k++) {
            float e = __expf(sc[tid][k] - mx);
            swt[tid][k] = e;
            sum += e;
        }
        float inv = 1.0f / sum;
#pragma unroll
        for (int k = 0; k < KNB; k++) swt[tid][k] *= inv;
    }
    __syncthreads();

    if (tid < 256) {
        int h = tid >> 7;
        float o = 0.f;
#pragma unroll
        for (int k = 0; k < KNB; k++)
            o = fmaf(swt[h][k], __half2float(__ldg(&kv[((size_t)r * KNB + k) * 512 + 256 + tid])), o);
        outp[(size_t)r * 256 + tid] = __float2half(sinv ? 0.f : o);
    }
}

// ---------------------------------------------------------------------------
// Host side
// ---------------------------------------------------------------------------
static void launch_mma(int mode, int ah, int M, int nchunks, const TcParams& p, cudaStream_t s) {
    dim3 grid(M / 128, nchunks);
    if (mode == MODE_PLAIN) {
        mma_gemm<MODE_PLAIN, 0><<<grid, 256, 0, s>>>(p);
    } else if (mode == MODE_QGATHER) {
        mma_gemm<MODE_QGATHER, 0><<<grid, 256, 0, s>>>(p);
    } else {
        if (ah) mma_gemm<MODE_CONCAT, 1><<<grid, 256, 0, s>>>(p);
        else    mma_gemm<MODE_CONCAT, 0><<<grid, 256, 0, s>>>(p);
    }
}

extern "C" void kernel_launch(void* const* d_in, const int* in_sizes, int n_in,
                              void* d_out, int out_size) {
    const float* nf   = (const float*)d_in[0];
    const float* mem  = (const float*)d_in[1];
    const float* ef   = (const float*)d_in[2];
    const float* tw   = (const float*)d_in[3];
    const float* tb   = (const float*)d_in[4];
    const float* Wq   = (const float*)d_in[5];
    const float* bq   = (const float*)d_in[6];
    const float* Wk   = (const float*)d_in[7];
    const float* bk   = (const float*)d_in[8];
    const float* Wv   = (const float*)d_in[9];
    const float* bv   = (const float*)d_in[10];
    const float* Wo   = (const float*)d_in[11];
    const float* bo   = (const float*)d_in[12];
    const float* f1w  = (const float*)d_in[13];
    const float* f1b  = (const float*)d_in[14];
    const float* f2w  = (const float*)d_in[15];
    const float* f2b  = (const float*)d_in[16];
    const int*   src  = (const int*)d_in[17];
    const float* ts   = (const float*)d_in[18];
    const int*   nb2  = (const int*)d_in[19];
    const int*   ei2  = (const int*)d_in[20];
    const float* tm2  = (const float*)d_in[21];
    const int*   nb1  = (const int*)d_in[22];
    const int*   ei1  = (const int*)d_in[23];
    const float* tm1  = (const float*)d_in[24];
    float* out = (float*)d_out;

    float *ph1, *pemb1, *ph2, *pwcat, *pc0, *pbq2;
    __half *pkv1, *pkv2, *pbph, *pq1, *pq2, *pattn1, *pattn2;
    unsigned char *pinv1, *pinv2;
    cudaGetSymbolAddress((void**)&pkv1, g_kv1);
    cudaGetSymbolAddress((void**)&pq1, g_q1);
    cudaGetSymbolAddress((void**)&pattn1, g_attn1);
    cudaGetSymbolAddress((void**)&ph1, g_h1);
    cudaGetSymbolAddress((void**)&pemb1, g_emb1);
    cudaGetSymbolAddress((void**)&pinv1, g_inv1);
    cudaGetSymbolAddress((void**)&pkv2, g_kv2);
    cudaGetSymbolAddress((void**)&pq2, g_q2);
    cudaGetSymbolAddress((void**)&pattn2, g_attn2);
    cudaGetSymbolAddress((void**)&ph2, g_h2);
    cudaGetSymbolAddress((void**)&pinv2, g_inv2);
    cudaGetSymbolAddress((void**)&pbph, g_bph);
    cudaGetSymbolAddress((void**)&pwcat, g_wcat);
    cudaGetSymbolAddress((void**)&pc0, g_c0);
    cudaGetSymbolAddress((void**)&pbq2, g_bq2);

    static cudaStream_t s_side = nullptr;
    static cudaEvent_t ev_fork = nullptr, ev_join = nullptr;
    if (s_side == nullptr) {
        cudaStreamCreateWithFlags(&s_side, cudaStreamNonBlocking);
        cudaEventCreateWithFlags(&ev_fork, cudaEventDisableTiming);
        cudaEventCreateWithFlags(&ev_join, cudaEventDisableTiming);
        cudaFuncSetAttribute(kv_kernel<0>, cudaFuncAttributeMaxDynamicSharedMemorySize, KV_DSMEM);
        cudaFuncSetAttribute(kv_kernel<1>, cudaFuncAttributeMaxDynamicSharedMemorySize, KV_DSMEM);
    }

    const cudaStream_t s0 = 0;

    const float* bk1 = bk + 256;
    const float* bv1 = bv + 256;
    const float* f2w1 = f2w + 128 * 128; const float* f2b1 = f2b + 128;

    // ---- fork immediately: side stream does preps + Q1 + Q2 + layer-1 B prep ----
    cudaEventRecord(ev_fork, s0);
    cudaStreamWaitEvent(s_side, ev_fork, 0);

    prep_b_kernel<<<(512 * 384 + 255) / 256, 256, 0, s_side>>>(Wk, Wv, pbph, 1);
    prep_bq_kernel<<<2, 256, 0, s_side>>>(Wq, bq, tb, pbq2);
    prep_wc_kernel<<<256, 384, 0, s_side>>>(Wo, bo, f1w, pwcat, pc0);
    {   // Q1 (fp16 out, K=128): [20480,256], 2 col chunks
        TcParams p{};
        p.Kdim = 128; p.ldC = 256; p.ldW = 256; p.half_out = 1;
        p.W = Wq; p.bias = pbq2; p.C = pq1;
        p.nf = nf; p.memv = mem; p.idx = nb2;
        launch_mma(MODE_QGATHER, 0, N1, 2, p, s_side);
    }
    {   // Q2 (fp16 out, K=128)
        TcParams p{};
        p.Kdim = 128; p.ldC = 256; p.ldW = 256; p.half_out = 1;
        p.W = Wq + 256 * 256; p.bias = pbq2 + 256; p.C = pq2;
        p.nf = nf; p.memv = mem; p.idx = src;
        launch_mma(MODE_QGATHER, 0, BB, 2, p, s_side);
    }
    cudaEventRecord(ev_join, s_side);

    // ---- main stream: layer-0 B prep then KV1 (persistent, 136 SMs) ----
    prep_b_kernel<<<(512 * 384 + 255) / 256, 256, 0, s0>>>(Wk, Wv, pbph, 0);
    {
        KvParams p{};
        p.Bp = pbph; p.bk = bk; p.bv = bv; p.C = pkv1;
        p.DIV = 100; p.nblk = NP1 / 64;
        p.ts = ts; p.etm = tm1; p.tw = tw; p.tb = tb;
        p.nf = nf; p.memv = mem; p.ef = ef; p.idx = nb1; p.eidx = ei1;
        kv_kernel<0><<<136, 512, KV_DSMEM, s0>>>(p);
    }
    cudaStreamWaitEvent(s0, ev_join, 0);

    attn_kernel<<<N1, 320, 0, s0>>>(pq1, pkv1, nb1, pattn1, pinv1);
    {   // fused O1+fc1 (fp16, A dense fp16): K=384, conditional c0, relu
        TcParams p{};
        p.Kdim = 384; p.ldC = 128; p.ldW = 384;
        p.W = pwcat; p.bias = f1b; p.cbias = pc0; p.C = ph1;
        p.Ah = pattn1; p.nf = nf; p.memv = mem; p.idx = nb2;
        p.invalid = pinv1; p.relu = 1;
        launch_mma(MODE_CONCAT, 1, N1, 1, p, s0);
    }
    {   // fc2 L0 (fp16) -> emb1
        TcParams p{};
        p.Kdim = 128; p.ldA = 128; p.ldC = 128; p.ldW = 128;
        p.W = f2w; p.bias = f2b; p.C = pemb1; p.Adense = ph1;
        launch_mma(MODE_PLAIN, 0, N1, 1, p, s0);
    }
    {   // KV2 (fp16, dense, persistent)
        KvParams p{};
        p.Bp = pbph + 512 * 384; p.bk = bk1; p.bv = bv1; p.C = pkv2;
        p.DIV = 10; p.nblk = NP2 / 64;
        p.ts = ts; p.etm = tm2; p.tw = tw; p.tb = tb;
        p.Adense = pemb1; p.ef = ef; p.eidx = ei2;
        kv_kernel<1><<<148, 512, KV_DSMEM, s0>>>(p);
    }
    attn_kernel<<<BB, 320, 0, s0>>>(pq2, pkv2, nb2, pattn2, pinv2);
    {   // fused O2+fc1 L1 (fp16, A dense fp16)
        TcParams p{};
        p.Kdim = 384; p.ldC = 128; p.ldW = 384;
        p.W = pwcat + 128 * 384; p.bias = f1b + 128; p.cbias = pc0 + 128; p.C = ph2;
        p.Ah = pattn2; p.nf = nf; p.memv = mem; p.idx = src;
        p.invalid = pinv2; p.relu = 1;
        launch_mma(MODE_CONCAT, 1, BB, 1, p, s0);
    }
    {   // fc2 L1 (fp16) -> out
        TcParams p{};
        p.Kdim = 128; p.ldA = 128; p.ldC = 128; p.ldW = 128;
        p.W = f2w1; p.bias = f2b1; p.C = out; p.Adense = ph2;
        launch_mma(MODE_PLAIN, 0, BB, 1, p, s0);
    }
}

// round 14
// speedup vs baseline: 1.1584x; 1.0080x over previous
#include <cuda_runtime.h>
#include <cuda_fp16.h>
#include <cstdint>

// ---------------------------------------------------------------------------
// Problem constants
// ---------------------------------------------------------------------------
#define KNB 10
#define BB  2048
#define N1  20480
#define NP1 204800
#define NP2 20480
// D = T = 128, QD = 256, KD = 384, H = 2, hd = 128

// ---------------------------------------------------------------------------
// Scratch
// ---------------------------------------------------------------------------
__device__ __half g_kv1[(size_t)NP1 * 512];
__device__ __half g_q1 [(size_t)N1  * 256];
__device__ __half g_attn1[(size_t)N1 * 256];
__device__ float g_emb1[(size_t)N1 * 128];
__device__ unsigned char g_inv1[N1];
__device__ __half g_kv2[(size_t)NP2 * 512];
__device__ __half g_q2 [(size_t)BB  * 256];
__device__ __half g_attn2[(size_t)BB * 256];
__device__ unsigned char g_inv2[BB];
// pre-permuted fragment-ordered fp16 weights for KV (2 layers x 512 n x 384 k)
__device__ __half g_bph[2 * 512 * 384];
// folded tail weights: Wcat = [f1w_left@Wo || f1w_right]  (2 layers x 128 x 384)
__device__ float g_wcat[2 * 128 * 384];
__device__ float g_c0[2 * 128];          // f1w_left @ bo per layer
__device__ float g_bq2[2 * 256];         // bq + st @ Wq_right^T per layer

// ---------------------------------------------------------------------------
// fp16 mma helper + fast cosine (FMA-pipe) + policy loads
// ---------------------------------------------------------------------------
__device__ __forceinline__ void mma_f16(float* c, const uint32_t* a, uint32_t b0, uint32_t b1) {
    asm volatile(
        "mma.sync.aligned.m16n8k16.row.col.f32.f16.f16.f32 "
        "{%0,%1,%2,%3}, {%4,%5,%6,%7}, {%8,%9}, {%0,%1,%2,%3};"
        : "+f"(c[0]), "+f"(c[1]), "+f"(c[2]), "+f"(c[3])
        : "r"(a[0]), "r"(a[1]), "r"(a[2]), "r"(a[3]), "r"(b0), "r"(b1));
}
__device__ __forceinline__ uint32_t f2h2(float a, float b) {
    __half2 h = __floats2half2_rn(a, b);
    return *(uint32_t*)&h;
}
__device__ __forceinline__ float fast_cos(float t) {
    float qf = rintf(t * 0.6366197723675814f);
    int q = (int)qf;
    float r = fmaf(qf, -1.5707962513f, t);
    r = fmaf(qf, -7.54978942e-8f, r);
    float z = r * r;
    float cp = fmaf(z, fmaf(z, fmaf(z, -1.3888397e-3f, 4.16666418e-2f), -0.5f), 1.0f);
    float sp = r * fmaf(z, fmaf(z, 8.3321608e-3f, -1.66666547e-1f), 1.0f);
    float v = (q & 1) ? sp : cp;
    uint32_t sgn = (uint32_t)((q + 1) & 2) << 30;
    return __uint_as_float(__float_as_uint(v) ^ sgn);
}
__device__ __forceinline__ uint4 ldg_el(const void* p) {
    uint4 v;
    asm volatile("ld.global.nc.L1::evict_last.v4.u32 {%0,%1,%2,%3}, [%4];"
        : "=r"(v.x), "=r"(v.y), "=r"(v.z), "=r"(v.w) : "l"(p));
    return v;
}
__device__ __forceinline__ uint4 ldg_ef(const void* p) {
    uint4 v;
    asm volatile("ld.global.nc.L1::evict_first.v4.u32 {%0,%1,%2,%3}, [%4];"
        : "=r"(v.x), "=r"(v.y), "=r"(v.z), "=r"(v.w) : "l"(p));
    return v;
}

// ===========================================================================
// B pre-permutation (one layer per launch)
// ===========================================================================
__global__ void prep_b_kernel(const float* __restrict__ Wk, const float* __restrict__ Wv,
                              __half* __restrict__ dst, int layer) {
    int idx = blockIdx.x * blockDim.x + threadIdx.x;
    if (idx >= 512 * 384) return;
    int n = idx / 384;
    int k = idx - n * 384;
    const float* W = (n < 256) ? (Wk + (size_t)layer * 256 * 384 + (size_t)n * 384)
                               : (Wv + (size_t)layer * 256 * 384 + (size_t)(n - 256) * 384);
    float v = W[k];
    int nt = n >> 3, gid = n & 7;
    int ktp = k >> 5, k32 = k & 31;
    int kt_in = k32 >> 4, klo = k32 & 15;
    int tg = (klo & 7) >> 1, reg = klo >> 3, par = k & 1;
    int lane = gid * 4 + tg;
    size_t off = ((((size_t)layer * 64 + nt) * 12 + ktp) * 32 + lane) * 8 + (kt_in * 2 + reg) * 2 + par;
    dst[off] = __float2half_rn(v);
}

// ===========================================================================
// Tail fold: Wcat / c0
// ===========================================================================
__global__ void prep_wc_kernel(const float* __restrict__ Wo, const float* __restrict__ bo,
                               const float* __restrict__ f1w,
                               float* __restrict__ wcat, float* __restrict__ c0) {
    int l = blockIdx.x >> 7;
    int i = blockIdx.x & 127;
    int k = threadIdx.x;
    const float* f1 = f1w + ((size_t)l * 128 + i) * 384;
    float v;
    if (k < 256) {
        const float* wo = Wo + (size_t)l * 256 * 256;
        float s = 0.f;
#pragma unroll 4
        for (int j = 0; j < 256; j++) s = fmaf(f1[j], wo[j * 256 + k], s);
        v = s;
    } else {
        v = f1[k];
    }
    wcat[((size_t)l * 128 + i) * 384 + k] = v;
    if (k == 0) {
        const float* bol = bo + l * 256;
        float s = 0.f;
#pragma unroll 4
        for (int j = 0; j < 256; j++) s = fmaf(f1[j], bol[j], s);
        c0[l * 128 + i] = s;
    }
}

// ===========================================================================
// Q-bias fold
// ===========================================================================
__global__ void prep_bq_kernel(const float* __restrict__ Wq, const float* __restrict__ bq,
                               const float* __restrict__ tb, float* __restrict__ bq2) {
    int l = blockIdx.x;
    int n = threadIdx.x;
    __shared__ float st[128];
    if (n < 128) st[n] = __cosf(tb[n]);
    __syncthreads();
    const float* w = Wq + (((size_t)l * 256 + n) * 256) + 128;
    float s = bq[l * 256 + n];
#pragma unroll 4
    for (int j = 0; j < 128; j++) s = fmaf(st[j], w[j], s);
    bq2[l * 256 + n] = s;
}

// ===========================================================================
// KV projection kernel: fp16 mma m16n8k16, persistent CTAs, double-buffered
// fragment-permuted A; B loads with L1 eviction policy (ktp<3 pinned).
// ===========================================================================
struct KvParams {
    const __half* Bp;
    const float *bk, *bv;
    __half* C;
    int DIV, nblk;
    const float *ts, *etm, *tw, *tb;
    const float *Adense, *nf, *memv, *ef;
    const int *idx, *eidx;
};

#define KV_DSMEM (2 * 49152)

__device__ __forceinline__ void kv_stash_h2(uint32_t* As, int m, int k, uint32_t h2) {
    int kt = k >> 4, mi = m >> 4;
    int r16 = m & 15, gid = r16 & 7, hi_r = r16 >> 3;
    int klo = k & 15, tg = (klo & 7) >> 1;
    int reg = hi_r + ((klo >> 3) << 1);
    As[(((kt * 4 + mi) * 32) + gid * 4 + tg) * 4 + reg] = h2;
}

template <int DENSE>
__device__ __forceinline__ void kv_convert(uint32_t* As, int bm, const KvParams& p, int tid) {
    const int grow = tid >> 3;
    const int gseg = tid & 7;
    const int m = bm + grow;
    if (DENSE) {
        const float4* s = (const float4*)(p.Adense + (size_t)m * 128);
#pragma unroll
        for (int i = 0; i < 4; i++) {
            int cf = gseg + 8 * i;
            float4 v = s[cf];
            int k = cf * 4;
            kv_stash_h2(As, grow, k, f2h2(v.x, v.y));
            kv_stash_h2(As, grow, k + 2, f2h2(v.z, v.w));
        }
    } else {
        int nd = __ldg(&p.idx[m]);
        const float4* s0 = (const float4*)(p.nf + (size_t)nd * 128);
        const float4* s1 = (const float4*)(p.memv + (size_t)nd * 128);
#pragma unroll
        for (int i = 0; i < 4; i++) {
            int cf = gseg + 8 * i;
            float4 x = s0[cf], y = s1[cf];
            int k = cf * 4;
            kv_stash_h2(As, grow, k, f2h2(x.x + y.x, x.y + y.y));
            kv_stash_h2(As, grow, k + 2, f2h2(x.z + y.z, x.w + y.w));
        }
    }
    {
        int e = __ldg(&p.eidx[m]);
        const float4* s = (const float4*)(p.ef + (size_t)e * 128);
#pragma unroll
        for (int i = 0; i < 4; i++) {
            int cf = gseg + 8 * i;
            float4 v = s[cf];
            int k = cf * 4;
            kv_stash_h2(As, grow, 128 + k, f2h2(v.x, v.y));
            kv_stash_h2(As, grow, 128 + k + 2, f2h2(v.z, v.w));
        }
    }
    float dt = __ldg(&p.ts[m / p.DIV]) - __ldg(&p.etm[m]);
#pragma unroll
    for (int i = 0; i < 4; i++) {
        int j0 = (gseg + 8 * i) * 4;
        float c0 = fast_cos(fmaf(dt, __ldg(&p.tw[j0 + 0]), __ldg(&p.tb[j0 + 0])));
        float c1 = fast_cos(fmaf(dt, __ldg(&p.tw[j0 + 1]), __ldg(&p.tb[j0 + 1])));
        float c2 = fast_cos(fmaf(dt, __ldg(&p.tw[j0 + 2]), __ldg(&p.tb[j0 + 2])));
        float c3 = fast_cos(fmaf(dt, __ldg(&p.tw[j0 + 3]), __ldg(&p.tb[j0 + 3])));
        kv_stash_h2(As, grow, 256 + j0, f2h2(c0, c1));
        kv_stash_h2(As, grow, 256 + j0 + 2, f2h2(c2, c3));
    }
}

template <int DENSE>
__global__ void __launch_bounds__(512, 1) kv_kernel(KvParams p) {
    extern __shared__ char smem[];
    uint32_t* perm = (uint32_t*)smem;

    const int tid = threadIdx.x;
    const int lane = tid & 31;
    const int wid = tid >> 5;
    const int gID = lane >> 2;
    const int tg = lane & 3;
    const char* bpw = (const char*)p.Bp + (size_t)(wid * 4) * 6144;

    int blk = blockIdx.x;
    if (blk < p.nblk) kv_convert<DENSE>(perm, blk * 64, p, tid);
    __syncthreads();

    int parity = 0;
#pragma unroll 1
    for (; blk < p.nblk; blk += gridDim.x) {
        const int bm = blk * 64;
        const uint4* As4 = (const uint4*)(perm + parity * 12288);

        float acc[4][4][4];
#pragma unroll
        for (int mi = 0; mi < 4; mi++)
#pragma unroll
            for (int nj = 0; nj < 4; nj++)
#pragma unroll
                for (int q = 0; q < 4; q++) acc[mi][nj][q] = 0.f;

        uint4 bA[4], bB[4];

#define KV_LDB(buf, ktp_) { \
    _Pragma("unroll") \
    for (int nj = 0; nj < 4; nj++) { \
        const char* _ptr = bpw + (size_t)nj * 6144 + (ktp_) * 512 + lane * 16; \
        buf[nj] = ((ktp_) < 3) ? ldg_el(_ptr) : ldg_ef(_ptr); \
    } }

#define KV_STEP(buf, ktp_) { \
    _Pragma("unroll") \
    for (int kt_in = 0; kt_in < 2; kt_in++) { \
        const int kt = (ktp_) * 2 + kt_in; \
        _Pragma("unroll") \
        for (int mi = 0; mi < 4; mi++) { \
            uint4 av = As4[(kt * 4 + mi) * 32 + lane]; \
            uint32_t aa[4] = {av.x, av.y, av.z, av.w}; \
            _Pragma("unroll") \
            for (int nj = 0; nj < 4; nj++) { \
                uint32_t b0 = kt_in ? buf[nj].z : buf[nj].x; \
                uint32_t b1 = kt_in ? buf[nj].w : buf[nj].y; \
                mma_f16(acc[mi][nj], aa, b0, b1); \
            } \
        } \
    } }

        KV_LDB(bA, 0);
#pragma unroll 1
        for (int ktp = 0; ktp < 12; ktp += 2) {
            KV_LDB(bB, ktp + 1);
            KV_STEP(bA, ktp);
            if (ktp + 2 < 12) KV_LDB(bA, ktp + 2);
            KV_STEP(bB, ktp + 1);
        }
#undef KV_LDB
#undef KV_STEP

#pragma unroll
        for (int mi = 0; mi < 4; mi++) {
            const int r_lo = bm + mi * 16 + gID;
            __half* clo = p.C + (size_t)r_lo * 512;
            __half* chi = clo + (size_t)8 * 512;
#pragma unroll
            for (int nj = 0; nj < 4; nj++) {
                const int col = wid * 32 + nj * 8 + tg * 2;
                const float b0 = (col < 256) ? __ldg(&p.bk[col]) : __ldg(&p.bv[col - 256]);
                const float b1 = (col + 1 < 256) ? __ldg(&p.bk[col + 1]) : __ldg(&p.bv[col + 1 - 256]);
                *(__half2*)(clo + col) = __floats2half2_rn(acc[mi][nj][0] + b0, acc[mi][nj][1] + b1);
                *(__half2*)(chi + col) = __floats2half2_rn(acc[mi][nj][2] + b0, acc[mi][nj][3] + b1);
            }
        }

        {
            int nxt = blk + gridDim.x;
            if (nxt < p.nblk)
                kv_convert<DENSE>(perm + (parity ^ 1) * 12288, nxt * 64, p, tid);
        }
        __syncthreads();
        parity ^= 1;
    }
}

// ===========================================================================
// Q GEMM (fp16 m16n8k16): CTA = 128(m) x 128(n), K=128, gather A, fp16 out.
// ===========================================================================
struct TcParams {
    const float* W;      // ldW = 256
    const float* bias;
    __half* C;           // ldC = 256
    const float *nf, *memv;
    const int *idx;
};

__global__ void __launch_bounds__(256) q_gemm(TcParams p) {
    __shared__ uint32_t As[128][20];
    __shared__ uint32_t Bs[128][20];
    const int tid = threadIdx.x;
    const int lane = tid & 31;
    const int wid = tid >> 5;
    const int bm = blockIdx.x * 128;
    const int noff = blockIdx.y * 128;
    const float* W = p.W + (size_t)noff * 256;
    const float* bias = p.bias + noff;
    const int row = tid >> 1;
    const int seg = tid & 1;
    const int m = bm + row;
    const int wr = (wid >> 1) * 32;
    const int wc = (wid & 1) * 64;
    const int gID = lane >> 2;
    const int tg = lane & 3;

    float acc[2][8][4];
#pragma unroll
    for (int mi = 0; mi < 2; mi++)
#pragma unroll
        for (int nj = 0; nj < 8; nj++)
#pragma unroll
            for (int q = 0; q < 4; q++) acc[mi][nj][q] = 0.f;

#pragma unroll 1
    for (int k0 = 0; k0 < 128; k0 += 32) {
        const int kb = k0 + seg * 16;
        {
            int nd = __ldg(&p.idx[m]);
            const float* s0 = p.nf + (size_t)nd * 128 + kb;
            const float* s1 = p.memv + (size_t)nd * 128 + kb;
            uint32_t h[8];
#pragma unroll
            for (int i = 0; i < 4; i++) {
                float4 v = *(const float4*)(s0 + i * 4);
                float4 w = *(const float4*)(s1 + i * 4);
                v.x += w.x; v.y += w.y; v.z += w.z; v.w += w.w;
                h[i * 2 + 0] = f2h2(v.x, v.y);
                h[i * 2 + 1] = f2h2(v.z, v.w);
            }
            *(uint4*)&As[row][seg * 8] = make_uint4(h[0], h[1], h[2], h[3]);
            *(uint4*)&As[row][seg * 8 + 4] = make_uint4(h[4], h[5], h[6], h[7]);
        }
        {
            const float* wsrc = W + (size_t)row * 256 + kb;
            uint32_t h[8];
#pragma unroll
            for (int i = 0; i < 4; i++) {
                float4 v = *(const float4*)(wsrc + i * 4);
                h[i * 2 + 0] = f2h2(v.x, v.y);
                h[i * 2 + 1] = f2h2(v.z, v.w);
            }
            *(uint4*)&Bs[row][seg * 8] = make_uint4(h[0], h[1], h[2], h[3]);
            *(uint4*)&Bs[row][seg * 8 + 4] = make_uint4(h[4], h[5], h[6], h[7]);
        }
        __syncthreads();
#pragma unroll
        for (int kt = 0; kt < 2; kt++) {
            const int cb = kt * 8;
            uint32_t a[2][4];
#pragma unroll
            for (int mi = 0; mi < 2; mi++) {
                int r0 = wr + mi * 16 + gID;
                a[mi][0] = As[r0][cb + tg];
                a[mi][1] = As[r0 + 8][cb + tg];
                a[mi][2] = As[r0][cb + 4 + tg];
                a[mi][3] = As[r0 + 8][cb + 4 + tg];
            }
#pragma unroll
            for (int nj = 0; nj < 8; nj++) {
                int nb_ = wc + nj * 8 + gID;
                uint32_t b0 = Bs[nb_][cb + tg];
                uint32_t b1 = Bs[nb_][cb + 4 + tg];
                mma_f16(acc[0][nj], a[0], b0, b1);
                mma_f16(acc[1][nj], a[1], b0, b1);
            }
        }
        __syncthreads();
    }

#pragma unroll
    for (int mi = 0; mi < 2; mi++) {
        const int r_lo = bm + wr + mi * 16 + gID;
        const int r_hi = r_lo + 8;
        __half* clo = p.C + (size_t)r_lo * 256 + noff;
        __half* chi = p.C + (size_t)r_hi * 256 + noff;
#pragma unroll
        for (int nj = 0; nj < 8; nj++) {
            const int cl = wc + nj * 8 + tg * 2;
            const float b0 = __ldg(&bias[cl]);
            const float b1 = __ldg(&bias[cl + 1]);
            *(__half2*)(clo + cl) = __floats2half2_rn(acc[mi][nj][0] + b0, acc[mi][nj][1] + b1);
            *(__half2*)(chi + cl) = __floats2half2_rn(acc[mi][nj][2] + b0, acc[mi][nj][3] + b1);
        }
    }
}

// ===========================================================================
// Fused tail kernel: stage1 = [attn(fp16) || base-gather] @ Wcat^T (+f1b,+c0
// conditional, relu) -> h (fp16 fragments in smem); stage2 = h @ f2w^T + f2b
// -> C (fp32). CTA = 128 rows x 128 cols, 256 threads.
// ===========================================================================
struct FtParams {
    const float* Wcat;   // [128,384]
    const float* f1b;    // [128]
    const float* c0;     // [128]
    const float* f2w;    // [128,128]
    const float* f2b;    // [128]
    float* C;            // [M,128]
    const __half* Ah;    // attn [M,256] fp16
    const float *nf, *memv;
    const int* idx;
    const unsigned char* invalid;
};

#define FT_DSMEM (20480 + 32768 + 32768)

__device__ __forceinline__ void ft_stashA(uint32_t* As2, int m, int k, uint32_t h2) {
    int kt = k >> 4, mi8 = m >> 4;
    int r16 = m & 15, gid = r16 & 7, hi_r = r16 >> 3;
    int klo = k & 15, tg = (klo & 7) >> 1;
    int reg = hi_r + ((klo >> 3) << 1);
    As2[(((kt * 8 + mi8) * 32) + gid * 4 + tg) * 4 + reg] = h2;
}
__device__ __forceinline__ void ft_stashB(uint32_t* Bs2, int n, int k, uint32_t h2) {
    int kt = k >> 4, nt = n >> 3;
    int gid = n & 7;
    int klo = k & 15, tg = (klo & 7) >> 1, reg = klo >> 3;
    Bs2[(((nt * 8 + kt) * 32) + gid * 4 + tg) * 2 + reg] = h2;
}

__global__ void __launch_bounds__(256) fused_tail(FtParams p) {
    extern __shared__ char sm[];
    uint32_t (*As)[20] = (uint32_t(*)[20])sm;                 // 10240 B
    uint32_t (*Bs)[20] = (uint32_t(*)[20])(sm + 10240);       // 10240 B
    uint32_t* As2 = (uint32_t*)(sm + 20480);                  // 32768 B
    uint32_t* Bs2 = (uint32_t*)(sm + 53248);                  // 32768 B

    const int tid = threadIdx.x;
    const int lane = tid & 31;
    const int wid = tid >> 5;
    const int bm = blockIdx.x * 128;
    const int row = tid >> 1;
    const int seg = tid & 1;
    const int m = bm + row;
    const int wr = (wid >> 1) * 32;
    const int wc = (wid & 1) * 64;
    const int gID = lane >> 2;
    const int tg = lane & 3;

    // ---- stage f2w into Bs2 (fragment-permuted fp16) ----
    for (int i = tid; i < 8192; i += 256) {
        int n = i >> 6;
        int k = (i & 63) * 2;
        float v0 = __ldg(&p.f2w[n * 128 + k]);
        float v1 = __ldg(&p.f2w[n * 128 + k + 1]);
        ft_stashB(Bs2, n, k, f2h2(v0, v1));
    }

    // ---- stage 1 GEMM: [Ah || base] @ Wcat^T ----
    float acc[2][8][4];
#pragma unroll
    for (int mi = 0; mi < 2; mi++)
#pragma unroll
        for (int nj = 0; nj < 8; nj++)
#pragma unroll
            for (int q = 0; q < 4; q++) acc[mi][nj][q] = 0.f;

#pragma unroll 1
    for (int k0 = 0; k0 < 384; k0 += 32) {
        const int kb = k0 + seg * 16;
        if (kb < 256) {
            const __half* ah = p.Ah + (size_t)m * 256 + kb;
            *(uint4*)&As[row][seg * 8] = *(const uint4*)ah;
            *(uint4*)&As[row][seg * 8 + 4] = *(const uint4*)(ah + 8);
        } else {
            int nd = __ldg(&p.idx[m]);
            const float* s0 = p.nf + (size_t)nd * 128 + (kb - 256);
            const float* s1 = p.memv + (size_t)nd * 128 + (kb - 256);
            uint32_t h[8];
#pragma unroll
            for (int i = 0; i < 4; i++) {
                float4 v = *(const float4*)(s0 + i * 4);
                float4 w = *(const float4*)(s1 + i * 4);
                v.x += w.x; v.y += w.y; v.z += w.z; v.w += w.w;
                h[i * 2 + 0] = f2h2(v.x, v.y);
                h[i * 2 + 1] = f2h2(v.z, v.w);
            }
            *(uint4*)&As[row][seg * 8] = make_uint4(h[0], h[1], h[2], h[3]);
            *(uint4*)&As[row][seg * 8 + 4] = make_uint4(h[4], h[5], h[6], h[7]);
        }
        {
            const float* wsrc = p.Wcat + (size_t)row * 384 + kb;
            uint32_t h[8];
#pragma unroll
            for (int i = 0; i < 4; i++) {
                float4 v = *(const float4*)(wsrc + i * 4);
                h[i * 2 + 0] = f2h2(v.x, v.y);
                h[i * 2 + 1] = f2h2(v.z, v.w);
            }
            *(uint4*)&Bs[row][seg * 8] = make_uint4(h[0], h[1], h[2], h[3]);
            *(uint4*)&Bs[row][seg * 8 + 4] = make_uint4(h[4], h[5], h[6], h[7]);
        }
        __syncthreads();
#pragma unroll
        for (int kt = 0; kt < 2; kt++) {
            const int cb = kt * 8;
            uint32_t a[2][4];
#pragma unroll
            for (int mi = 0; mi < 2; mi++) {
                int r0 = wr + mi * 16 + gID;
                a[mi][0] = As[r0][cb + tg];
                a[mi][1] = As[r0 + 8][cb + tg];
                a[mi][2] = As[r0][cb + 4 + tg];
                a[mi][3] = As[r0 + 8][cb + 4 + tg];
            }
#pragma unroll
            for (int nj = 0; nj < 8; nj++) {
                int nb_ = wc + nj * 8 + gID;
                uint32_t b0 = Bs[nb_][cb + tg];
                uint32_t b1 = Bs[nb_][cb + 4 + tg];
                mma_f16(acc[0][nj], a[0], b0, b1);
                mma_f16(acc[1][nj], a[1], b0, b1);
            }
        }
        __syncthreads();
    }

    // ---- stage-1 epilogue: h = relu(acc + f1b + (valid ? c0 : 0)) -> As2 fp16 ----
#pragma unroll
    for (int mi = 0; mi < 2; mi++) {
        const int rl = wr + mi * 16 + gID;
        const int rh = rl + 8;
        const bool z_lo = p.invalid[bm + rl];
        const bool z_hi = p.invalid[bm + rh];
#pragma unroll
        for (int nj = 0; nj < 8; nj++) {
            const int cl = wc + nj * 8 + tg * 2;
            const float b0 = __ldg(&p.f1b[cl]);
            const float b1 = __ldg(&p.f1b[cl + 1]);
            const float cb0 = __ldg(&p.c0[cl]);
            const float cb1 = __ldg(&p.c0[cl + 1]);
            float v00 = fmaxf(acc[mi][nj][0] + b0 + (z_lo ? 0.f : cb0), 0.f);
            float v01 = fmaxf(acc[mi][nj][1] + b1 + (z_lo ? 0.f : cb1), 0.f);
            float v10 = fmaxf(acc[mi][nj][2] + b0 + (z_hi ? 0.f : cb0), 0.f);
            float v11 = fmaxf(acc[mi][nj][3] + b1 + (z_hi ? 0.f : cb1), 0.f);
            ft_stashA(As2, rl, cl, f2h2(v00, v01));
            ft_stashA(As2, rh, cl, f2h2(v10, v11));
        }
    }
    __syncthreads();

    // ---- stage 2: emb = h @ f2w^T + f2b ----
    float acc2[2][8][4];
#pragma unroll
    for (int mi = 0; mi < 2; mi++)
#pragma unroll
        for (int nj = 0; nj < 8; nj++)
#pragma unroll
            for (int q = 0; q < 4; q++) acc2[mi][nj][q] = 0.f;

    const uint4* As2_4 = (const uint4*)As2;
    const int mi8base = wr >> 4;
#pragma unroll
    for (int kt = 0; kt < 8; kt++) {
        uint4 a0v = As2_4[(kt * 8 + mi8base) * 32 + lane];
        uint4 a1v = As2_4[(kt * 8 + mi8base + 1) * 32 + lane];
        uint32_t a0[4] = {a0v.x, a0v.y, a0v.z, a0v.w};
        uint32_t a1[4] = {a1v.x, a1v.y, a1v.z, a1v.w};
#pragma unroll
        for (int nj = 0; nj < 8; nj++) {
            int nt = (wc >> 3) + nj;
            uint2 bb = *(const uint2*)&Bs2[(((nt * 8 + kt) * 32) + lane) * 2];
            mma_f16(acc2[0][nj], a0, bb.x, bb.y);
            mma_f16(acc2[1][nj], a1, bb.x, bb.y);
        }
    }

    // ---- stage-2 epilogue: + f2b, write fp32 ----
#pragma unroll
    for (int mi = 0; mi < 2; mi++) {
        const int r_lo = bm + wr + mi * 16 + gID;
        const int r_hi = r_lo + 8;
        float* clo = p.C + (size_t)r_lo * 128;
        float* chi = p.C + (size_t)r_hi * 128;
#pragma unroll
        for (int nj = 0; nj < 8; nj++) {
            const int cl = wc + nj * 8 + tg * 2;
            const float b0 = __ldg(&p.f2b[cl]);
            const float b1 = __ldg(&p.f2b[cl + 1]);
            *(float2*)(clo + cl) = make_float2(acc2[mi][nj][0] + b0, acc2[mi][nj][1] + b1);
            *(float2*)(chi + cl) = make_float2(acc2[mi][nj][2] + b0, acc2[mi][nj][3] + b1);
        }
    }
}

// ---------------------------------------------------------------------------
// Temporal attention (q fp16, kv fp16, out fp16); zeroes invalid rows.
// ---------------------------------------------------------------------------
__global__ void attn_kernel(const __half* __restrict__ q, const __half* __restrict__ kv,
                            const int* __restrict__ nbrs, __half* __restrict__ outp,
                            unsigned char* __restrict__ invalid) {
    const int r = blockIdx.x;
    const int tid = threadIdx.x;
    const int warp = tid >> 5;
    const int lane = tid & 31;
    __shared__ float sq[256];
    __shared__ float sc[2][KNB];
    __shared__ float swt[2][KNB];
    __shared__ int smask[KNB];
    __shared__ int sinv;

    if (tid < 256) sq[tid] = __half2float(q[(size_t)r * 256 + tid]);
    if (tid < KNB) smask[tid] = (nbrs[r * KNB + tid] != 0) ? 1 : 0;
    __syncthreads();
    if (tid == 0) {
        int any = 0;
#pragma unroll
        for (int k = 0; k < KNB; k++) any |= smask[k];
        if (!any) smask[KNB - 1] = 1;
        sinv = !any;
        invalid[r] = (unsigned char)(!any);
    }
    __syncthreads();

    if (warp < KNB) {
        const __half* kp = kv + ((size_t)r * KNB + warp) * 512;
        float s0 = 0.f, s1 = 0.f;
#pragma unroll
        for (int i = 0; i < 4; i++) {
            int d = lane + 32 * i;
            s0 = fmaf(sq[d], __half2float(__ldg(&kp[d])), s0);
            s1 = fmaf(sq[128 + d], __half2float(__ldg(&kp[128 + d])), s1);
        }
#pragma unroll
        for (int o = 16; o > 0; o >>= 1) {
            s0 += __shfl_down_sync(0xffffffffu, s0, o);
            s1 += __shfl_down_sync(0xffffffffu, s1, o);
        }
        if (lane == 0) {
            const float scale = 0.08838834764831845f;
            sc[0][warp] = smask[warp] ? s0 * scale : -1e9f;
            sc[1][warp] = smask[warp] ? s1 * scale : -1e9f;
        }
    }
    __syncthreads();

    if (tid < 2) {
        float mx = -3.0e38f;
#pragma unroll
        for (int k = 0; k < KNB; k++) mx = fmaxf(mx, sc[tid][k]);
        float sum = 0.f;
#pragma unroll
        for (int k = 0; k < KNB; k++) {
            float e = __expf(sc[tid][k] - mx);
            swt[tid][k] = e;
            sum += e;
        }
        float inv = 1.0f / sum;
#pragma unroll
        for (int k = 0; k < KNB; k++) swt[tid][k] *= inv;
    }
    __syncthreads();

    if (tid < 256) {
        int h = tid >> 7;
        float o = 0.f;
#pragma unroll
        for (int k = 0; k < KNB; k++)
            o = fmaf(swt[h][k], __half2float(__ldg(&kv[((size_t)r * KNB + k) * 512 + 256 + tid])), o);
        outp[(size_t)r * 256 + tid] = __float2half(sinv ? 0.f : o);
    }
}

// ---------------------------------------------------------------------------
// Host side
// ---------------------------------------------------------------------------
extern "C" void kernel_launch(void* const* d_in, const int* in_sizes, int n_in,
                              void* d_out, int out_size) {
    const float* nf   = (const float*)d_in[0];
    const float* mem  = (const float*)d_in[1];
    const float* ef   = (const float*)d_in[2];
    const float* tw   = (const float*)d_in[3];
    const float* tb   = (const float*)d_in[4];
    const float* Wq   = (const float*)d_in[5];
    const float* bq   = (const float*)d_in[6];
    const float* Wk   = (const float*)d_in[7];
    const float* bk   = (const float*)d_in[8];
    const float* Wv   = (const float*)d_in[9];
    const float* bv   = (const float*)d_in[10];
    const float* Wo   = (const float*)d_in[11];
    const float* bo   = (const float*)d_in[12];
    const float* f1w  = (const float*)d_in[13];
    const float* f1b  = (const float*)d_in[14];
    const float* f2w  = (const float*)d_in[15];
    const float* f2b  = (const float*)d_in[16];
    const int*   src  = (const int*)d_in[17];
    const float* ts   = (const float*)d_in[18];
    const int*   nb2  = (const int*)d_in[19];
    const int*   ei2  = (const int*)d_in[20];
    const float* tm2  = (const float*)d_in[21];
    const int*   nb1  = (const int*)d_in[22];
    const int*   ei1  = (const int*)d_in[23];
    const float* tm1  = (const float*)d_in[24];
    float* out = (float*)d_out;

    float *pemb1, *pwcat, *pc0, *pbq2;
    __half *pkv1, *pkv2, *pbph, *pq1, *pq2, *pattn1, *pattn2;
    unsigned char *pinv1, *pinv2;
    cudaGetSymbolAddress((void**)&pkv1, g_kv1);
    cudaGetSymbolAddress((void**)&pq1, g_q1);
    cudaGetSymbolAddress((void**)&pattn1, g_attn1);
    cudaGetSymbolAddress((void**)&pemb1, g_emb1);
    cudaGetSymbolAddress((void**)&pinv1, g_inv1);
    cudaGetSymbolAddress((void**)&pkv2, g_kv2);
    cudaGetSymbolAddress((void**)&pq2, g_q2);
    cudaGetSymbolAddress((void**)&pattn2, g_attn2);
    cudaGetSymbolAddress((void**)&pinv2, g_inv2);
    cudaGetSymbolAddress((void**)&pbph, g_bph);
    cudaGetSymbolAddress((void**)&pwcat, g_wcat);
    cudaGetSymbolAddress((void**)&pc0, g_c0);
    cudaGetSymbolAddress((void**)&pbq2, g_bq2);

    static cudaStream_t s_side = nullptr;
    static cudaEvent_t ev_fork = nullptr, ev_join = nullptr;
    if (s_side == nullptr) {
        cudaStreamCreateWithFlags(&s_side, cudaStreamNonBlocking);
        cudaEventCreateWithFlags(&ev_fork, cudaEventDisableTiming);
        cudaEventCreateWithFlags(&ev_join, cudaEventDisableTiming);
        cudaFuncSetAttribute(kv_kernel<0>, cudaFuncAttributeMaxDynamicSharedMemorySize, KV_DSMEM);
        cudaFuncSetAttribute(kv_kernel<1>, cudaFuncAttributeMaxDynamicSharedMemorySize, KV_DSMEM);
        cudaFuncSetAttribute(fused_tail, cudaFuncAttributeMaxDynamicSharedMemorySize, FT_DSMEM);
    }

    const cudaStream_t s0 = 0;

    const float* bk1 = bk + 256;
    const float* bv1 = bv + 256;
    const float* f2w1 = f2w + 128 * 128; const float* f2b1 = f2b + 128;

    // ---- fork immediately: side stream does preps + Q1 + Q2 + layer-1 B prep ----
    cudaEventRecord(ev_fork, s0);
    cudaStreamWaitEvent(s_side, ev_fork, 0);

    prep_b_kernel<<<(512 * 384 + 255) / 256, 256, 0, s_side>>>(Wk, Wv, pbph, 1);
    prep_bq_kernel<<<2, 256, 0, s_side>>>(Wq, bq, tb, pbq2);
    prep_wc_kernel<<<256, 384, 0, s_side>>>(Wo, bo, f1w, pwcat, pc0);
    {   // Q1 (fp16 out, K=128): [20480,256], 2 col chunks
        TcParams p{};
        p.W = Wq; p.bias = pbq2; p.C = pq1;
        p.nf = nf; p.memv = mem; p.idx = nb2;
        q_gemm<<<dim3(N1 / 128, 2), 256, 0, s_side>>>(p);
    }
    {   // Q2 (fp16 out, K=128)
        TcParams p{};
        p.W = Wq + 256 * 256; p.bias = pbq2 + 256; p.C = pq2;
        p.nf = nf; p.memv = mem; p.idx = src;
        q_gemm<<<dim3(BB / 128, 2), 256, 0, s_side>>>(p);
    }
    cudaEventRecord(ev_join, s_side);

    // ---- main stream: layer-0 B prep then KV1 (persistent, 136 SMs) ----
    prep_b_kernel<<<(512 * 384 + 255) / 256, 256, 0, s0>>>(Wk, Wv, pbph, 0);
    {
        KvParams p{};
        p.Bp = pbph; p.bk = bk; p.bv = bv; p.C = pkv1;
        p.DIV = 100; p.nblk = NP1 / 64;
        p.ts = ts; p.etm = tm1; p.tw = tw; p.tb = tb;
        p.nf = nf; p.memv = mem; p.ef = ef; p.idx = nb1; p.eidx = ei1;
        kv_kernel<0><<<136, 512, KV_DSMEM, s0>>>(p);
    }
    cudaStreamWaitEvent(s0, ev_join, 0);

    attn_kernel<<<N1, 320, 0, s0>>>(pq1, pkv1, nb1, pattn1, pinv1);
    {   // fused O1+fc1+fc2 (L0) -> emb1
        FtParams p{};
        p.Wcat = pwcat; p.f1b = f1b; p.c0 = pc0;
        p.f2w = f2w; p.f2b = f2b; p.C = pemb1;
        p.Ah = pattn1; p.nf = nf; p.memv = mem; p.idx = nb2; p.invalid = pinv1;
        fused_tail<<<N1 / 128, 256, FT_DSMEM, s0>>>(p);
    }
    {   // KV2 (fp16, dense, persistent)
        KvParams p{};
        p.Bp = pbph + 512 * 384; p.bk = bk1; p.bv = bv1; p.C = pkv2;
        p.DIV = 10; p.nblk = NP2 / 64;
        p.ts = ts; p.etm = tm2; p.tw = tw; p.tb = tb;
        p.Adense = pemb1; p.ef = ef; p.eidx = ei2;
        kv_kernel<1><<<148, 512, KV_DSMEM, s0>>>(p);
    }
    attn_kernel<<<BB, 320, 0, s0>>>(pq2, pkv2, nb2, pattn2, pinv2);
    {   // fused O2+fc1+fc2 (L1) -> out
        FtParams p{};
        p.Wcat = pwcat + 128 * 384; p.f1b = f1b + 128; p.c0 = pc0 + 128;
        p.f2w = f2w1; p.f2b = f2b1; p.C = out;
        p.Ah = pattn2; p.nf = nf; p.memv = mem; p.idx = src; p.invalid = pinv2;
        fused_tail<<<BB / 128, 256, FT_DSMEM, s0>>>(p);
    }
}

// round 15
// speedup vs baseline: 1.3045x; 1.1261x over previous
#include <cuda_runtime.h>
#include <cuda_fp16.h>
#include <cstdint>

// ---------------------------------------------------------------------------
// Problem constants
// ---------------------------------------------------------------------------
#define KNB 10
#define BB  2048
#define N1  20480
#define NP1 204800
#define NP2 20480
// D = T = 128, QD = 256, KD = 384, H = 2, hd = 128

// ---------------------------------------------------------------------------
// Scratch
// ---------------------------------------------------------------------------
__device__ __half g_q1 [(size_t)N1  * 256];
__device__ __half g_attn1[(size_t)N1 * 256];
__device__ float g_emb1[(size_t)N1 * 128];
__device__ unsigned char g_inv1[N1];
__device__ __half g_q2 [(size_t)BB  * 256];
__device__ __half g_attn2[(size_t)BB * 256];
__device__ unsigned char g_inv2[BB];
// pre-permuted fragment-ordered fp16 weights for KV (2 layers x 512 n x 384 k)
__device__ __half g_bph[2 * 512 * 384];
// folded tail weights: Wcat = [f1w_left@Wo || f1w_right]  (2 layers x 128 x 384)
__device__ float g_wcat[2 * 128 * 384];
__device__ float g_c0[2 * 128];
__device__ float g_bq2[2 * 256];

// ---------------------------------------------------------------------------
// fp16 mma helper + fast cosine
// ---------------------------------------------------------------------------
__device__ __forceinline__ void mma_f16(float* c, const uint32_t* a, uint32_t b0, uint32_t b1) {
    asm volatile(
        "mma.sync.aligned.m16n8k16.row.col.f32.f16.f16.f32 "
        "{%0,%1,%2,%3}, {%4,%5,%6,%7}, {%8,%9}, {%0,%1,%2,%3};"
        : "+f"(c[0]), "+f"(c[1]), "+f"(c[2]), "+f"(c[3])
        : "r"(a[0]), "r"(a[1]), "r"(a[2]), "r"(a[3]), "r"(b0), "r"(b1));
}
__device__ __forceinline__ uint32_t f2h2(float a, float b) {
    __half2 h = __floats2half2_rn(a, b);
    return *(uint32_t*)&h;
}
__device__ __forceinline__ float fast_cos(float t) {
    float qf = rintf(t * 0.6366197723675814f);
    int q = (int)qf;
    float r = fmaf(qf, -1.5707962513f, t);
    r = fmaf(qf, -7.54978942e-8f, r);
    float z = r * r;
    float cp = fmaf(z, fmaf(z, fmaf(z, -1.3888397e-3f, 4.16666418e-2f), -0.5f), 1.0f);
    float sp = r * fmaf(z, fmaf(z, 8.3321608e-3f, -1.66666547e-1f), 1.0f);
    float v = (q & 1) ? sp : cp;
    uint32_t sgn = (uint32_t)((q + 1) & 2) << 30;
    return __uint_as_float(__float_as_uint(v) ^ sgn);
}

// ===========================================================================
// B pre-permutation (one layer per launch)
// ===========================================================================
__global__ void prep_b_kernel(const float* __restrict__ Wk, const float* __restrict__ Wv,
                              __half* __restrict__ dst, int layer) {
    int idx = blockIdx.x * blockDim.x + threadIdx.x;
    if (idx >= 512 * 384) return;
    int n = idx / 384;
    int k = idx - n * 384;
    const float* W = (n < 256) ? (Wk + (size_t)layer * 256 * 384 + (size_t)n * 384)
                               : (Wv + (size_t)layer * 256 * 384 + (size_t)(n - 256) * 384);
    float v = W[k];
    int nt = n >> 3, gid = n & 7;
    int ktp = k >> 5, k32 = k & 31;
    int kt_in = k32 >> 4, klo = k32 & 15;
    int tg = (klo & 7) >> 1, reg = klo >> 3, par = k & 1;
    int lane = gid * 4 + tg;
    size_t off = ((((size_t)layer * 64 + nt) * 12 + ktp) * 32 + lane) * 8 + (kt_in * 2 + reg) * 2 + par;
    dst[off] = __float2half_rn(v);
}

// ===========================================================================
// Tail fold: Wcat / c0
// ===========================================================================
__global__ void prep_wc_kernel(const float* __restrict__ Wo, const float* __restrict__ bo,
                               const float* __restrict__ f1w,
                               float* __restrict__ wcat, float* __restrict__ c0) {
    int l = blockIdx.x >> 7;
    int i = blockIdx.x & 127;
    int k = threadIdx.x;
    const float* f1 = f1w + ((size_t)l * 128 + i) * 384;
    float v;
    if (k < 256) {
        const float* wo = Wo + (size_t)l * 256 * 256;
        float s = 0.f;
#pragma unroll 4
        for (int j = 0; j < 256; j++) s = fmaf(f1[j], wo[j * 256 + k], s);
        v = s;
    } else {
        v = f1[k];
    }
    wcat[((size_t)l * 128 + i) * 384 + k] = v;
    if (k == 0) {
        const float* bol = bo + l * 256;
        float s = 0.f;
#pragma unroll 4
        for (int j = 0; j < 256; j++) s = fmaf(f1[j], bol[j], s);
        c0[l * 128 + i] = s;
    }
}

// ===========================================================================
// Q-bias fold
// ===========================================================================
__global__ void prep_bq_kernel(const float* __restrict__ Wq, const float* __restrict__ bq,
                               const float* __restrict__ tb, float* __restrict__ bq2) {
    int l = blockIdx.x;
    int n = threadIdx.x;
    __shared__ float st[128];
    if (n < 128) st[n] = __cosf(tb[n]);
    __syncthreads();
    const float* w = Wq + (((size_t)l * 256 + n) * 256) + 128;
    float s = bq[l * 256 + n];
#pragma unroll 4
    for (int j = 0; j < 128; j++) s = fmaf(st[j], w[j], s);
    bq2[l * 256 + n] = s;
}

// ===========================================================================
// FUSED KV + attention kernel.
// Persistent CTAs; block = 80 rows = 8 queries (query r <-> rows 10r..10r+9).
// Per block: convert A (80x384 fp16, fragment-permuted smem) -> MMA 80x512
// (fp16 m16n8k16, acc[5][4][4], 16 warps x 32 cols, B from pre-permuted gmem)
// -> kv tile into smem (80x520 padded fp16) -> in-block attention (scores,
// softmax, weighted V) -> write attn[8x256] fp16 + invalid flags.
// ===========================================================================
struct KvParams {
    const __half* Bp;
    const float *bk, *bv;
    const __half* q;              // [nq, 256] fp16
    __half* attn_out;             // [nq, 256] fp16
    unsigned char* invalid;       // [nq]
    const int* mask_idx;          // neighbor ids for mask, [nblk*80]
    int DIV, nblk;
    const float *ts, *etm, *tw, *tb;
    const float *Adense, *nf, *memv, *ef;
    const int *idx, *eidx;
};

#define KV_OFF_PERM  0
#define KV_OFF_KVS   61440                       // 80*384*2
#define KV_OFF_QS    (61440 + 83200)             // kvs = 80*520*2
#define KV_OFF_SC    (KV_OFF_QS + 4096)
#define KV_OFF_WT    (KV_OFF_SC + 640)
#define KV_OFF_MASK  (KV_OFF_WT + 640)
#define KV_OFF_SINV  (KV_OFF_MASK + 320)
#define KV_DSMEM     (KV_OFF_SINV + 32)
#define KVS_LD 520

__device__ __forceinline__ void kv_stash_h2(uint32_t* As, int m, int k, uint32_t h2) {
    int kt = k >> 4, mi = m >> 4;
    int r16 = m & 15, gid = r16 & 7, hi_r = r16 >> 3;
    int klo = k & 15, tg = (klo & 7) >> 1;
    int reg = hi_r + ((klo >> 3) << 1);
    As[(((kt * 5 + mi) * 32) + gid * 4 + tg) * 4 + reg] = h2;
}

template <int DENSE>
__device__ __forceinline__ void kv_convert_row(uint32_t* As, int bm, int grow, int gseg,
                                               const KvParams& p) {
    const int m = bm + grow;
    if (DENSE) {
        const float4* s = (const float4*)(p.Adense + (size_t)m * 128);
#pragma unroll
        for (int i = 0; i < 4; i++) {
            int cf = gseg + 8 * i;
            float4 v = s[cf];
            int k = cf * 4;
            kv_stash_h2(As, grow, k, f2h2(v.x, v.y));
            kv_stash_h2(As, grow, k + 2, f2h2(v.z, v.w));
        }
    } else {
        int nd = __ldg(&p.idx[m]);
        const float4* s0 = (const float4*)(p.nf + (size_t)nd * 128);
        const float4* s1 = (const float4*)(p.memv + (size_t)nd * 128);
#pragma unroll
        for (int i = 0; i < 4; i++) {
            int cf = gseg + 8 * i;
            float4 x = s0[cf], y = s1[cf];
            int k = cf * 4;
            kv_stash_h2(As, grow, k, f2h2(x.x + y.x, x.y + y.y));
            kv_stash_h2(As, grow, k + 2, f2h2(x.z + y.z, x.w + y.w));
        }
    }
    {
        int e = __ldg(&p.eidx[m]);
        const float4* s = (const float4*)(p.ef + (size_t)e * 128);
#pragma unroll
        for (int i = 0; i < 4; i++) {
            int cf = gseg + 8 * i;
            float4 v = s[cf];
            int k = cf * 4;
            kv_stash_h2(As, grow, 128 + k, f2h2(v.x, v.y));
            kv_stash_h2(As, grow, 128 + k + 2, f2h2(v.z, v.w));
        }
    }
    float dt = __ldg(&p.ts[m / p.DIV]) - __ldg(&p.etm[m]);
#pragma unroll
    for (int i = 0; i < 4; i++) {
        int j0 = (gseg + 8 * i) * 4;
        float c0 = fast_cos(fmaf(dt, __ldg(&p.tw[j0 + 0]), __ldg(&p.tb[j0 + 0])));
        float c1 = fast_cos(fmaf(dt, __ldg(&p.tw[j0 + 1]), __ldg(&p.tb[j0 + 1])));
        float c2 = fast_cos(fmaf(dt, __ldg(&p.tw[j0 + 2]), __ldg(&p.tb[j0 + 2])));
        float c3 = fast_cos(fmaf(dt, __ldg(&p.tw[j0 + 3]), __ldg(&p.tb[j0 + 3])));
        kv_stash_h2(As, grow, 256 + j0, f2h2(c0, c1));
        kv_stash_h2(As, grow, 256 + j0 + 2, f2h2(c2, c3));
    }
}

template <int DENSE>
__global__ void __launch_bounds__(512, 1) kv_kernel(KvParams p) {
    extern __shared__ char smem[];
    uint32_t* perm = (uint32_t*)(smem + KV_OFF_PERM);
    __half* kvs = (__half*)(smem + KV_OFF_KVS);
    __half* qs = (__half*)(smem + KV_OFF_QS);
    float* scf = (float*)(smem + KV_OFF_SC);
    float* wtf = (float*)(smem + KV_OFF_WT);
    int* smask = (int*)(smem + KV_OFF_MASK);
    int* sinv = (int*)(smem + KV_OFF_SINV);

    const int tid = threadIdx.x;
    const int lane = tid & 31;
    const int wid = tid >> 5;
    const int gID = lane >> 2;
    const int tg = lane & 3;
    const char* bpw = (const char*)p.Bp + (size_t)(wid * 4) * 6144;

#pragma unroll 1
    for (int blk = blockIdx.x; blk < p.nblk; blk += gridDim.x) {
        const int bm = blk * 80;
        const int gq0 = blk * 8;

        // ---- convert A (80 rows) + load q + masks ----
        kv_convert_row<DENSE>(perm, bm, tid >> 3, tid & 7, p);
        if (tid < 128) kv_convert_row<DENSE>(perm, bm, 64 + (tid >> 3), tid & 7, p);
        if (tid < 256) ((uint4*)qs)[tid] = ((const uint4*)(p.q + (size_t)gq0 * 256))[tid];
        if (tid < 80) smask[tid] = (__ldg(&p.mask_idx[bm + tid]) != 0) ? 1 : 0;
        __syncthreads();
        if (tid < 8) {
            int any = 0;
#pragma unroll
            for (int k = 0; k < KNB; k++) any |= smask[tid * KNB + k];
            if (!any) smask[tid * KNB + KNB - 1] = 1;
            sinv[tid] = !any;
            p.invalid[gq0 + tid] = (unsigned char)(!any);
        }

        // ---- MMA: 80 rows x 512 cols ----
        float acc[5][4][4];
#pragma unroll
        for (int mi = 0; mi < 5; mi++)
#pragma unroll
            for (int nj = 0; nj < 4; nj++)
#pragma unroll
                for (int q8 = 0; q8 < 4; q8++) acc[mi][nj][q8] = 0.f;

        const uint4* As4 = (const uint4*)perm;
        uint4 bA[4];
#pragma unroll 1
        for (int ktp = 0; ktp < 12; ktp++) {
#pragma unroll
            for (int nj = 0; nj < 4; nj++)
                bA[nj] = *(const uint4*)(bpw + (size_t)nj * 6144 + ktp * 512 + lane * 16);
#pragma unroll
            for (int kt_in = 0; kt_in < 2; kt_in++) {
                const int kt = ktp * 2 + kt_in;
#pragma unroll
                for (int mi = 0; mi < 5; mi++) {
                    uint4 av = As4[(kt * 5 + mi) * 32 + lane];
                    uint32_t aa[4] = {av.x, av.y, av.z, av.w};
#pragma unroll
                    for (int nj = 0; nj < 4; nj++) {
                        uint32_t b0 = kt_in ? bA[nj].z : bA[nj].x;
                        uint32_t b1 = kt_in ? bA[nj].w : bA[nj].y;
                        mma_f16(acc[mi][nj], aa, b0, b1);
                    }
                }
            }
        }

        // ---- epilogue: kv tile -> smem (with bias) ----
#pragma unroll
        for (int mi = 0; mi < 5; mi++) {
            const int r_lo = mi * 16 + gID;
            __half* clo = kvs + (size_t)r_lo * KVS_LD;
            __half* chi = clo + (size_t)8 * KVS_LD;
#pragma unroll
            for (int nj = 0; nj < 4; nj++) {
                const int col = wid * 32 + nj * 8 + tg * 2;
                const float b0 = (col < 256) ? __ldg(&p.bk[col]) : __ldg(&p.bv[col - 256]);
                const float b1 = (col + 1 < 256) ? __ldg(&p.bk[col + 1]) : __ldg(&p.bv[col + 1 - 256]);
                *(__half2*)(clo + col) = __floats2half2_rn(acc[mi][nj][0] + b0, acc[mi][nj][1] + b1);
                *(__half2*)(chi + col) = __floats2half2_rn(acc[mi][nj][2] + b0, acc[mi][nj][3] + b1);
            }
        }
        __syncthreads();

        // ---- attention: scores (160 threads: q x h x k) ----
        if (tid < 160) {
            const int q8 = tid / 20;
            const int rem = tid - q8 * 20;
            const int h = rem / KNB;
            const int k = rem - h * KNB;
            const __half2* qp = (const __half2*)(qs + q8 * 256 + h * 128);
            const __half2* kp = (const __half2*)(kvs + (size_t)(q8 * KNB + k) * KVS_LD + h * 128);
            float s = 0.f;
#pragma unroll 8
            for (int d = 0; d < 64; d++) {
                float2 a = __half22float2(qp[d]);
                float2 b = __half22float2(kp[d]);
                s = fmaf(a.x, b.x, s);
                s = fmaf(a.y, b.y, s);
            }
            const float scale = 0.08838834764831845f;
            scf[(q8 * 2 + h) * KNB + k] = smask[q8 * KNB + k] ? s * scale : -1e9f;
        }
        __syncthreads();

        // ---- softmax (16 threads: q x h) ----
        if (tid < 16) {
            const int base = tid * KNB;
            float mx = -3.0e38f;
#pragma unroll
            for (int k = 0; k < KNB; k++) mx = fmaxf(mx, scf[base + k]);
            float sum = 0.f;
            float e[KNB];
#pragma unroll
            for (int k = 0; k < KNB; k++) {
                e[k] = __expf(scf[base + k] - mx);
                sum += e[k];
            }
            float inv = 1.0f / sum;
#pragma unroll
            for (int k = 0; k < KNB; k++) wtf[base + k] = e[k] * inv;
        }
        __syncthreads();

        // ---- weighted V -> attn_out (512 threads: q x 64 x 4dims) ----
        {
            const int q8 = tid >> 6;
            const int d0 = (tid & 63) * 4;
            const int h = d0 >> 7;
            float o0 = 0.f, o1 = 0.f, o2 = 0.f, o3 = 0.f;
            const float* w = wtf + (q8 * 2 + h) * KNB;
#pragma unroll
            for (int k = 0; k < KNB; k++) {
                const __half2* vp = (const __half2*)(kvs + (size_t)(q8 * KNB + k) * KVS_LD + 256 + d0);
                float2 v01 = __half22float2(vp[0]);
                float2 v23 = __half22float2(vp[1]);
                float wk = w[k];
                o0 = fmaf(wk, v01.x, o0);
                o1 = fmaf(wk, v01.y, o1);
                o2 = fmaf(wk, v23.x, o2);
                o3 = fmaf(wk, v23.y, o3);
            }
            if (sinv[q8]) { o0 = 0.f; o1 = 0.f; o2 = 0.f; o3 = 0.f; }
            __half* op = p.attn_out + (size_t)(gq0 + q8) * 256 + d0;
            *(__half2*)op = __floats2half2_rn(o0, o1);
            *(__half2*)(op + 2) = __floats2half2_rn(o2, o3);
        }
        __syncthreads();   // kvs/perm reuse next iteration
    }
}

// ===========================================================================
// Q GEMM (fp16 m16n8k16): CTA = 128(m) x 128(n), K=128, gather A, fp16 out.
// ===========================================================================
struct TcParams {
    const float* W;      // ldW = 256
    const float* bias;
    __half* C;           // ldC = 256
    const float *nf, *memv;
    const int *idx;
};

__global__ void __launch_bounds__(256) q_gemm(TcParams p) {
    __shared__ uint32_t As[128][20];
    __shared__ uint32_t Bs[128][20];
    const int tid = threadIdx.x;
    const int lane = tid & 31;
    const int wid = tid >> 5;
    const int bm = blockIdx.x * 128;
    const int noff = blockIdx.y * 128;
    const float* W = p.W + (size_t)noff * 256;
    const float* bias = p.bias + noff;
    const int row = tid >> 1;
    const int seg = tid & 1;
    const int m = bm + row;
    const int wr = (wid >> 1) * 32;
    const int wc = (wid & 1) * 64;
    const int gID = lane >> 2;
    const int tg = lane & 3;

    float acc[2][8][4];
#pragma unroll
    for (int mi = 0; mi < 2; mi++)
#pragma unroll
        for (int nj = 0; nj < 8; nj++)
#pragma unroll
            for (int q = 0; q < 4; q++) acc[mi][nj][q] = 0.f;

#pragma unroll 1
    for (int k0 = 0; k0 < 128; k0 += 32) {
        const int kb = k0 + seg * 16;
        {
            int nd = __ldg(&p.idx[m]);
            const float* s0 = p.nf + (size_t)nd * 128 + kb;
            const float* s1 = p.memv + (size_t)nd * 128 + kb;
            uint32_t h[8];
#pragma unroll
            for (int i = 0; i < 4; i++) {
                float4 v = *(const float4*)(s0 + i * 4);
                float4 w = *(const float4*)(s1 + i * 4);
                v.x += w.x; v.y += w.y; v.z += w.z; v.w += w.w;
                h[i * 2 + 0] = f2h2(v.x, v.y);
                h[i * 2 + 1] = f2h2(v.z, v.w);
            }
            *(uint4*)&As[row][seg * 8] = make_uint4(h[0], h[1], h[2], h[3]);
            *(uint4*)&As[row][seg * 8 + 4] = make_uint4(h[4], h[5], h[6], h[7]);
        }
        {
            const float* wsrc = W + (size_t)row * 256 + kb;
            uint32_t h[8];
#pragma unroll
            for (int i = 0; i < 4; i++) {
                float4 v = *(const float4*)(wsrc + i * 4);
                h[i * 2 + 0] = f2h2(v.x, v.y);
                h[i * 2 + 1] = f2h2(v.z, v.w);
            }
            *(uint4*)&Bs[row][seg * 8] = make_uint4(h[0], h[1], h[2], h[3]);
            *(uint4*)&Bs[row][seg * 8 + 4] = make_uint4(h[4], h[5], h[6], h[7]);
        }
        __syncthreads();
#pragma unroll
        for (int kt = 0; kt < 2; kt++) {
            const int cb = kt * 8;
            uint32_t a[2][4];
#pragma unroll
            for (int mi = 0; mi < 2; mi++) {
                int r0 = wr + mi * 16 + gID;
                a[mi][0] = As[r0][cb + tg];
                a[mi][1] = As[r0 + 8][cb + tg];
                a[mi][2] = As[r0][cb + 4 + tg];
                a[mi][3] = As[r0 + 8][cb + 4 + tg];
            }
#pragma unroll
            for (int nj = 0; nj < 8; nj++) {
                int nb_ = wc + nj * 8 + gID;
                uint32_t b0 = Bs[nb_][cb + tg];
                uint32_t b1 = Bs[nb_][cb + 4 + tg];
                mma_f16(acc[0][nj], a[0], b0, b1);
                mma_f16(acc[1][nj], a[1], b0, b1);
            }
        }
        __syncthreads();
    }

#pragma unroll
    for (int mi = 0; mi < 2; mi++) {
        const int r_lo = bm + wr + mi * 16 + gID;
        const int r_hi = r_lo + 8;
        __half* clo = p.C + (size_t)r_lo * 256 + noff;
        __half* chi = p.C + (size_t)r_hi * 256 + noff;
#pragma unroll
        for (int nj = 0; nj < 8; nj++) {
            const int cl = wc + nj * 8 + tg * 2;
            const float b0 = __ldg(&bias[cl]);
            const float b1 = __ldg(&bias[cl + 1]);
            *(__half2*)(clo + cl) = __floats2half2_rn(acc[mi][nj][0] + b0, acc[mi][nj][1] + b1);
            *(__half2*)(chi + cl) = __floats2half2_rn(acc[mi][nj][2] + b0, acc[mi][nj][3] + b1);
        }
    }
}

// ===========================================================================
// Fused tail kernel (O+fc1+fc2), unchanged from R14.
// ===========================================================================
struct FtParams {
    const float* Wcat;
    const float* f1b;
    const float* c0;
    const float* f2w;
    const float* f2b;
    float* C;
    const __half* Ah;
    const float *nf, *memv;
    const int* idx;
    const unsigned char* invalid;
};

#define FT_DSMEM (20480 + 32768 + 32768)

__device__ __forceinline__ void ft_stashA(uint32_t* As2, int m, int k, uint32_t h2) {
    int kt = k >> 4, mi8 = m >> 4;
    int r16 = m & 15, gid = r16 & 7, hi_r = r16 >> 3;
    int klo = k & 15, tg = (klo & 7) >> 1;
    int reg = hi_r + ((klo >> 3) << 1);
    As2[(((kt * 8 + mi8) * 32) + gid * 4 + tg) * 4 + reg] = h2;
}
__device__ __forceinline__ void ft_stashB(uint32_t* Bs2, int n, int k, uint32_t h2) {
    int kt = k >> 4, nt = n >> 3;
    int gid = n & 7;
    int klo = k & 15, tg = (klo & 7) >> 1, reg = klo >> 3;
    Bs2[(((nt * 8 + kt) * 32) + gid * 4 + tg) * 2 + reg] = h2;
}

__global__ void __launch_bounds__(256) fused_tail(FtParams p) {
    extern __shared__ char sm[];
    uint32_t (*As)[20] = (uint32_t(*)[20])sm;
    uint32_t (*Bs)[20] = (uint32_t(*)[20])(sm + 10240);
    uint32_t* As2 = (uint32_t*)(sm + 20480);
    uint32_t* Bs2 = (uint32_t*)(sm + 53248);

    const int tid = threadIdx.x;
    const int lane = tid & 31;
    const int wid = tid >> 5;
    const int bm = blockIdx.x * 128;
    const int row = tid >> 1;
    const int seg = tid & 1;
    const int m = bm + row;
    const int wr = (wid >> 1) * 32;
    const int wc = (wid & 1) * 64;
    const int gID = lane >> 2;
    const int tg = lane & 3;

    for (int i = tid; i < 8192; i += 256) {
        int n = i >> 6;
        int k = (i & 63) * 2;
        float v0 = __ldg(&p.f2w[n * 128 + k]);
        float v1 = __ldg(&p.f2w[n * 128 + k + 1]);
        ft_stashB(Bs2, n, k, f2h2(v0, v1));
    }

    float acc[2][8][4];
#pragma unroll
    for (int mi = 0; mi < 2; mi++)
#pragma unroll
        for (int nj = 0; nj < 8; nj++)
#pragma unroll
            for (int q = 0; q < 4; q++) acc[mi][nj][q] = 0.f;

#pragma unroll 1
    for (int k0 = 0; k0 < 384; k0 += 32) {
        const int kb = k0 + seg * 16;
        if (kb < 256) {
            const __half* ah = p.Ah + (size_t)m * 256 + kb;
            *(uint4*)&As[row][seg * 8] = *(const uint4*)ah;
            *(uint4*)&As[row][seg * 8 + 4] = *(const uint4*)(ah + 8);
        } else {
            int nd = __ldg(&p.idx[m]);
            const float* s0 = p.nf + (size_t)nd * 128 + (kb - 256);
            const float* s1 = p.memv + (size_t)nd * 128 + (kb - 256);
            uint32_t h[8];
#pragma unroll
            for (int i = 0; i < 4; i++) {
                float4 v = *(const float4*)(s0 + i * 4);
                float4 w = *(const float4*)(s1 + i * 4);
                v.x += w.x; v.y += w.y; v.z += w.z; v.w += w.w;
                h[i * 2 + 0] = f2h2(v.x, v.y);
                h[i * 2 + 1] = f2h2(v.z, v.w);
            }
            *(uint4*)&As[row][seg * 8] = make_uint4(h[0], h[1], h[2], h[3]);
            *(uint4*)&As[row][seg * 8 + 4] = make_uint4(h[4], h[5], h[6], h[7]);
        }
        {
            const float* wsrc = p.Wcat + (size_t)row * 384 + kb;
            uint32_t h[8];
#pragma unroll
            for (int i = 0; i < 4; i++) {
                float4 v = *(const float4*)(wsrc + i * 4);
                h[i * 2 + 0] = f2h2(v.x, v.y);
                h[i * 2 + 1] = f2h2(v.z, v.w);
            }
            *(uint4*)&Bs[row][seg * 8] = make_uint4(h[0], h[1], h[2], h[3]);
            *(uint4*)&Bs[row][seg * 8 + 4] = make_uint4(h[4], h[5], h[6], h[7]);
        }
        __syncthreads();
#pragma unroll
        for (int kt = 0; kt < 2; kt++) {
            const int cb = kt * 8;
            uint32_t a[2][4];
#pragma unroll
            for (int mi = 0; mi < 2; mi++) {
                int r0 = wr + mi * 16 + gID;
                a[mi][0] = As[r0][cb + tg];
                a[mi][1] = As[r0 + 8][cb + tg];
                a[mi][2] = As[r0][cb + 4 + tg];
                a[mi][3] = As[r0 + 8][cb + 4 + tg];
            }
#pragma unroll
            for (int nj = 0; nj < 8; nj++) {
                int nb_ = wc + nj * 8 + gID;
                uint32_t b0 = Bs[nb_][cb + tg];
                uint32_t b1 = Bs[nb_][cb + 4 + tg];
                mma_f16(acc[0][nj], a[0], b0, b1);
                mma_f16(acc[1][nj], a[1], b0, b1);
            }
        }
        __syncthreads();
    }

#pragma unroll
    for (int mi = 0; mi < 2; mi++) {
        const int rl = wr + mi * 16 + gID;
        const int rh = rl + 8;
        const bool z_lo = p.invalid[bm + rl];
        const bool z_hi = p.invalid[bm + rh];
#pragma unroll
        for (int nj = 0; nj < 8; nj++) {
            const int cl = wc + nj * 8 + tg * 2;
            const float b0 = __ldg(&p.f1b[cl]);
            const float b1 = __ldg(&p.f1b[cl + 1]);
            const float cb0 = __ldg(&p.c0[cl]);
            const float cb1 = __ldg(&p.c0[cl + 1]);
            float v00 = fmaxf(acc[mi][nj][0] + b0 + (z_lo ? 0.f : cb0), 0.f);
            float v01 = fmaxf(acc[mi][nj][1] + b1 + (z_lo ? 0.f : cb1), 0.f);
            float v10 = fmaxf(acc[mi][nj][2] + b0 + (z_hi ? 0.f : cb0), 0.f);
            float v11 = fmaxf(acc[mi][nj][3] + b1 + (z_hi ? 0.f : cb1), 0.f);
            ft_stashA(As2, rl, cl, f2h2(v00, v01));
            ft_stashA(As2, rh, cl, f2h2(v10, v11));
        }
    }
    __syncthreads();

    float acc2[2][8][4];
#pragma unroll
    for (int mi = 0; mi < 2; mi++)
#pragma unroll
        for (int nj = 0; nj < 8; nj++)
#pragma unroll
            for (int q = 0; q < 4; q++) acc2[mi][nj][q] = 0.f;

    const uint4* As2_4 = (const uint4*)As2;
    const int mi8base = wr >> 4;
#pragma unroll
    for (int kt = 0; kt < 8; kt++) {
        uint4 a0v = As2_4[(kt * 8 + mi8base) * 32 + lane];
        uint4 a1v = As2_4[(kt * 8 + mi8base + 1) * 32 + lane];
        uint32_t a0[4] = {a0v.x, a0v.y, a0v.z, a0v.w};
        uint32_t a1[4] = {a1v.x, a1v.y, a1v.z, a1v.w};
#pragma unroll
        for (int nj = 0; nj < 8; nj++) {
            int nt = (wc >> 3) + nj;
            uint2 bb = *(const uint2*)&Bs2[(((nt * 8 + kt) * 32) + lane) * 2];
            mma_f16(acc2[0][nj], a0, bb.x, bb.y);
            mma_f16(acc2[1][nj], a1, bb.x, bb.y);
        }
    }

#pragma unroll
    for (int mi = 0; mi < 2; mi++) {
        const int r_lo = bm + wr + mi * 16 + gID;
        const int r_hi = r_lo + 8;
        float* clo = p.C + (size_t)r_lo * 128;
        float* chi = p.C + (size_t)r_hi * 128;
#pragma unroll
        for (int nj = 0; nj < 8; nj++) {
            const int cl = wc + nj * 8 + tg * 2;
            const float b0 = __ldg(&p.f2b[cl]);
            const float b1 = __ldg(&p.f2b[cl + 1]);
            *(float2*)(clo + cl) = make_float2(acc2[mi][nj][0] + b0, acc2[mi][nj][1] + b1);
            *(float2*)(chi + cl) = make_float2(acc2[mi][nj][2] + b0, acc2[mi][nj][3] + b1);
        }
    }
}

// ---------------------------------------------------------------------------
// Host side
// ---------------------------------------------------------------------------
extern "C" void kernel_launch(void* const* d_in, const int* in_sizes, int n_in,
                              void* d_out, int out_size) {
    const float* nf   = (const float*)d_in[0];
    const float* mem  = (const float*)d_in[1];
    const float* ef   = (const float*)d_in[2];
    const float* tw   = (const float*)d_in[3];
    const float* tb   = (const float*)d_in[4];
    const float* Wq   = (const float*)d_in[5];
    const float* bq   = (const float*)d_in[6];
    const float* Wk   = (const float*)d_in[7];
    const float* bk   = (const float*)d_in[8];
    const float* Wv   = (const float*)d_in[9];
    const float* bv   = (const float*)d_in[10];
    const float* Wo   = (const float*)d_in[11];
    const float* bo   = (const float*)d_in[12];
    const float* f1w  = (const float*)d_in[13];
    const float* f1b  = (const float*)d_in[14];
    const float* f2w  = (const float*)d_in[15];
    const float* f2b  = (const float*)d_in[16];
    const int*   src  = (const int*)d_in[17];
    const float* ts   = (const float*)d_in[18];
    const int*   nb2  = (const int*)d_in[19];
    const int*   ei2  = (const int*)d_in[20];
    const float* tm2  = (const float*)d_in[21];
    const int*   nb1  = (const int*)d_in[22];
    const int*   ei1  = (const int*)d_in[23];
    const float* tm1  = (const float*)d_in[24];
    float* out = (float*)d_out;

    float *pemb1, *pwcat, *pc0, *pbq2;
    __half *pbph, *pq1, *pq2, *pattn1, *pattn2;
    unsigned char *pinv1, *pinv2;
    cudaGetSymbolAddress((void**)&pq1, g_q1);
    cudaGetSymbolAddress((void**)&pattn1, g_attn1);
    cudaGetSymbolAddress((void**)&pemb1, g_emb1);
    cudaGetSymbolAddress((void**)&pinv1, g_inv1);
    cudaGetSymbolAddress((void**)&pq2, g_q2);
    cudaGetSymbolAddress((void**)&pattn2, g_attn2);
    cudaGetSymbolAddress((void**)&pinv2, g_inv2);
    cudaGetSymbolAddress((void**)&pbph, g_bph);
    cudaGetSymbolAddress((void**)&pwcat, g_wcat);
    cudaGetSymbolAddress((void**)&pc0, g_c0);
    cudaGetSymbolAddress((void**)&pbq2, g_bq2);

    static cudaStream_t s_side = nullptr;
    static cudaEvent_t ev_fork = nullptr, ev_q1 = nullptr, ev_join = nullptr;
    if (s_side == nullptr) {
        cudaStreamCreateWithFlags(&s_side, cudaStreamNonBlocking);
        cudaEventCreateWithFlags(&ev_fork, cudaEventDisableTiming);
        cudaEventCreateWithFlags(&ev_q1, cudaEventDisableTiming);
        cudaEventCreateWithFlags(&ev_join, cudaEventDisableTiming);
        cudaFuncSetAttribute(kv_kernel<0>, cudaFuncAttributeMaxDynamicSharedMemorySize, KV_DSMEM);
        cudaFuncSetAttribute(kv_kernel<1>, cudaFuncAttributeMaxDynamicSharedMemorySize, KV_DSMEM);
        cudaFuncSetAttribute(fused_tail, cudaFuncAttributeMaxDynamicSharedMemorySize, FT_DSMEM);
    }

    const cudaStream_t s0 = 0;

    const float* bk1 = bk + 256;
    const float* bv1 = bv + 256;
    const float* f2w1 = f2w + 128 * 128; const float* f2b1 = f2b + 128;

    // ---- side stream: prep_bq -> Q1 (ev_q1) -> Q2, prep_wc, prep_b L1 ----
    cudaEventRecord(ev_fork, s0);
    cudaStreamWaitEvent(s_side, ev_fork, 0);

    prep_bq_kernel<<<2, 256, 0, s_side>>>(Wq, bq, tb, pbq2);
    {   // Q1 (fp16 out, K=128)
        TcParams p{};
        p.W = Wq; p.bias = pbq2; p.C = pq1;
        p.nf = nf; p.memv = mem; p.idx = nb2;
        q_gemm<<<dim3(N1 / 128, 2), 256, 0, s_side>>>(p);
    }
    cudaEventRecord(ev_q1, s_side);
    {   // Q2 (fp16 out, K=128)
        TcParams p{};
        p.W = Wq + 256 * 256; p.bias = pbq2 + 256; p.C = pq2;
        p.nf = nf; p.memv = mem; p.idx = src;
        q_gemm<<<dim3(BB / 128, 2), 256, 0, s_side>>>(p);
    }
    prep_wc_kernel<<<256, 384, 0, s_side>>>(Wo, bo, f1w, pwcat, pc0);
    prep_b_kernel<<<(512 * 384 + 255) / 256, 256, 0, s_side>>>(Wk, Wv, pbph, 1);
    cudaEventRecord(ev_join, s_side);

    // ---- main stream: prep_b L0, wait q1, fused KV1+attn1 ----
    prep_b_kernel<<<(512 * 384 + 255) / 256, 256, 0, s0>>>(Wk, Wv, pbph, 0);
    cudaStreamWaitEvent(s0, ev_q1, 0);
    {
        KvParams p{};
        p.Bp = pbph; p.bk = bk; p.bv = bv;
        p.q = pq1; p.attn_out = pattn1; p.invalid = pinv1; p.mask_idx = nb1;
        p.DIV = 100; p.nblk = NP1 / 80;
        p.ts = ts; p.etm = tm1; p.tw = tw; p.tb = tb;
        p.nf = nf; p.memv = mem; p.ef = ef; p.idx = nb1; p.eidx = ei1;
        kv_kernel<0><<<148, 512, KV_DSMEM, s0>>>(p);
    }
    cudaStreamWaitEvent(s0, ev_join, 0);   // wcat / q2 / bph L1 ready

    {   // fused O1+fc1+fc2 (L0) -> emb1
        FtParams p{};
        p.Wcat = pwcat; p.f1b = f1b; p.c0 = pc0;
        p.f2w = f2w; p.f2b = f2b; p.C = pemb1;
        p.Ah = pattn1; p.nf = nf; p.memv = mem; p.idx = nb2; p.invalid = pinv1;
        fused_tail<<<N1 / 128, 256, FT_DSMEM, s0>>>(p);
    }
    {   // fused KV2+attn2 (dense)
        KvParams p{};
        p.Bp = pbph + 512 * 384; p.bk = bk1; p.bv = bv1;
        p.q = pq2; p.attn_out = pattn2; p.invalid = pinv2; p.mask_idx = nb2;
        p.DIV = 10; p.nblk = NP2 / 80;
        p.ts = ts; p.etm = tm2; p.tw = tw; p.tb = tb;
        p.Adense = pemb1; p.ef = ef; p.eidx = ei2;
        kv_kernel<1><<<148, 512, KV_DSMEM, s0>>>(p);
    }
    {   // fused O2+fc1+fc2 (L1) -> out
        FtParams p{};
        p.Wcat = pwcat + 128 * 384; p.f1b = f1b + 128; p.c0 = pc0 + 128;
        p.f2w = f2w1; p.f2b = f2b1; p.C = out;
        p.Ah = pattn2; p.nf = nf; p.memv = mem; p.idx = src; p.invalid = pinv2;
        fused_tail<<<BB / 128, 256, FT_DSMEM, s0>>>(p);
    }
}

// round 16
// speedup vs baseline: 1.4149x; 1.0846x over previous
#include <cuda_runtime.h>
#include <cuda_fp16.h>
#include <cstdint>

// ---------------------------------------------------------------------------
// Problem constants
// ---------------------------------------------------------------------------
#define KNB 10
#define BB  2048
#define N1  20480
#define NP1 204800
#define NP2 20480
// D = T = 128, QD = 256, KD = 384, H = 2, hd = 128

// ---------------------------------------------------------------------------
// Scratch
// ---------------------------------------------------------------------------
__device__ __half g_q1 [(size_t)N1  * 256];
__device__ __half g_attn1[(size_t)N1 * 256];
__device__ __half g_emb1[(size_t)N1 * 128];
__device__ unsigned char g_inv1[N1];
__device__ __half g_q2 [(size_t)BB  * 256];
__device__ __half g_attn2[(size_t)BB * 256];
__device__ unsigned char g_inv2[BB];
__device__ __half g_bph[2 * 512 * 384];
__device__ float g_wcat[2 * 128 * 384];
__device__ float g_c0[2 * 128];
__device__ float g_bq2[2 * 256];

// ---------------------------------------------------------------------------
// fp16 mma helper + fast cosine
// ---------------------------------------------------------------------------
__device__ __forceinline__ void mma_f16(float* c, const uint32_t* a, uint32_t b0, uint32_t b1) {
    asm volatile(
        "mma.sync.aligned.m16n8k16.row.col.f32.f16.f16.f32 "
        "{%0,%1,%2,%3}, {%4,%5,%6,%7}, {%8,%9}, {%0,%1,%2,%3};"
        : "+f"(c[0]), "+f"(c[1]), "+f"(c[2]), "+f"(c[3])
        : "r"(a[0]), "r"(a[1]), "r"(a[2]), "r"(a[3]), "r"(b0), "r"(b1));
}
__device__ __forceinline__ uint32_t f2h2(float a, float b) {
    __half2 h = __floats2half2_rn(a, b);
    return *(uint32_t*)&h;
}
__device__ __forceinline__ float fast_cos(float t) {
    float qf = rintf(t * 0.6366197723675814f);
    int q = (int)qf;
    float r = fmaf(qf, -1.5707962513f, t);
    r = fmaf(qf, -7.54978942e-8f, r);
    float z = r * r;
    float cp = fmaf(z, fmaf(z, fmaf(z, -1.3888397e-3f, 4.16666418e-2f), -0.5f), 1.0f);
    float sp = r * fmaf(z, fmaf(z, 8.3321608e-3f, -1.66666547e-1f), 1.0f);
    float v = (q & 1) ? sp : cp;
    uint32_t sgn = (uint32_t)((q + 1) & 2) << 30;
    return __uint_as_float(__float_as_uint(v) ^ sgn);
}

// ===========================================================================
// B pre-permutation (one layer per launch)
// ===========================================================================
__global__ void prep_b_kernel(const float* __restrict__ Wk, const float* __restrict__ Wv,
                              __half* __restrict__ dst, int layer) {
    int idx = blockIdx.x * blockDim.x + threadIdx.x;
    if (idx >= 512 * 384) return;
    int n = idx / 384;
    int k = idx - n * 384;
    const float* W = (n < 256) ? (Wk + (size_t)layer * 256 * 384 + (size_t)n * 384)
                               : (Wv + (size_t)layer * 256 * 384 + (size_t)(n - 256) * 384);
    float v = W[k];
    int nt = n >> 3, gid = n & 7;
    int ktp = k >> 5, k32 = k & 31;
    int kt_in = k32 >> 4, klo = k32 & 15;
    int tg = (klo & 7) >> 1, reg = klo >> 3, par = k & 1;
    int lane = gid * 4 + tg;
    size_t off = ((((size_t)layer * 64 + nt) * 12 + ktp) * 32 + lane) * 8 + (kt_in * 2 + reg) * 2 + par;
    dst[off] = __float2half_rn(v);
}

// ===========================================================================
// Tail fold: Wcat / c0
// ===========================================================================
__global__ void prep_wc_kernel(const float* __restrict__ Wo, const float* __restrict__ bo,
                               const float* __restrict__ f1w,
                               float* __restrict__ wcat, float* __restrict__ c0) {
    int l = blockIdx.x >> 7;
    int i = blockIdx.x & 127;
    int k = threadIdx.x;
    const float* f1 = f1w + ((size_t)l * 128 + i) * 384;
    float v;
    if (k < 256) {
        const float* wo = Wo + (size_t)l * 256 * 256;
        float s = 0.f;
#pragma unroll 4
        for (int j = 0; j < 256; j++) s = fmaf(f1[j], wo[j * 256 + k], s);
        v = s;
    } else {
        v = f1[k];
    }
    wcat[((size_t)l * 128 + i) * 384 + k] = v;
    if (k == 0) {
        const float* bol = bo + l * 256;
        float s = 0.f;
#pragma unroll 4
        for (int j = 0; j < 256; j++) s = fmaf(f1[j], bol[j], s);
        c0[l * 128 + i] = s;
    }
}

// ===========================================================================
// Q-bias fold
// ===========================================================================
__global__ void prep_bq_kernel(const float* __restrict__ Wq, const float* __restrict__ bq,
                               const float* __restrict__ tb, float* __restrict__ bq2) {
    int l = blockIdx.x;
    int n = threadIdx.x;
    __shared__ float st[128];
    if (n < 128) st[n] = __cosf(tb[n]);
    __syncthreads();
    const float* w = Wq + (((size_t)l * 256 + n) * 256) + 128;
    float s = bq[l * 256 + n];
#pragma unroll 4
    for (int j = 0; j < 128; j++) s = fmaf(st[j], w[j], s);
    bq2[l * 256 + n] = s;
}

// ===========================================================================
// FUSED KV + attention kernel, pipelined convert.
// Block = 80 rows = 8 queries. During block i's attention phases, warps 5-15
// convert block i+1's A into perm (free after MMA(i)) and warps 0-4 prefetch
// q/masks for i+1 before computing scores(i). qs/smask/sinv double-buffered.
// ===========================================================================
struct KvParams {
    const __half* Bp;
    const float *bk, *bv;
    const __half* q;              // [nq, 256] fp16
    __half* attn_out;             // [nq, 256] fp16
    unsigned char* invalid;       // [nq]
    const int* mask_idx;          // [nblk*80]
    int DIV, nblk;
    const float *ts, *etm, *tw, *tb;
    const __half* Adense;         // fp16 (emb1) for DENSE
    const float *nf, *memv, *ef;
    const int *idx, *eidx;
};

#define KV_OFF_PERM  0
#define KV_OFF_KVS   61440                        // perm = 80*384*2
#define KV_OFF_QS    (61440 + 83200)              // kvs = 80*520*2
#define KV_OFF_SC    (KV_OFF_QS + 8192)           // qs double: 2*4096
#define KV_OFF_WT    (KV_OFF_SC + 640)
#define KV_OFF_MASK  (KV_OFF_WT + 640)
#define KV_OFF_SINV  (KV_OFF_MASK + 640)          // smask double: 2*320
#define KV_DSMEM     (KV_OFF_SINV + 64)           // sinv double: 2*32
#define KVS_LD 520

__device__ __forceinline__ void kv_stash_h2(uint32_t* As, int m, int k, uint32_t h2) {
    int kt = k >> 4, mi = m >> 4;
    int r16 = m & 15, gid = r16 & 7, hi_r = r16 >> 3;
    int klo = k & 15, tg = (klo & 7) >> 1;
    int reg = hi_r + ((klo >> 3) << 1);
    As[(((kt * 5 + mi) * 32) + gid * 4 + tg) * 4 + reg] = h2;
}

template <int DENSE>
__device__ __forceinline__ void kv_convert_row(uint32_t* As, int bm, int grow, int gseg,
                                               const KvParams& p) {
    const int m = bm + grow;
    if (DENSE) {
        const uint2* s = (const uint2*)(p.Adense + (size_t)m * 128);  // 4 halves per uint2
#pragma unroll
        for (int i = 0; i < 4; i++) {
            int cf = gseg + 8 * i;
            uint2 u = s[cf];
            int k = cf * 4;
            kv_stash_h2(As, grow, k, u.x);
            kv_stash_h2(As, grow, k + 2, u.y);
        }
    } else {
        int nd = __ldg(&p.idx[m]);
        const float4* s0 = (const float4*)(p.nf + (size_t)nd * 128);
        const float4* s1 = (const float4*)(p.memv + (size_t)nd * 128);
#pragma unroll
        for (int i = 0; i < 4; i++) {
            int cf = gseg + 8 * i;
            float4 x = s0[cf], y = s1[cf];
            int k = cf * 4;
            kv_stash_h2(As, grow, k, f2h2(x.x + y.x, x.y + y.y));
            kv_stash_h2(As, grow, k + 2, f2h2(x.z + y.z, x.w + y.w));
        }
    }
    {
        int e = __ldg(&p.eidx[m]);
        const float4* s = (const float4*)(p.ef + (size_t)e * 128);
#pragma unroll
        for (int i = 0; i < 4; i++) {
            int cf = gseg + 8 * i;
            float4 v = s[cf];
            int k = cf * 4;
            kv_stash_h2(As, grow, 128 + k, f2h2(v.x, v.y));
            kv_stash_h2(As, grow, 128 + k + 2, f2h2(v.z, v.w));
        }
    }
    float dt = __ldg(&p.ts[m / p.DIV]) - __ldg(&p.etm[m]);
#pragma unroll
    for (int i = 0; i < 4; i++) {
        int j0 = (gseg + 8 * i) * 4;
        float c0 = fast_cos(fmaf(dt, __ldg(&p.tw[j0 + 0]), __ldg(&p.tb[j0 + 0])));
        float c1 = fast_cos(fmaf(dt, __ldg(&p.tw[j0 + 1]), __ldg(&p.tb[j0 + 1])));
        float c2 = fast_cos(fmaf(dt, __ldg(&p.tw[j0 + 2]), __ldg(&p.tb[j0 + 2])));
        float c3 = fast_cos(fmaf(dt, __ldg(&p.tw[j0 + 3]), __ldg(&p.tb[j0 + 3])));
        kv_stash_h2(As, grow, 256 + j0, f2h2(c0, c1));
        kv_stash_h2(As, grow, 256 + j0 + 2, f2h2(c2, c3));
    }
}

template <int DENSE>
__global__ void __launch_bounds__(512, 1) kv_kernel(KvParams p) {
    extern __shared__ char smem[];
    uint32_t* perm = (uint32_t*)(smem + KV_OFF_PERM);
    __half* kvs = (__half*)(smem + KV_OFF_KVS);
    __half* qs = (__half*)(smem + KV_OFF_QS);     // 2 x 2048 halves
    float* scf = (float*)(smem + KV_OFF_SC);
    float* wtf = (float*)(smem + KV_OFF_WT);
    int* smask = (int*)(smem + KV_OFF_MASK);      // 2 x 80
    int* sinv = (int*)(smem + KV_OFF_SINV);       // 2 x 8

    const int tid = threadIdx.x;
    const int lane = tid & 31;
    const int wid = tid >> 5;
    const int gID = lane >> 2;
    const int tg = lane & 3;
    const char* bpw = (const char*)p.Bp + (size_t)(wid * 4) * 6144;

    // ---- prologue: block blockIdx.x into buffer 0 ----
    {
        const int bm = blockIdx.x * 80;
        const int gq0 = blockIdx.x * 8;
        kv_convert_row<DENSE>(perm, bm, tid >> 3, tid & 7, p);
        if (tid < 128) kv_convert_row<DENSE>(perm, bm, 64 + (tid >> 3), tid & 7, p);
        if (tid < 256) ((uint4*)qs)[tid] = ((const uint4*)(p.q + (size_t)gq0 * 256))[tid];
        if (tid < 80) smask[tid] = (__ldg(&p.mask_idx[bm + tid]) != 0) ? 1 : 0;
        __syncthreads();
        if (tid < 8) {
            int any = 0;
#pragma unroll
            for (int k = 0; k < KNB; k++) any |= smask[tid * KNB + k];
            if (!any) smask[tid * KNB + KNB - 1] = 1;
            sinv[tid] = !any;
            p.invalid[gq0 + tid] = (unsigned char)(!any);
        }
        __syncthreads();
    }

    int it = 0;
#pragma unroll 1
    for (int blk = blockIdx.x; blk < p.nblk; blk += gridDim.x) {
        const int gq0 = blk * 8;

        // ---- MMA: 80 rows x 512 cols ----
        float acc[5][4][4];
#pragma unroll
        for (int mi = 0; mi < 5; mi++)
#pragma unroll
            for (int nj = 0; nj < 4; nj++)
#pragma unroll
                for (int q8 = 0; q8 < 4; q8++) acc[mi][nj][q8] = 0.f;

        const uint4* As4 = (const uint4*)perm;
        uint4 bA[4];
#pragma unroll 1
        for (int ktp = 0; ktp < 12; ktp++) {
#pragma unroll
            for (int nj = 0; nj < 4; nj++)
                bA[nj] = *(const uint4*)(bpw + (size_t)nj * 6144 + ktp * 512 + lane * 16);
#pragma unroll
            for (int kt_in = 0; kt_in < 2; kt_in++) {
                const int kt = ktp * 2 + kt_in;
#pragma unroll
                for (int mi = 0; mi < 5; mi++) {
                    uint4 av = As4[(kt * 5 + mi) * 32 + lane];
                    uint32_t aa[4] = {av.x, av.y, av.z, av.w};
#pragma unroll
                    for (int nj = 0; nj < 4; nj++) {
                        uint32_t b0 = kt_in ? bA[nj].z : bA[nj].x;
                        uint32_t b1 = kt_in ? bA[nj].w : bA[nj].y;
                        mma_f16(acc[mi][nj], aa, b0, b1);
                    }
                }
            }
        }

        // ---- epilogue: kv tile -> smem (with bias) ----
#pragma unroll
        for (int mi = 0; mi < 5; mi++) {
            const int r_lo = mi * 16 + gID;
            __half* clo = kvs + (size_t)r_lo * KVS_LD;
            __half* chi = clo + (size_t)8 * KVS_LD;
#pragma unroll
            for (int nj = 0; nj < 4; nj++) {
                const int col = wid * 32 + nj * 8 + tg * 2;
                const float b0 = (col < 256) ? __ldg(&p.bk[col]) : __ldg(&p.bv[col - 256]);
                const float b1 = (col + 1 < 256) ? __ldg(&p.bk[col + 1]) : __ldg(&p.bv[col + 1 - 256]);
                *(__half2*)(clo + col) = __floats2half2_rn(acc[mi][nj][0] + b0, acc[mi][nj][1] + b1);
                *(__half2*)(chi + col) = __floats2half2_rn(acc[mi][nj][2] + b0, acc[mi][nj][3] + b1);
            }
        }
        __syncthreads();   // kvs ready; perm free

        const int nb_blk = blk + gridDim.x;
        const bool has_next = nb_blk < p.nblk;
        const int nbuf = it ^ 1;

        if (tid >= 160) {
            // ---- convert next block's A (overlaps scores) ----
            if (has_next) {
                const int bm_n = nb_blk * 80;
                int t0 = tid - 160;
                kv_convert_row<DENSE>(perm, bm_n, t0 >> 3, t0 & 7, p);
                int t1 = t0 + 352;
                if (t1 < 640) kv_convert_row<DENSE>(perm, bm_n, t1 >> 3, t1 & 7, p);
            }
        } else {
            // ---- prefetch next q/masks, then scores(cur) ----
            if (has_next) {
                const uint4* qsrc = (const uint4*)(p.q + (size_t)(nb_blk * 8) * 256);
                uint4* qdst = (uint4*)(qs + nbuf * 2048);
                qdst[tid] = qsrc[tid];
                if (tid + 160 < 256) qdst[tid + 160] = qsrc[tid + 160];
                if (tid < 80)
                    smask[nbuf * 80 + tid] = (__ldg(&p.mask_idx[nb_blk * 80 + tid]) != 0) ? 1 : 0;
            }
            const int q8 = tid / 20;
            const int rem = tid - q8 * 20;
            const int h = rem / KNB;
            const int k = rem - h * KNB;
            const __half2* qp = (const __half2*)(qs + it * 2048 + q8 * 256 + h * 128);
            const __half2* kp = (const __half2*)(kvs + (size_t)(q8 * KNB + k) * KVS_LD + h * 128);
            float s = 0.f;
#pragma unroll 8
            for (int d = 0; d < 64; d++) {
                float2 a = __half22float2(qp[d]);
                float2 b = __half22float2(kp[d]);
                s = fmaf(a.x, b.x, s);
                s = fmaf(a.y, b.y, s);
            }
            const float scale = 0.08838834764831845f;
            scf[(q8 * 2 + h) * KNB + k] = smask[it * 80 + q8 * KNB + k] ? s * scale : -1e9f;
        }
        __syncthreads();

        // ---- softmax (16 threads) + next-block invalid (threads 16-23) ----
        if (tid < 16) {
            const int base = tid * KNB;
            float mx = -3.0e38f;
#pragma unroll
            for (int k = 0; k < KNB; k++) mx = fmaxf(mx, scf[base + k]);
            float sum = 0.f;
            float e[KNB];
#pragma unroll
            for (int k = 0; k < KNB; k++) {
                e[k] = __expf(scf[base + k] - mx);
                sum += e[k];
            }
            float inv = 1.0f / sum;
#pragma unroll
            for (int k = 0; k < KNB; k++) wtf[base + k] = e[k] * inv;
        } else if (tid < 24 && has_next) {
            const int q8 = tid - 16;
            int any = 0;
#pragma unroll
            for (int k = 0; k < KNB; k++) any |= smask[nbuf * 80 + q8 * KNB + k];
            if (!any) smask[nbuf * 80 + q8 * KNB + KNB - 1] = 1;
            sinv[nbuf * 8 + q8] = !any;
            p.invalid[nb_blk * 8 + q8] = (unsigned char)(!any);
        }
        __syncthreads();

        // ---- weighted V -> attn_out (512 threads) ----
        {
            const int q8 = tid >> 6;
            const int d0 = (tid & 63) * 4;
            const int h = d0 >> 7;
            float o0 = 0.f, o1 = 0.f, o2 = 0.f, o3 = 0.f;
            const float* w = wtf + (q8 * 2 + h) * KNB;
#pragma unroll
            for (int k = 0; k < KNB; k++) {
                const __half2* vp = (const __half2*)(kvs + (size_t)(q8 * KNB + k) * KVS_LD + 256 + d0);
                float2 v01 = __half22float2(vp[0]);
                float2 v23 = __half22float2(vp[1]);
                float wk = w[k];
                o0 = fmaf(wk, v01.x, o0);
                o1 = fmaf(wk, v01.y, o1);
                o2 = fmaf(wk, v23.x, o2);
                o3 = fmaf(wk, v23.y, o3);
            }
            if (sinv[it * 8 + q8]) { o0 = 0.f; o1 = 0.f; o2 = 0.f; o3 = 0.f; }
            __half* op = p.attn_out + (size_t)(gq0 + q8) * 256 + d0;
            *(__half2*)op = __floats2half2_rn(o0, o1);
            *(__half2*)(op + 2) = __floats2half2_rn(o2, o3);
        }
        __syncthreads();   // perm writes visible; kvs free
        it ^= 1;
    }
}

// ===========================================================================
// Q GEMM (fp16 m16n8k16): CTA = 128(m) x 128(n), K=128, gather A, fp16 out.
// ===========================================================================
struct TcParams {
    const float* W;
    const float* bias;
    __half* C;
    const float *nf, *memv;
    const int *idx;
};

__global__ void __launch_bounds__(256) q_gemm(TcParams p) {
    __shared__ uint32_t As[128][20];
    __shared__ uint32_t Bs[128][20];
    const int tid = threadIdx.x;
    const int lane = tid & 31;
    const int wid = tid >> 5;
    const int bm = blockIdx.x * 128;
    const int noff = blockIdx.y * 128;
    const float* W = p.W + (size_t)noff * 256;
    const float* bias = p.bias + noff;
    const int row = tid >> 1;
    const int seg = tid & 1;
    const int m = bm + row;
    const int wr = (wid >> 1) * 32;
    const int wc = (wid & 1) * 64;
    const int gID = lane >> 2;
    const int tg = lane & 3;

    float acc[2][8][4];
#pragma unroll
    for (int mi = 0; mi < 2; mi++)
#pragma unroll
        for (int nj = 0; nj < 8; nj++)
#pragma unroll
            for (int q = 0; q < 4; q++) acc[mi][nj][q] = 0.f;

#pragma unroll 1
    for (int k0 = 0; k0 < 128; k0 += 32) {
        const int kb = k0 + seg * 16;
        {
            int nd = __ldg(&p.idx[m]);
            const float* s0 = p.nf + (size_t)nd * 128 + kb;
            const float* s1 = p.memv + (size_t)nd * 128 + kb;
            uint32_t h[8];
#pragma unroll
            for (int i = 0; i < 4; i++) {
                float4 v = *(const float4*)(s0 + i * 4);
                float4 w = *(const float4*)(s1 + i * 4);
                v.x += w.x; v.y += w.y; v.z += w.z; v.w += w.w;
                h[i * 2 + 0] = f2h2(v.x, v.y);
                h[i * 2 + 1] = f2h2(v.z, v.w);
            }
            *(uint4*)&As[row][seg * 8] = make_uint4(h[0], h[1], h[2], h[3]);
            *(uint4*)&As[row][seg * 8 + 4] = make_uint4(h[4], h[5], h[6], h[7]);
        }
        {
            const float* wsrc = W + (size_t)row * 256 + kb;
            uint32_t h[8];
#pragma unroll
            for (int i = 0; i < 4; i++) {
                float4 v = *(const float4*)(wsrc + i * 4);
                h[i * 2 + 0] = f2h2(v.x, v.y);
                h[i * 2 + 1] = f2h2(v.z, v.w);
            }
            *(uint4*)&Bs[row][seg * 8] = make_uint4(h[0], h[1], h[2], h[3]);
            *(uint4*)&Bs[row][seg * 8 + 4] = make_uint4(h[4], h[5], h[6], h[7]);
        }
        __syncthreads();
#pragma unroll
        for (int kt = 0; kt < 2; kt++) {
            const int cb = kt * 8;
            uint32_t a[2][4];
#pragma unroll
            for (int mi = 0; mi < 2; mi++) {
                int r0 = wr + mi * 16 + gID;
                a[mi][0] = As[r0][cb + tg];
                a[mi][1] = As[r0 + 8][cb + tg];
                a[mi][2] = As[r0][cb + 4 + tg];
                a[mi][3] = As[r0 + 8][cb + 4 + tg];
            }
#pragma unroll
            for (int nj = 0; nj < 8; nj++) {
                int nb_ = wc + nj * 8 + gID;
                uint32_t b0 = Bs[nb_][cb + tg];
                uint32_t b1 = Bs[nb_][cb + 4 + tg];
                mma_f16(acc[0][nj], a[0], b0, b1);
                mma_f16(acc[1][nj], a[1], b0, b1);
            }
        }
        __syncthreads();
    }

#pragma unroll
    for (int mi = 0; mi < 2; mi++) {
        const int r_lo = bm + wr + mi * 16 + gID;
        const int r_hi = r_lo + 8;
        __half* clo = p.C + (size_t)r_lo * 256 + noff;
        __half* chi = p.C + (size_t)r_hi * 256 + noff;
#pragma unroll
        for (int nj = 0; nj < 8; nj++) {
            const int cl = wc + nj * 8 + tg * 2;
            const float b0 = __ldg(&bias[cl]);
            const float b1 = __ldg(&bias[cl + 1]);
            *(__half2*)(clo + cl) = __floats2half2_rn(acc[mi][nj][0] + b0, acc[mi][nj][1] + b1);
            *(__half2*)(chi + cl) = __floats2half2_rn(acc[mi][nj][2] + b0, acc[mi][nj][3] + b1);
        }
    }
}

// ===========================================================================
// Fused tail kernel (O+fc1+fc2). HALF_OUT=1 writes fp16 (emb1), else fp32.
// ===========================================================================
struct FtParams {
    const float* Wcat;
    const float* f1b;
    const float* c0;
    const float* f2w;
    const float* f2b;
    void* C;
    const __half* Ah;
    const float *nf, *memv;
    const int* idx;
    const unsigned char* invalid;
};

#define FT_DSMEM (20480 + 32768 + 32768)

__device__ __forceinline__ void ft_stashA(uint32_t* As2, int m, int k, uint32_t h2) {
    int kt = k >> 4, mi8 = m >> 4;
    int r16 = m & 15, gid = r16 & 7, hi_r = r16 >> 3;
    int klo = k & 15, tg = (klo & 7) >> 1;
    int reg = hi_r + ((klo >> 3) << 1);
    As2[(((kt * 8 + mi8) * 32) + gid * 4 + tg) * 4 + reg] = h2;
}
__device__ __forceinline__ void ft_stashB(uint32_t* Bs2, int n, int k, uint32_t h2) {
    int kt = k >> 4, nt = n >> 3;
    int gid = n & 7;
    int klo = k & 15, tg = (klo & 7) >> 1, reg = klo >> 3;
    Bs2[(((nt * 8 + kt) * 32) + gid * 4 + tg) * 2 + reg] = h2;
}

template <int HALF_OUT>
__global__ void __launch_bounds__(256) fused_tail(FtParams p) {
    extern __shared__ char sm[];
    uint32_t (*As)[20] = (uint32_t(*)[20])sm;
    uint32_t (*Bs)[20] = (uint32_t(*)[20])(sm + 10240);
    uint32_t* As2 = (uint32_t*)(sm + 20480);
    uint32_t* Bs2 = (uint32_t*)(sm + 53248);

    const int tid = threadIdx.x;
    const int lane = tid & 31;
    const int wid = tid >> 5;
    const int bm = blockIdx.x * 128;
    const int row = tid >> 1;
    const int seg = tid & 1;
    const int m = bm + row;
    const int wr = (wid >> 1) * 32;
    const int wc = (wid & 1) * 64;
    const int gID = lane >> 2;
    const int tg = lane & 3;

    for (int i = tid; i < 8192; i += 256) {
        int n = i >> 6;
        int k = (i & 63) * 2;
        float v0 = __ldg(&p.f2w[n * 128 + k]);
        float v1 = __ldg(&p.f2w[n * 128 + k + 1]);
        ft_stashB(Bs2, n, k, f2h2(v0, v1));
    }

    float acc[2][8][4];
#pragma unroll
    for (int mi = 0; mi < 2; mi++)
#pragma unroll
        for (int nj = 0; nj < 8; nj++)
#pragma unroll
            for (int q = 0; q < 4; q++) acc[mi][nj][q] = 0.f;

#pragma unroll 1
    for (int k0 = 0; k0 < 384; k0 += 32) {
        const int kb = k0 + seg * 16;
        if (kb < 256) {
            const __half* ah = p.Ah + (size_t)m * 256 + kb;
            *(uint4*)&As[row][seg * 8] = *(const uint4*)ah;
            *(uint4*)&As[row][seg * 8 + 4] = *(const uint4*)(ah + 8);
        } else {
            int nd = __ldg(&p.idx[m]);
            const float* s0 = p.nf + (size_t)nd * 128 + (kb - 256);
            const float* s1 = p.memv + (size_t)nd * 128 + (kb - 256);
            uint32_t h[8];
#pragma unroll
            for (int i = 0; i < 4; i++) {
                float4 v = *(const float4*)(s0 + i * 4);
                float4 w = *(const float4*)(s1 + i * 4);
                v.x += w.x; v.y += w.y; v.z += w.z; v.w += w.w;
                h[i * 2 + 0] = f2h2(v.x, v.y);
                h[i * 2 + 1] = f2h2(v.z, v.w);
            }
            *(uint4*)&As[row][seg * 8] = make_uint4(h[0], h[1], h[2], h[3]);
            *(uint4*)&As[row][seg * 8 + 4] = make_uint4(h[4], h[5], h[6], h[7]);
        }
        {
            const float* wsrc = p.Wcat + (size_t)row * 384 + kb;
            uint32_t h[8];
#pragma unroll
            for (int i = 0; i < 4; i++) {
                float4 v = *(const float4*)(wsrc + i * 4);
                h[i * 2 + 0] = f2h2(v.x, v.y);
                h[i * 2 + 1] = f2h2(v.z, v.w);
            }
            *(uint4*)&Bs[row][seg * 8] = make_uint4(h[0], h[1], h[2], h[3]);
            *(uint4*)&Bs[row][seg * 8 + 4] = make_uint4(h[4], h[5], h[6], h[7]);
        }
        __syncthreads();
#pragma unroll
        for (int kt = 0; kt < 2; kt++) {
            const int cb = kt * 8;
            uint32_t a[2][4];
#pragma unroll
            for (int mi = 0; mi < 2; mi++) {
                int r0 = wr + mi * 16 + gID;
                a[mi][0] = As[r0][cb + tg];
                a[mi][1] = As[r0 + 8][cb + tg];
                a[mi][2] = As[r0][cb + 4 + tg];
                a[mi][3] = As[r0 + 8][cb + 4 + tg];
            }
#pragma unroll
            for (int nj = 0; nj < 8; nj++) {
                int nb_ = wc + nj * 8 + gID;
                uint32_t b0 = Bs[nb_][cb + tg];
                uint32_t b1 = Bs[nb_][cb + 4 + tg];
                mma_f16(acc[0][nj], a[0], b0, b1);
                mma_f16(acc[1][nj], a[1], b0, b1);
            }
        }
        __syncthreads();
    }

#pragma unroll
    for (int mi = 0; mi < 2; mi++) {
        const int rl = wr + mi * 16 + gID;
        const int rh = rl + 8;
        const bool z_lo = p.invalid[bm + rl];
        const bool z_hi = p.invalid[bm + rh];
#pragma unroll
        for (int nj = 0; nj < 8; nj++) {
            const int cl = wc + nj * 8 + tg * 2;
            const float b0 = __ldg(&p.f1b[cl]);
            const float b1 = __ldg(&p.f1b[cl + 1]);
            const float cb0 = __ldg(&p.c0[cl]);
            const float cb1 = __ldg(&p.c0[cl + 1]);
            float v00 = fmaxf(acc[mi][nj][0] + b0 + (z_lo ? 0.f : cb0), 0.f);
            float v01 = fmaxf(acc[mi][nj][1] + b1 + (z_lo ? 0.f : cb1), 0.f);
            float v10 = fmaxf(acc[mi][nj][2] + b0 + (z_hi ? 0.f : cb0), 0.f);
            float v11 = fmaxf(acc[mi][nj][3] + b1 + (z_hi ? 0.f : cb1), 0.f);
            ft_stashA(As2, rl, cl, f2h2(v00, v01));
            ft_stashA(As2, rh, cl, f2h2(v10, v11));
        }
    }
    __syncthreads();

    float acc2[2][8][4];
#pragma unroll
    for (int mi = 0; mi < 2; mi++)
#pragma unroll
        for (int nj = 0; nj < 8; nj++)
#pragma unroll
            for (int q = 0; q < 4; q++) acc2[mi][nj][q] = 0.f;

    const uint4* As2_4 = (const uint4*)As2;
    const int mi8base = wr >> 4;
#pragma unroll
    for (int kt = 0; kt < 8; kt++) {
        uint4 a0v = As2_4[(kt * 8 + mi8base) * 32 + lane];
        uint4 a1v = As2_4[(kt * 8 + mi8base + 1) * 32 + lane];
        uint32_t a0[4] = {a0v.x, a0v.y, a0v.z, a0v.w};
        uint32_t a1[4] = {a1v.x, a1v.y, a1v.z, a1v.w};
#pragma unroll
        for (int nj = 0; nj < 8; nj++) {
            int nt = (wc >> 3) + nj;
            uint2 bb = *(const uint2*)&Bs2[(((nt * 8 + kt) * 32) + lane) * 2];
            mma_f16(acc2[0][nj], a0, bb.x, bb.y);
            mma_f16(acc2[1][nj], a1, bb.x, bb.y);
        }
    }

#pragma unroll
    for (int mi = 0; mi < 2; mi++) {
        const int r_lo = bm + wr + mi * 16 + gID;
        const int r_hi = r_lo + 8;
#pragma unroll
        for (int nj = 0; nj < 8; nj++) {
            const int cl = wc + nj * 8 + tg * 2;
            const float b0 = __ldg(&p.f2b[cl]);
            const float b1 = __ldg(&p.f2b[cl + 1]);
            float v00 = acc2[mi][nj][0] + b0, v01 = acc2[mi][nj][1] + b1;
            float v10 = acc2[mi][nj][2] + b0, v11 = acc2[mi][nj][3] + b1;
            if (HALF_OUT) {
                __half* clo = (__half*)p.C + (size_t)r_lo * 128;
                __half* chi = (__half*)p.C + (size_t)r_hi * 128;
                *(__half2*)(clo + cl) = __floats2half2_rn(v00, v01);
                *(__half2*)(chi + cl) = __floats2half2_rn(v10, v11);
            } else {
                float* clo = (float*)p.C + (size_t)r_lo * 128;
                float* chi = (float*)p.C + (size_t)r_hi * 128;
                *(float2*)(clo + cl) = make_float2(v00, v01);
                *(float2*)(chi + cl) = make_float2(v10, v11);
            }
        }
    }
}

// ---------------------------------------------------------------------------
// Host side
// ---------------------------------------------------------------------------
extern "C" void kernel_launch(void* const* d_in, const int* in_sizes, int n_in,
                              void* d_out, int out_size) {
    const float* nf   = (const float*)d_in[0];
    const float* mem  = (const float*)d_in[1];
    const float* ef   = (const float*)d_in[2];
    const float* tw   = (const float*)d_in[3];
    const float* tb   = (const float*)d_in[4];
    const float* Wq   = (const float*)d_in[5];
    const float* bq   = (const float*)d_in[6];
    const float* Wk   = (const float*)d_in[7];
    const float* bk   = (const float*)d_in[8];
    const float* Wv   = (const float*)d_in[9];
    const float* bv   = (const float*)d_in[10];
    const float* Wo   = (const float*)d_in[11];
    const float* bo   = (const float*)d_in[12];
    const float* f1w  = (const float*)d_in[13];
    const float* f1b  = (const float*)d_in[14];
    const float* f2w  = (const float*)d_in[15];
    const float* f2b  = (const float*)d_in[16];
    const int*   src  = (const int*)d_in[17];
    const float* ts   = (const float*)d_in[18];
    const int*   nb2  = (const int*)d_in[19];
    const int*   ei2  = (const int*)d_in[20];
    const float* tm2  = (const float*)d_in[21];
    const int*   nb1  = (const int*)d_in[22];
    const int*   ei1  = (const int*)d_in[23];
    const float* tm1  = (const float*)d_in[24];
    float* out = (float*)d_out;

    float *pwcat, *pc0, *pbq2;
    __half *pbph, *pq1, *pq2, *pattn1, *pattn2, *pemb1;
    unsigned char *pinv1, *pinv2;
    cudaGetSymbolAddress((void**)&pq1, g_q1);
    cudaGetSymbolAddress((void**)&pattn1, g_attn1);
    cudaGetSymbolAddress((void**)&pemb1, g_emb1);
    cudaGetSymbolAddress((void**)&pinv1, g_inv1);
    cudaGetSymbolAddress((void**)&pq2, g_q2);
    cudaGetSymbolAddress((void**)&pattn2, g_attn2);
    cudaGetSymbolAddress((void**)&pinv2, g_inv2);
    cudaGetSymbolAddress((void**)&pbph, g_bph);
    cudaGetSymbolAddress((void**)&pwcat, g_wcat);
    cudaGetSymbolAddress((void**)&pc0, g_c0);
    cudaGetSymbolAddress((void**)&pbq2, g_bq2);

    static cudaStream_t s_side = nullptr;
    static cudaEvent_t ev_fork = nullptr, ev_q1 = nullptr, ev_join = nullptr;
    if (s_side == nullptr) {
        cudaStreamCreateWithFlags(&s_side, cudaStreamNonBlocking);
        cudaEventCreateWithFlags(&ev_fork, cudaEventDisableTiming);
        cudaEventCreateWithFlags(&ev_q1, cudaEventDisableTiming);
        cudaEventCreateWithFlags(&ev_join, cudaEventDisableTiming);
        cudaFuncSetAttribute(kv_kernel<0>, cudaFuncAttributeMaxDynamicSharedMemorySize, KV_DSMEM);
        cudaFuncSetAttribute(kv_kernel<1>, cudaFuncAttributeMaxDynamicSharedMemorySize, KV_DSMEM);
        cudaFuncSetAttribute(fused_tail<0>, cudaFuncAttributeMaxDynamicSharedMemorySize, FT_DSMEM);
        cudaFuncSetAttribute(fused_tail<1>, cudaFuncAttributeMaxDynamicSharedMemorySize, FT_DSMEM);
    }

    const cudaStream_t s0 = 0;

    const float* bk1 = bk + 256;
    const float* bv1 = bv + 256;
    const float* f2w1 = f2w + 128 * 128; const float* f2b1 = f2b + 128;

    // ---- side stream: prep_bq -> Q1 (ev_q1) -> Q2, prep_wc, prep_b L1 ----
    cudaEventRecord(ev_fork, s0);
    cudaStreamWaitEvent(s_side, ev_fork, 0);

    prep_bq_kernel<<<2, 256, 0, s_side>>>(Wq, bq, tb, pbq2);
    {   // Q1 (fp16 out, K=128)
        TcParams p{};
        p.W = Wq; p.bias = pbq2; p.C = pq1;
        p.nf = nf; p.memv = mem; p.idx = nb2;
        q_gemm<<<dim3(N1 / 128, 2), 256, 0, s_side>>>(p);
    }
    cudaEventRecord(ev_q1, s_side);
    {   // Q2 (fp16 out, K=128)
        TcParams p{};
        p.W = Wq + 256 * 256; p.bias = pbq2 + 256; p.C = pq2;
        p.nf = nf; p.memv = mem; p.idx = src;
        q_gemm<<<dim3(BB / 128, 2), 256, 0, s_side>>>(p);
    }
    prep_wc_kernel<<<256, 384, 0, s_side>>>(Wo, bo, f1w, pwcat, pc0);
    prep_b_kernel<<<(512 * 384 + 255) / 256, 256, 0, s_side>>>(Wk, Wv, pbph, 1);
    cudaEventRecord(ev_join, s_side);

    // ---- main stream: prep_b L0, wait q1, fused KV1+attn1 ----
    prep_b_kernel<<<(512 * 384 + 255) / 256, 256, 0, s0>>>(Wk, Wv, pbph, 0);
    cudaStreamWaitEvent(s0, ev_q1, 0);
    {
        KvParams p{};
        p.Bp = pbph; p.bk = bk; p.bv = bv;
        p.q = pq1; p.attn_out = pattn1; p.invalid = pinv1; p.mask_idx = nb1;
        p.DIV = 100; p.nblk = NP1 / 80;
        p.ts = ts; p.etm = tm1; p.tw = tw; p.tb = tb;
        p.nf = nf; p.memv = mem; p.ef = ef; p.idx = nb1; p.eidx = ei1;
        kv_kernel<0><<<148, 512, KV_DSMEM, s0>>>(p);
    }
    cudaStreamWaitEvent(s0, ev_join, 0);

    {   // fused O1+fc1+fc2 (L0) -> emb1 (fp16)
        FtParams p{};
        p.Wcat = pwcat; p.f1b = f1b; p.c0 = pc0;
        p.f2w = f2w; p.f2b = f2b; p.C = pemb1;
        p.Ah = pattn1; p.nf = nf; p.memv = mem; p.idx = nb2; p.invalid = pinv1;
        fused_tail<1><<<N1 / 128, 256, FT_DSMEM, s0>>>(p);
    }
    {   // fused KV2+attn2 (dense fp16 emb1)
        KvParams p{};
        p.Bp = pbph + 512 * 384; p.bk = bk1; p.bv = bv1;
        p.q = pq2; p.attn_out = pattn2; p.invalid = pinv2; p.mask_idx = nb2;
        p.DIV = 10; p.nblk = NP2 / 80;
        p.ts = ts; p.etm = tm2; p.tw = tw; p.tb = tb;
        p.Adense = pemb1; p.ef = ef; p.eidx = ei2;
        kv_kernel<1><<<148, 512, KV_DSMEM, s0>>>(p);
    }
    {   // fused O2+fc1+fc2 (L1) -> out (fp32)
        FtParams p{};
        p.Wcat = pwcat + 128 * 384; p.f1b = f1b + 128; p.c0 = pc0 + 128;
        p.f2w = f2w1; p.f2b = f2b1; p.C = out;
        p.Ah = pattn2; p.nf = nf; p.memv = mem; p.idx = src; p.invalid = pinv2;
        fused_tail<0><<<BB / 128, 256, FT_DSMEM, s0>>>(p);
    }
}

// round 17
// speedup vs baseline: 1.4185x; 1.0026x over previous
#include <cuda_runtime.h>
#include <cuda_fp16.h>
#include <cstdint>

// ---------------------------------------------------------------------------
// Problem constants
// ---------------------------------------------------------------------------
#define KNB 10
#define BB  2048
#define N1  20480
#define NP1 204800
#define NP2 20480
// D = T = 128, QD = 256, KD = 384, H = 2, hd = 128

// ---------------------------------------------------------------------------
// Scratch
// ---------------------------------------------------------------------------
__device__ __half g_q1 [(size_t)N1  * 256];
__device__ __half g_attn1[(size_t)N1 * 256];
__device__ __half g_emb1[(size_t)N1 * 128];
__device__ unsigned char g_inv1[N1];
__device__ __half g_q2 [(size_t)BB  * 256];
__device__ __half g_attn2[(size_t)BB * 256];
__device__ unsigned char g_inv2[BB];
__device__ __half g_bph[2 * 512 * 384];
__device__ float g_wcat[2 * 128 * 384];
__device__ float g_c0[2 * 128];
__device__ float g_bq2[2 * 256];

// ---------------------------------------------------------------------------
// fp16 mma helper + fast cosine
// ---------------------------------------------------------------------------
__device__ __forceinline__ void mma_f16(float* c, const uint32_t* a, uint32_t b0, uint32_t b1) {
    asm volatile(
        "mma.sync.aligned.m16n8k16.row.col.f32.f16.f16.f32 "
        "{%0,%1,%2,%3}, {%4,%5,%6,%7}, {%8,%9}, {%0,%1,%2,%3};"
        : "+f"(c[0]), "+f"(c[1]), "+f"(c[2]), "+f"(c[3])
        : "r"(a[0]), "r"(a[1]), "r"(a[2]), "r"(a[3]), "r"(b0), "r"(b1));
}
__device__ __forceinline__ uint32_t f2h2(float a, float b) {
    __half2 h = __floats2half2_rn(a, b);
    return *(uint32_t*)&h;
}
__device__ __forceinline__ float fast_cos(float t) {
    float qf = rintf(t * 0.6366197723675814f);
    int q = (int)qf;
    float r = fmaf(qf, -1.5707962513f, t);
    r = fmaf(qf, -7.54978942e-8f, r);
    float z = r * r;
    float cp = fmaf(z, fmaf(z, fmaf(z, -1.3888397e-3f, 4.16666418e-2f), -0.5f), 1.0f);
    float sp = r * fmaf(z, fmaf(z, 8.3321608e-3f, -1.66666547e-1f), 1.0f);
    float v = (q & 1) ? sp : cp;
    uint32_t sgn = (uint32_t)((q + 1) & 2) << 30;
    return __uint_as_float(__float_as_uint(v) ^ sgn);
}

// ===========================================================================
// B pre-permutation (one layer per launch)
// ===========================================================================
__global__ void prep_b_kernel(const float* __restrict__ Wk, const float* __restrict__ Wv,
                              __half* __restrict__ dst, int layer) {
    int idx = blockIdx.x * blockDim.x + threadIdx.x;
    if (idx >= 512 * 384) return;
    int n = idx / 384;
    int k = idx - n * 384;
    const float* W = (n < 256) ? (Wk + (size_t)layer * 256 * 384 + (size_t)n * 384)
                               : (Wv + (size_t)layer * 256 * 384 + (size_t)(n - 256) * 384);
    float v = W[k];
    int nt = n >> 3, gid = n & 7;
    int ktp = k >> 5, k32 = k & 31;
    int kt_in = k32 >> 4, klo = k32 & 15;
    int tg = (klo & 7) >> 1, reg = klo >> 3, par = k & 1;
    int lane = gid * 4 + tg;
    size_t off = ((((size_t)layer * 64 + nt) * 12 + ktp) * 32 + lane) * 8 + (kt_in * 2 + reg) * 2 + par;
    dst[off] = __float2half_rn(v);
}

// ===========================================================================
// Tail fold: Wcat / c0
// ===========================================================================
__global__ void prep_wc_kernel(const float* __restrict__ Wo, const float* __restrict__ bo,
                               const float* __restrict__ f1w,
                               float* __restrict__ wcat, float* __restrict__ c0) {
    int l = blockIdx.x >> 7;
    int i = blockIdx.x & 127;
    int k = threadIdx.x;
    const float* f1 = f1w + ((size_t)l * 128 + i) * 384;
    float v;
    if (k < 256) {
        const float* wo = Wo + (size_t)l * 256 * 256;
        float s = 0.f;
#pragma unroll 4
        for (int j = 0; j < 256; j++) s = fmaf(f1[j], wo[j * 256 + k], s);
        v = s;
    } else {
        v = f1[k];
    }
    wcat[((size_t)l * 128 + i) * 384 + k] = v;
    if (k == 0) {
        const float* bol = bo + l * 256;
        float s = 0.f;
#pragma unroll 4
        for (int j = 0; j < 256; j++) s = fmaf(f1[j], bol[j], s);
        c0[l * 128 + i] = s;
    }
}

// ===========================================================================
// Q-bias fold
// ===========================================================================
__global__ void prep_bq_kernel(const float* __restrict__ Wq, const float* __restrict__ bq,
                               const float* __restrict__ tb, float* __restrict__ bq2) {
    int l = blockIdx.x;
    int n = threadIdx.x;
    __shared__ float st[128];
    if (n < 128) st[n] = __cosf(tb[n]);
    __syncthreads();
    const float* w = Wq + (((size_t)l * 256 + n) * 256) + 128;
    float s = bq[l * 256 + n];
#pragma unroll 4
    for (int j = 0; j < 128; j++) s = fmaf(st[j], w[j], s);
    bq2[l * 256 + n] = s;
}

// ===========================================================================
// FUSED KV + attention kernel, pipelined convert + double-buffered B.
// ===========================================================================
struct KvParams {
    const __half* Bp;
    const float *bk, *bv;
    const __half* q;
    __half* attn_out;
    unsigned char* invalid;
    const int* mask_idx;
    int DIV, nblk;
    const float *ts, *etm, *tw, *tb;
    const __half* Adense;
    const float *nf, *memv, *ef;
    const int *idx, *eidx;
};

#define KV_OFF_PERM  0
#define KV_OFF_KVS   61440
#define KV_OFF_QS    (61440 + 83200)
#define KV_OFF_SC    (KV_OFF_QS + 8192)
#define KV_OFF_WT    (KV_OFF_SC + 640)
#define KV_OFF_MASK  (KV_OFF_WT + 640)
#define KV_OFF_SINV  (KV_OFF_MASK + 640)
#define KV_DSMEM     (KV_OFF_SINV + 64)
#define KVS_LD 520

__device__ __forceinline__ void kv_stash_h2(uint32_t* As, int m, int k, uint32_t h2) {
    int kt = k >> 4, mi = m >> 4;
    int r16 = m & 15, gid = r16 & 7, hi_r = r16 >> 3;
    int klo = k & 15, tg = (klo & 7) >> 1;
    int reg = hi_r + ((klo >> 3) << 1);
    As[(((kt * 5 + mi) * 32) + gid * 4 + tg) * 4 + reg] = h2;
}

template <int DENSE>
__device__ __forceinline__ void kv_convert_row(uint32_t* As, int bm, int grow, int gseg,
                                               const KvParams& p) {
    const int m = bm + grow;
    if (DENSE) {
        const uint2* s = (const uint2*)(p.Adense + (size_t)m * 128);
#pragma unroll
        for (int i = 0; i < 4; i++) {
            int cf = gseg + 8 * i;
            uint2 u = s[cf];
            int k = cf * 4;
            kv_stash_h2(As, grow, k, u.x);
            kv_stash_h2(As, grow, k + 2, u.y);
        }
    } else {
        int nd = __ldg(&p.idx[m]);
        const float4* s0 = (const float4*)(p.nf + (size_t)nd * 128);
        const float4* s1 = (const float4*)(p.memv + (size_t)nd * 128);
#pragma unroll
        for (int i = 0; i < 4; i++) {
            int cf = gseg + 8 * i;
            float4 x = s0[cf], y = s1[cf];
            int k = cf * 4;
            kv_stash_h2(As, grow, k, f2h2(x.x + y.x, x.y + y.y));
            kv_stash_h2(As, grow, k + 2, f2h2(x.z + y.z, x.w + y.w));
        }
    }
    {
        int e = __ldg(&p.eidx[m]);
        const float4* s = (const float4*)(p.ef + (size_t)e * 128);
#pragma unroll
        for (int i = 0; i < 4; i++) {
            int cf = gseg + 8 * i;
            float4 v = s[cf];
            int k = cf * 4;
            kv_stash_h2(As, grow, 128 + k, f2h2(v.x, v.y));
            kv_stash_h2(As, grow, 128 + k + 2, f2h2(v.z, v.w));
        }
    }
    float dt = __ldg(&p.ts[m / p.DIV]) - __ldg(&p.etm[m]);
#pragma unroll
    for (int i = 0; i < 4; i++) {
        int j0 = (gseg + 8 * i) * 4;
        float c0 = fast_cos(fmaf(dt, __ldg(&p.tw[j0 + 0]), __ldg(&p.tb[j0 + 0])));
        float c1 = fast_cos(fmaf(dt, __ldg(&p.tw[j0 + 1]), __ldg(&p.tb[j0 + 1])));
        float c2 = fast_cos(fmaf(dt, __ldg(&p.tw[j0 + 2]), __ldg(&p.tb[j0 + 2])));
        float c3 = fast_cos(fmaf(dt, __ldg(&p.tw[j0 + 3]), __ldg(&p.tb[j0 + 3])));
        kv_stash_h2(As, grow, 256 + j0, f2h2(c0, c1));
        kv_stash_h2(As, grow, 256 + j0 + 2, f2h2(c2, c3));
    }
}

template <int DENSE>
__global__ void __launch_bounds__(512, 1) kv_kernel(KvParams p) {
    extern __shared__ char smem[];
    uint32_t* perm = (uint32_t*)(smem + KV_OFF_PERM);
    __half* kvs = (__half*)(smem + KV_OFF_KVS);
    __half* qs = (__half*)(smem + KV_OFF_QS);
    float* scf = (float*)(smem + KV_OFF_SC);
    float* wtf = (float*)(smem + KV_OFF_WT);
    int* smask = (int*)(smem + KV_OFF_MASK);
    int* sinv = (int*)(smem + KV_OFF_SINV);

    const int tid = threadIdx.x;
    const int lane = tid & 31;
    const int wid = tid >> 5;
    const int gID = lane >> 2;
    const int tg = lane & 3;
    const char* bpw = (const char*)p.Bp + (size_t)(wid * 4) * 6144;

    // ---- prologue ----
    {
        const int bm = blockIdx.x * 80;
        const int gq0 = blockIdx.x * 8;
        kv_convert_row<DENSE>(perm, bm, tid >> 3, tid & 7, p);
        if (tid < 128) kv_convert_row<DENSE>(perm, bm, 64 + (tid >> 3), tid & 7, p);
        if (tid < 256) ((uint4*)qs)[tid] = ((const uint4*)(p.q + (size_t)gq0 * 256))[tid];
        if (tid < 80) smask[tid] = (__ldg(&p.mask_idx[bm + tid]) != 0) ? 1 : 0;
        __syncthreads();
        if (tid < 8) {
            int any = 0;
#pragma unroll
            for (int k = 0; k < KNB; k++) any |= smask[tid * KNB + k];
            if (!any) smask[tid * KNB + KNB - 1] = 1;
            sinv[tid] = !any;
            p.invalid[gq0 + tid] = (unsigned char)(!any);
        }
        __syncthreads();
    }

    int it = 0;
#pragma unroll 1
    for (int blk = blockIdx.x; blk < p.nblk; blk += gridDim.x) {
        const int gq0 = blk * 8;

        // ---- MMA: 80 rows x 512 cols, B double-buffered ----
        float acc[5][4][4];
#pragma unroll
        for (int mi = 0; mi < 5; mi++)
#pragma unroll
            for (int nj = 0; nj < 4; nj++)
#pragma unroll
                for (int q8 = 0; q8 < 4; q8++) acc[mi][nj][q8] = 0.f;

        const uint4* As4 = (const uint4*)perm;
        uint4 bA[4], bB[4];

#define KV_LDB(buf, ktp_) { \
    _Pragma("unroll") \
    for (int nj = 0; nj < 4; nj++) \
        buf[nj] = *(const uint4*)(bpw + (size_t)nj * 6144 + (ktp_) * 512 + lane * 16); }

#define KV_STEP(buf, ktp_) { \
    _Pragma("unroll") \
    for (int kt_in = 0; kt_in < 2; kt_in++) { \
        const int kt = (ktp_) * 2 + kt_in; \
        _Pragma("unroll") \
        for (int mi = 0; mi < 5; mi++) { \
            uint4 av = As4[(kt * 5 + mi) * 32 + lane]; \
            uint32_t aa[4] = {av.x, av.y, av.z, av.w}; \
            _Pragma("unroll") \
            for (int nj = 0; nj < 4; nj++) { \
                uint32_t b0 = kt_in ? buf[nj].z : buf[nj].x; \
                uint32_t b1 = kt_in ? buf[nj].w : buf[nj].y; \
                mma_f16(acc[mi][nj], aa, b0, b1); \
            } \
        } \
    } }

        KV_LDB(bA, 0);
#pragma unroll 1
        for (int ktp = 0; ktp < 12; ktp += 2) {
            KV_LDB(bB, ktp + 1);
            KV_STEP(bA, ktp);
            if (ktp + 2 < 12) KV_LDB(bA, ktp + 2);
            KV_STEP(bB, ktp + 1);
        }
#undef KV_LDB
#undef KV_STEP

        // ---- epilogue: kv tile -> smem (with bias) ----
#pragma unroll
        for (int mi = 0; mi < 5; mi++) {
            const int r_lo = mi * 16 + gID;
            __half* clo = kvs + (size_t)r_lo * KVS_LD;
            __half* chi = clo + (size_t)8 * KVS_LD;
#pragma unroll
            for (int nj = 0; nj < 4; nj++) {
                const int col = wid * 32 + nj * 8 + tg * 2;
                const float b0 = (col < 256) ? __ldg(&p.bk[col]) : __ldg(&p.bv[col - 256]);
                const float b1 = (col + 1 < 256) ? __ldg(&p.bk[col + 1]) : __ldg(&p.bv[col + 1 - 256]);
                *(__half2*)(clo + col) = __floats2half2_rn(acc[mi][nj][0] + b0, acc[mi][nj][1] + b1);
                *(__half2*)(chi + col) = __floats2half2_rn(acc[mi][nj][2] + b0, acc[mi][nj][3] + b1);
            }
        }
        __syncthreads();   // kvs ready; perm free

        const int nb_blk = blk + gridDim.x;
        const bool has_next = nb_blk < p.nblk;
        const int nbuf = it ^ 1;

        if (tid >= 160) {
            if (has_next) {
                const int bm_n = nb_blk * 80;
                int t0 = tid - 160;
                kv_convert_row<DENSE>(perm, bm_n, t0 >> 3, t0 & 7, p);
                int t1 = t0 + 352;
                if (t1 < 640) kv_convert_row<DENSE>(perm, bm_n, t1 >> 3, t1 & 7, p);
            }
        } else {
            if (has_next) {
                const uint4* qsrc = (const uint4*)(p.q + (size_t)(nb_blk * 8) * 256);
                uint4* qdst = (uint4*)(qs + nbuf * 2048);
                qdst[tid] = qsrc[tid];
                if (tid + 160 < 256) qdst[tid + 160] = qsrc[tid + 160];
                if (tid < 80)
                    smask[nbuf * 80 + tid] = (__ldg(&p.mask_idx[nb_blk * 80 + tid]) != 0) ? 1 : 0;
            }
            const int q8 = tid / 20;
            const int rem = tid - q8 * 20;
            const int h = rem / KNB;
            const int k = rem - h * KNB;
            const __half2* qp = (const __half2*)(qs + it * 2048 + q8 * 256 + h * 128);
            const __half2* kp = (const __half2*)(kvs + (size_t)(q8 * KNB + k) * KVS_LD + h * 128);
            float s = 0.f;
#pragma unroll 8
            for (int d = 0; d < 64; d++) {
                float2 a = __half22float2(qp[d]);
                float2 b = __half22float2(kp[d]);
                s = fmaf(a.x, b.x, s);
                s = fmaf(a.y, b.y, s);
            }
            const float scale = 0.08838834764831845f;
            scf[(q8 * 2 + h) * KNB + k] = smask[it * 80 + q8 * KNB + k] ? s * scale : -1e9f;
        }
        __syncthreads();

        if (tid < 16) {
            const int base = tid * KNB;
            float mx = -3.0e38f;
#pragma unroll
            for (int k = 0; k < KNB; k++) mx = fmaxf(mx, scf[base + k]);
            float sum = 0.f;
            float e[KNB];
#pragma unroll
            for (int k = 0; k < KNB; k++) {
                e[k] = __expf(scf[base + k] - mx);
                sum += e[k];
            }
            float inv = 1.0f / sum;
#pragma unroll
            for (int k = 0; k < KNB; k++) wtf[base + k] = e[k] * inv;
        } else if (tid < 24 && has_next) {
            const int q8 = tid - 16;
            int any = 0;
#pragma unroll
            for (int k = 0; k < KNB; k++) any |= smask[nbuf * 80 + q8 * KNB + k];
            if (!any) smask[nbuf * 80 + q8 * KNB + KNB - 1] = 1;
            sinv[nbuf * 8 + q8] = !any;
            p.invalid[nb_blk * 8 + q8] = (unsigned char)(!any);
        }
        __syncthreads();

        {
            const int q8 = tid >> 6;
            const int d0 = (tid & 63) * 4;
            const int h = d0 >> 7;
            float o0 = 0.f, o1 = 0.f, o2 = 0.f, o3 = 0.f;
            const float* w = wtf + (q8 * 2 + h) * KNB;
#pragma unroll
            for (int k = 0; k < KNB; k++) {
                const __half2* vp = (const __half2*)(kvs + (size_t)(q8 * KNB + k) * KVS_LD + 256 + d0);
                float2 v01 = __half22float2(vp[0]);
                float2 v23 = __half22float2(vp[1]);
                float wk = w[k];
                o0 = fmaf(wk, v01.x, o0);
                o1 = fmaf(wk, v01.y, o1);
                o2 = fmaf(wk, v23.x, o2);
                o3 = fmaf(wk, v23.y, o3);
            }
            if (sinv[it * 8 + q8]) { o0 = 0.f; o1 = 0.f; o2 = 0.f; o3 = 0.f; }
            __half* op = p.attn_out + (size_t)(gq0 + q8) * 256 + d0;
            *(__half2*)op = __floats2half2_rn(o0, o1);
            *(__half2*)(op + 2) = __floats2half2_rn(o2, o3);
        }
        __syncthreads();
        it ^= 1;
    }
}

// ===========================================================================
// Q GEMM (fp16 m16n8k16)
// ===========================================================================
struct TcParams {
    const float* W;
    const float* bias;
    __half* C;
    const float *nf, *memv;
    const int *idx;
};

__global__ void __launch_bounds__(256) q_gemm(TcParams p) {
    __shared__ uint32_t As[128][20];
    __shared__ uint32_t Bs[128][20];
    const int tid = threadIdx.x;
    const int lane = tid & 31;
    const int wid = tid >> 5;
    const int bm = blockIdx.x * 128;
    const int noff = blockIdx.y * 128;
    const float* W = p.W + (size_t)noff * 256;
    const float* bias = p.bias + noff;
    const int row = tid >> 1;
    const int seg = tid & 1;
    const int m = bm + row;
    const int wr = (wid >> 1) * 32;
    const int wc = (wid & 1) * 64;
    const int gID = lane >> 2;
    const int tg = lane & 3;

    float acc[2][8][4];
#pragma unroll
    for (int mi = 0; mi < 2; mi++)
#pragma unroll
        for (int nj = 0; nj < 8; nj++)
#pragma unroll
            for (int q = 0; q < 4; q++) acc[mi][nj][q] = 0.f;

#pragma unroll 1
    for (int k0 = 0; k0 < 128; k0 += 32) {
        const int kb = k0 + seg * 16;
        {
            int nd = __ldg(&p.idx[m]);
            const float* s0 = p.nf + (size_t)nd * 128 + kb;
            const float* s1 = p.memv + (size_t)nd * 128 + kb;
            uint32_t h[8];
#pragma unroll
            for (int i = 0; i < 4; i++) {
                float4 v = *(const float4*)(s0 + i * 4);
                float4 w = *(const float4*)(s1 + i * 4);
                v.x += w.x; v.y += w.y; v.z += w.z; v.w += w.w;
                h[i * 2 + 0] = f2h2(v.x, v.y);
                h[i * 2 + 1] = f2h2(v.z, v.w);
            }
            *(uint4*)&As[row][seg * 8] = make_uint4(h[0], h[1], h[2], h[3]);
            *(uint4*)&As[row][seg * 8 + 4] = make_uint4(h[4], h[5], h[6], h[7]);
        }
        {
            const float* wsrc = W + (size_t)row * 256 + kb;
            uint32_t h[8];
#pragma unroll
            for (int i = 0; i < 4; i++) {
                float4 v = *(const float4*)(wsrc + i * 4);
                h[i * 2 + 0] = f2h2(v.x, v.y);
                h[i * 2 + 1] = f2h2(v.z, v.w);
            }
            *(uint4*)&Bs[row][seg * 8] = make_uint4(h[0], h[1], h[2], h[3]);
            *(uint4*)&Bs[row][seg * 8 + 4] = make_uint4(h[4], h[5], h[6], h[7]);
        }
        __syncthreads();
#pragma unroll
        for (int kt = 0; kt < 2; kt++) {
            const int cb = kt * 8;
            uint32_t a[2][4];
#pragma unroll
            for (int mi = 0; mi < 2; mi++) {
                int r0 = wr + mi * 16 + gID;
                a[mi][0] = As[r0][cb + tg];
                a[mi][1] = As[r0 + 8][cb + tg];
                a[mi][2] = As[r0][cb + 4 + tg];
                a[mi][3] = As[r0 + 8][cb + 4 + tg];
            }
#pragma unroll
            for (int nj = 0; nj < 8; nj++) {
                int nb_ = wc + nj * 8 + gID;
                uint32_t b0 = Bs[nb_][cb + tg];
                uint32_t b1 = Bs[nb_][cb + 4 + tg];
                mma_f16(acc[0][nj], a[0], b0, b1);
                mma_f16(acc[1][nj], a[1], b0, b1);
            }
        }
        __syncthreads();
    }

#pragma unroll
    for (int mi = 0; mi < 2; mi++) {
        const int r_lo = bm + wr + mi * 16 + gID;
        const int r_hi = r_lo + 8;
        __half* clo = p.C + (size_t)r_lo * 256 + noff;
        __half* chi = p.C + (size_t)r_hi * 256 + noff;
#pragma unroll
        for (int nj = 0; nj < 8; nj++) {
            const int cl = wc + nj * 8 + tg * 2;
            const float b0 = __ldg(&bias[cl]);
            const float b1 = __ldg(&bias[cl + 1]);
            *(__half2*)(clo + cl) = __floats2half2_rn(acc[mi][nj][0] + b0, acc[mi][nj][1] + b1);
            *(__half2*)(chi + cl) = __floats2half2_rn(acc[mi][nj][2] + b0, acc[mi][nj][3] + b1);
        }
    }
}

// ===========================================================================
// Fused tail kernel (O+fc1+fc2), stage-1 with register prefetch of next chunk.
// ===========================================================================
struct FtParams {
    const float* Wcat;
    const float* f1b;
    const float* c0;
    const float* f2w;
    const float* f2b;
    void* C;
    const __half* Ah;
    const float *nf, *memv;
    const int* idx;
    const unsigned char* invalid;
};

#define FT_DSMEM (20480 + 32768 + 32768)

__device__ __forceinline__ void ft_stashA(uint32_t* As2, int m, int k, uint32_t h2) {
    int kt = k >> 4, mi8 = m >> 4;
    int r16 = m & 15, gid = r16 & 7, hi_r = r16 >> 3;
    int klo = k & 15, tg = (klo & 7) >> 1;
    int reg = hi_r + ((klo >> 3) << 1);
    As2[(((kt * 8 + mi8) * 32) + gid * 4 + tg) * 4 + reg] = h2;
}
__device__ __forceinline__ void ft_stashB(uint32_t* Bs2, int n, int k, uint32_t h2) {
    int kt = k >> 4, nt = n >> 3;
    int gid = n & 7;
    int klo = k & 15, tg = (klo & 7) >> 1, reg = klo >> 3;
    Bs2[(((nt * 8 + kt) * 32) + gid * 4 + tg) * 2 + reg] = h2;
}

__device__ __forceinline__ void ft_loadA(const FtParams& p, int m, int kb,
                                         uint4& lo, uint4& hi) {
    if (kb < 256) {
        const __half* ah = p.Ah + (size_t)m * 256 + kb;
        lo = *(const uint4*)ah;
        hi = *(const uint4*)(ah + 8);
    } else {
        int nd = __ldg(&p.idx[m]);
        const float* s0 = p.nf + (size_t)nd * 128 + (kb - 256);
        const float* s1 = p.memv + (size_t)nd * 128 + (kb - 256);
        uint32_t h[8];
#pragma unroll
        for (int i = 0; i < 4; i++) {
            float4 v = *(const float4*)(s0 + i * 4);
            float4 w = *(const float4*)(s1 + i * 4);
            v.x += w.x; v.y += w.y; v.z += w.z; v.w += w.w;
            h[i * 2 + 0] = f2h2(v.x, v.y);
            h[i * 2 + 1] = f2h2(v.z, v.w);
        }
        lo = make_uint4(h[0], h[1], h[2], h[3]);
        hi = make_uint4(h[4], h[5], h[6], h[7]);
    }
}
__device__ __forceinline__ void ft_loadB(const FtParams& p, int row, int kb,
                                         uint4& lo, uint4& hi) {
    const float* wsrc = p.Wcat + (size_t)row * 384 + kb;
    uint32_t h[8];
#pragma unroll
    for (int i = 0; i < 4; i++) {
        float4 v = *(const float4*)(wsrc + i * 4);
        h[i * 2 + 0] = f2h2(v.x, v.y);
        h[i * 2 + 1] = f2h2(v.z, v.w);
    }
    lo = make_uint4(h[0], h[1], h[2], h[3]);
    hi = make_uint4(h[4], h[5], h[6], h[7]);
}

template <int HALF_OUT>
__global__ void __launch_bounds__(256) fused_tail(FtParams p) {
    extern __shared__ char sm[];
    uint32_t (*As)[20] = (uint32_t(*)[20])sm;
    uint32_t (*Bs)[20] = (uint32_t(*)[20])(sm + 10240);
    uint32_t* As2 = (uint32_t*)(sm + 20480);
    uint32_t* Bs2 = (uint32_t*)(sm + 53248);

    const int tid = threadIdx.x;
    const int lane = tid & 31;
    const int wid = tid >> 5;
    const int bm = blockIdx.x * 128;
    const int row = tid >> 1;
    const int seg = tid & 1;
    const int m = bm + row;
    const int wr = (wid >> 1) * 32;
    const int wc = (wid & 1) * 64;
    const int gID = lane >> 2;
    const int tg = lane & 3;

    for (int i = tid; i < 8192; i += 256) {
        int n = i >> 6;
        int k = (i & 63) * 2;
        float v0 = __ldg(&p.f2w[n * 128 + k]);
        float v1 = __ldg(&p.f2w[n * 128 + k + 1]);
        ft_stashB(Bs2, n, k, f2h2(v0, v1));
    }

    float acc[2][8][4];
#pragma unroll
    for (int mi = 0; mi < 2; mi++)
#pragma unroll
        for (int nj = 0; nj < 8; nj++)
#pragma unroll
            for (int q = 0; q < 4; q++) acc[mi][nj][q] = 0.f;

    // register-prefetched stage-1 loop
    uint4 ra_lo, ra_hi, rb_lo, rb_hi;
    ft_loadA(p, m, seg * 16, ra_lo, ra_hi);
    ft_loadB(p, row, seg * 16, rb_lo, rb_hi);

#pragma unroll 1
    for (int k0 = 0; k0 < 384; k0 += 32) {
        *(uint4*)&As[row][seg * 8] = ra_lo;
        *(uint4*)&As[row][seg * 8 + 4] = ra_hi;
        *(uint4*)&Bs[row][seg * 8] = rb_lo;
        *(uint4*)&Bs[row][seg * 8 + 4] = rb_hi;
        __syncthreads();
        if (k0 + 32 < 384) {
            ft_loadA(p, m, k0 + 32 + seg * 16, ra_lo, ra_hi);
            ft_loadB(p, row, k0 + 32 + seg * 16, rb_lo, rb_hi);
        }
#pragma unroll
        for (int kt = 0; kt < 2; kt++) {
            const int cb = kt * 8;
            uint32_t a[2][4];
#pragma unroll
            for (int mi = 0; mi < 2; mi++) {
                int r0 = wr + mi * 16 + gID;
                a[mi][0] = As[r0][cb + tg];
                a[mi][1] = As[r0 + 8][cb + tg];
                a[mi][2] = As[r0][cb + 4 + tg];
                a[mi][3] = As[r0 + 8][cb + 4 + tg];
            }
#pragma unroll
            for (int nj = 0; nj < 8; nj++) {
                int nb_ = wc + nj * 8 + gID;
                uint32_t b0 = Bs[nb_][cb + tg];
                uint32_t b1 = Bs[nb_][cb + 4 + tg];
                mma_f16(acc[0][nj], a[0], b0, b1);
                mma_f16(acc[1][nj], a[1], b0, b1);
            }
        }
        __syncthreads();
    }

#pragma unroll
    for (int mi = 0; mi < 2; mi++) {
        const int rl = wr + mi * 16 + gID;
        const int rh = rl + 8;
        const bool z_lo = p.invalid[bm + rl];
        const bool z_hi = p.invalid[bm + rh];
#pragma unroll
        for (int nj = 0; nj < 8; nj++) {
            const int cl = wc + nj * 8 + tg * 2;
            const float b0 = __ldg(&p.f1b[cl]);
            const float b1 = __ldg(&p.f1b[cl + 1]);
            const float cb0 = __ldg(&p.c0[cl]);
            const float cb1 = __ldg(&p.c0[cl + 1]);
            float v00 = fmaxf(acc[mi][nj][0] + b0 + (z_lo ? 0.f : cb0), 0.f);
            float v01 = fmaxf(acc[mi][nj][1] + b1 + (z_lo ? 0.f : cb1), 0.f);
            float v10 = fmaxf(acc[mi][nj][2] + b0 + (z_hi ? 0.f : cb0), 0.f);
            float v11 = fmaxf(acc[mi][nj][3] + b1 + (z_hi ? 0.f : cb1), 0.f);
            ft_stashA(As2, rl, cl, f2h2(v00, v01));
            ft_stashA(As2, rh, cl, f2h2(v10, v11));
        }
    }
    __syncthreads();

    float acc2[2][8][4];
#pragma unroll
    for (int mi = 0; mi < 2; mi++)
#pragma unroll
        for (int nj = 0; nj < 8; nj++)
#pragma unroll
            for (int q = 0; q < 4; q++) acc2[mi][nj][q] = 0.f;

    const uint4* As2_4 = (const uint4*)As2;
    const int mi8base = wr >> 4;
#pragma unroll
    for (int kt = 0; kt < 8; kt++) {
        uint4 a0v = As2_4[(kt * 8 + mi8base) * 32 + lane];
        uint4 a1v = As2_4[(kt * 8 + mi8base + 1) * 32 + lane];
        uint32_t a0[4] = {a0v.x, a0v.y, a0v.z, a0v.w};
        uint32_t a1[4] = {a1v.x, a1v.y, a1v.z, a1v.w};
#pragma unroll
        for (int nj = 0; nj < 8; nj++) {
            int nt = (wc >> 3) + nj;
            uint2 bb = *(const uint2*)&Bs2[(((nt * 8 + kt) * 32) + lane) * 2];
            mma_f16(acc2[0][nj], a0, bb.x, bb.y);
            mma_f16(acc2[1][nj], a1, bb.x, bb.y);
        }
    }

#pragma unroll
    for (int mi = 0; mi < 2; mi++) {
        const int r_lo = bm + wr + mi * 16 + gID;
        const int r_hi = r_lo + 8;
#pragma unroll
        for (int nj = 0; nj < 8; nj++) {
            const int cl = wc + nj * 8 + tg * 2;
            const float b0 = __ldg(&p.f2b[cl]);
            const float b1 = __ldg(&p.f2b[cl + 1]);
            float v00 = acc2[mi][nj][0] + b0, v01 = acc2[mi][nj][1] + b1;
            float v10 = acc2[mi][nj][2] + b0, v11 = acc2[mi][nj][3] + b1;
            if (HALF_OUT) {
                __half* clo = (__half*)p.C + (size_t)r_lo * 128;
                __half* chi = (__half*)p.C + (size_t)r_hi * 128;
                *(__half2*)(clo + cl) = __floats2half2_rn(v00, v01);
                *(__half2*)(chi + cl) = __floats2half2_rn(v10, v11);
            } else {
                float* clo = (float*)p.C + (size_t)r_lo * 128;
                float* chi = (float*)p.C + (size_t)r_hi * 128;
                *(float2*)(clo + cl) = make_float2(v00, v01);
                *(float2*)(chi + cl) = make_float2(v10, v11);
            }
        }
    }
}

// ---------------------------------------------------------------------------
// Host side
// ---------------------------------------------------------------------------
extern "C" void kernel_launch(void* const* d_in, const int* in_sizes, int n_in,
                              void* d_out, int out_size) {
    const float* nf   = (const float*)d_in[0];
    const float* mem  = (const float*)d_in[1];
    const float* ef   = (const float*)d_in[2];
    const float* tw   = (const float*)d_in[3];
    const float* tb   = (const float*)d_in[4];
    const float* Wq   = (const float*)d_in[5];
    const float* bq   = (const float*)d_in[6];
    const float* Wk   = (const float*)d_in[7];
    const float* bk   = (const float*)d_in[8];
    const float* Wv   = (const float*)d_in[9];
    const float* bv   = (const float*)d_in[10];
    const float* Wo   = (const float*)d_in[11];
    const float* bo   = (const float*)d_in[12];
    const float* f1w  = (const float*)d_in[13];
    const float* f1b  = (const float*)d_in[14];
    const float* f2w  = (const float*)d_in[15];
    const float* f2b  = (const float*)d_in[16];
    const int*   src  = (const int*)d_in[17];
    const float* ts   = (const float*)d_in[18];
    const int*   nb2  = (const int*)d_in[19];
    const int*   ei2  = (const int*)d_in[20];
    const float* tm2  = (const float*)d_in[21];
    const int*   nb1  = (const int*)d_in[22];
    const int*   ei1  = (const int*)d_in[23];
    const float* tm1  = (const float*)d_in[24];
    float* out = (float*)d_out;

    float *pwcat, *pc0, *pbq2;
    __half *pbph, *pq1, *pq2, *pattn1, *pattn2, *pemb1;
    unsigned char *pinv1, *pinv2;
    cudaGetSymbolAddress((void**)&pq1, g_q1);
    cudaGetSymbolAddress((void**)&pattn1, g_attn1);
    cudaGetSymbolAddress((void**)&pemb1, g_emb1);
    cudaGetSymbolAddress((void**)&pinv1, g_inv1);
    cudaGetSymbolAddress((void**)&pq2, g_q2);
    cudaGetSymbolAddress((void**)&pattn2, g_attn2);
    cudaGetSymbolAddress((void**)&pinv2, g_inv2);
    cudaGetSymbolAddress((void**)&pbph, g_bph);
    cudaGetSymbolAddress((void**)&pwcat, g_wcat);
    cudaGetSymbolAddress((void**)&pc0, g_c0);
    cudaGetSymbolAddress((void**)&pbq2, g_bq2);

    static cudaStream_t s_side = nullptr;
    static cudaEvent_t ev_fork = nullptr, ev_q1 = nullptr, ev_join = nullptr;
    if (s_side == nullptr) {
        cudaStreamCreateWithFlags(&s_side, cudaStreamNonBlocking);
        cudaEventCreateWithFlags(&ev_fork, cudaEventDisableTiming);
        cudaEventCreateWithFlags(&ev_q1, cudaEventDisableTiming);
        cudaEventCreateWithFlags(&ev_join, cudaEventDisableTiming);
        cudaFuncSetAttribute(kv_kernel<0>, cudaFuncAttributeMaxDynamicSharedMemorySize, KV_DSMEM);
        cudaFuncSetAttribute(kv_kernel<1>, cudaFuncAttributeMaxDynamicSharedMemorySize, KV_DSMEM);
        cudaFuncSetAttribute(fused_tail<0>, cudaFuncAttributeMaxDynamicSharedMemorySize, FT_DSMEM);
        cudaFuncSetAttribute(fused_tail<1>, cudaFuncAttributeMaxDynamicSharedMemorySize, FT_DSMEM);
    }

    const cudaStream_t s0 = 0;

    const float* bk1 = bk + 256;
    const float* bv1 = bv + 256;
    const float* f2w1 = f2w + 128 * 128; const float* f2b1 = f2b + 128;

    // ---- side stream: prep_bq -> Q1 (ev_q1) -> Q2, prep_wc, prep_b L1 ----
    cudaEventRecord(ev_fork, s0);
    cudaStreamWaitEvent(s_side, ev_fork, 0);

    prep_bq_kernel<<<2, 256, 0, s_side>>>(Wq, bq, tb, pbq2);
    {
        TcParams p{};
        p.W = Wq; p.bias = pbq2; p.C = pq1;
        p.nf = nf; p.memv = mem; p.idx = nb2;
        q_gemm<<<dim3(N1 / 128, 2), 256, 0, s_side>>>(p);
    }
    cudaEventRecord(ev_q1, s_side);
    {
        TcParams p{};
        p.W = Wq + 256 * 256; p.bias = pbq2 + 256; p.C = pq2;
        p.nf = nf; p.memv = mem; p.idx = src;
        q_gemm<<<dim3(BB / 128, 2), 256, 0, s_side>>>(p);
    }
    prep_wc_kernel<<<256, 384, 0, s_side>>>(Wo, bo, f1w, pwcat, pc0);
    prep_b_kernel<<<(512 * 384 + 255) / 256, 256, 0, s_side>>>(Wk, Wv, pbph, 1);
    cudaEventRecord(ev_join, s_side);

    // ---- main stream: prep_b L0, wait q1, fused KV1+attn1 ----
    prep_b_kernel<<<(512 * 384 + 255) / 256, 256, 0, s0>>>(Wk, Wv, pbph, 0);
    cudaStreamWaitEvent(s0, ev_q1, 0);
    {
        KvParams p{};
        p.Bp = pbph; p.bk = bk; p.bv = bv;
        p.q = pq1; p.attn_out = pattn1; p.invalid = pinv1; p.mask_idx = nb1;
        p.DIV = 100; p.nblk = NP1 / 80;
        p.ts = ts; p.etm = tm1; p.tw = tw; p.tb = tb;
        p.nf = nf; p.memv = mem; p.ef = ef; p.idx = nb1; p.eidx = ei1;
        kv_kernel<0><<<148, 512, KV_DSMEM, s0>>>(p);
    }
    cudaStreamWaitEvent(s0, ev_join, 0);

    {   // fused O1+fc1+fc2 (L0) -> emb1 (fp16)
        FtParams p{};
        p.Wcat = pwcat; p.f1b = f1b; p.c0 = pc0;
        p.f2w = f2w; p.f2b = f2b; p.C = pemb1;
        p.Ah = pattn1; p.nf = nf; p.memv = mem; p.idx = nb2; p.invalid = pinv1;
        fused_tail<1><<<N1 / 128, 256, FT_DSMEM, s0>>>(p);
    }
    {   // fused KV2+attn2 (dense fp16 emb1)
        KvParams p{};
        p.Bp = pbph + 512 * 384; p.bk = bk1; p.bv = bv1;
        p.q = pq2; p.attn_out = pattn2; p.invalid = pinv2; p.mask_idx = nb2;
        p.DIV = 10; p.nblk = NP2 / 80;
        p.ts = ts; p.etm = tm2; p.tw = tw; p.tb = tb;
        p.Adense = pemb1; p.ef = ef; p.eidx = ei2;
        kv_kernel<1><<<148, 512, KV_DSMEM, s0>>>(p);
    }
    {   // fused O2+fc1+fc2 (L1) -> out (fp32)
        FtParams p{};
        p.Wcat = pwcat + 128 * 384; p.f1b = f1b + 128; p.c0 = pc0 + 128;
        p.f2w = f2w1; p.f2b = f2b1; p.C = out;
        p.Ah = pattn2; p.nf = nf; p.memv = mem; p.idx = src; p.invalid = pinv2;
        fused_tail<0><<<BB / 128, 256, FT_DSMEM, s0>>>(p);
    }
}